// round 4
// baseline (speedup 1.0000x reference)
#include <cuda_runtime.h>
#include <math.h>

#define BB 32
#define SQ 200
#define SMEMLEN 1024
#define DMODEL 1024
#define NH 16
#define HD 64
#define DFF 4096
#define NT (BB*SQ)        // 6400 target tokens
#define MTOK (BB*SMEMLEN) // 32768 memory tokens
#define EPS 1e-5f

// ---------------- scratch ----------------
__device__ float g_h[NT*DMODEL];
__device__ float g_roped[NT*DMODEL];
__device__ float g_q[NT*DMODEL];
__device__ float g_k[MTOK*DMODEL];
__device__ float g_v[MTOK*DMODEL];
__device__ float g_attn[NT*DMODEL];
__device__ float g_x[NT*DMODEL];
__device__ float g_ffh[NT*DFF];

// ---------------- LayerNorm ----------------
__global__ __launch_bounds__(256) void ln_kernel(const float* __restrict__ x,
                                                 const float* __restrict__ g,
                                                 const float* __restrict__ b,
                                                 float* __restrict__ out) {
    __shared__ float rs[8], rss[8];
    int t = blockIdx.x;
    int tid = threadIdx.x;
    const float4* xr = (const float4*)(x + (size_t)t * DMODEL);
    float4 v = xr[tid];
    float s  = v.x + v.y + v.z + v.w;
    float ss = v.x*v.x + v.y*v.y + v.z*v.z + v.w*v.w;
    #pragma unroll
    for (int o = 16; o; o >>= 1) {
        s  += __shfl_xor_sync(0xffffffffu, s, o);
        ss += __shfl_xor_sync(0xffffffffu, ss, o);
    }
    int lane = tid & 31, wid = tid >> 5;
    if (lane == 0) { rs[wid] = s; rss[wid] = ss; }
    __syncthreads();
    float ts = 0.f, tss = 0.f;
    #pragma unroll
    for (int w = 0; w < 8; w++) { ts += rs[w]; tss += rss[w]; }
    float mu  = ts * (1.0f / DMODEL);
    float var = tss * (1.0f / DMODEL) - mu * mu;
    float r   = rsqrtf(var + EPS);
    float4 gv = ((const float4*)g)[tid];
    float4 bv = ((const float4*)b)[tid];
    float4 o;
    o.x = (v.x - mu) * r * gv.x + bv.x;
    o.y = (v.y - mu) * r * gv.y + bv.y;
    o.z = (v.z - mu) * r * gv.z + bv.z;
    o.w = (v.w - mu) * r * gv.w + bv.w;
    ((float4*)(out + (size_t)t * DMODEL))[tid] = o;
}

// ---------------- RoPE ----------------
__global__ void rope_kernel(const float* __restrict__ in, float* __restrict__ out) {
    int idx = blockIdx.x * blockDim.x + threadIdx.x;
    if (idx >= NT * (DMODEL / 2)) return;
    int t = idx / (DMODEL / 2);
    int p = idx - t * (DMODEL / 2);
    int i = p & 31;
    int s = t % SQ;
    float freq = __expf(-9.210340371976184f * (2.0f * i) * (1.0f / 64.0f));
    float ang = (float)s * freq;
    float sn, cs;
    sincosf(ang, &sn, &cs);
    const float2 xv = ((const float2*)in)[idx];
    float2 o;
    o.x = xv.x * cs - xv.y * sn;
    o.y = xv.y * cs + xv.x * sn;
    ((float2*)out)[idx] = o;
}

// ---------------- tf32 tensor-core GEMM (3-stage cp.async + ldmatrix + cvt.rna) ----
// C[M,N] = A[M,K] @ W[N,K]^T + bias (+res)(+relu)
// 128x128 tile, BK=32, 3-stage pipeline (1 barrier/slab), 8 warps, warp tile 32x64.
#define BK 32
#define SPAD 36
#define NSTG 3
#define STAGEF (2 * 128 * SPAD)          // floats per stage (A+W)
#define GSMEM  (NSTG * STAGEF * 4)       // 110592 bytes

__device__ __forceinline__ void cpa16(unsigned dst, const void* src) {
    asm volatile("cp.async.cg.shared.global [%0], [%1], 16;\n" :: "r"(dst), "l"(src));
}
__device__ __forceinline__ void ldsm4(unsigned& r0, unsigned& r1, unsigned& r2, unsigned& r3,
                                      unsigned a) {
    asm volatile("ldmatrix.sync.aligned.m8n8.x4.shared.b16 {%0,%1,%2,%3}, [%4];"
                 : "=r"(r0), "=r"(r1), "=r"(r2), "=r"(r3) : "r"(a));
}
__device__ __forceinline__ unsigned rna(unsigned x) {
    unsigned r;
    asm("cvt.rna.tf32.f32 %0, %1;" : "=r"(r) : "f"(__uint_as_float(x)));
    return r;
}

__global__ __launch_bounds__(256, 2) void sgemm_tf32(const float* __restrict__ A,
                                                     const float* __restrict__ W,
                                                     const float* __restrict__ bias,
                                                     const float* __restrict__ res,
                                                     float* __restrict__ C,
                                                     int M, int N, int K, int flags) {
    extern __shared__ float smx[];
    int tid = threadIdx.x;
    int wid = tid >> 5, lane = tid & 31;
    int gid = lane >> 2, tig = lane & 3;
    int row0 = blockIdx.y * 128;
    int col0 = blockIdx.x * 128;
    int wm = (wid & 3) * 32;
    int wn = (wid >> 2) * 64;

    unsigned sbase = (unsigned)__cvta_generic_to_shared(smx);
    unsigned stgA[NSTG], stgW[NSTG];
    #pragma unroll
    for (int s = 0; s < NSTG; s++) {
        stgA[s] = sbase + s * STAGEF * 4;
        stgW[s] = stgA[s] + 128 * SPAD * 4;
    }

    // loader mapping: 32 rows x (8 chunks of 16B) per wave, 4 waves
    int lr  = tid >> 3;           // 0..31
    int lkc = (tid & 7) * 4;      // 0,4,...,28
    const float* Ab = A + (size_t)(row0 + lr) * K + lkc;
    const float* Wb = W + (size_t)(col0 + lr) * K + lkc;

    float c[2][8][4];
    #pragma unroll
    for (int mi = 0; mi < 2; mi++)
        #pragma unroll
        for (int ni = 0; ni < 8; ni++)
            #pragma unroll
            for (int q = 0; q < 4; q++) c[mi][ni][q] = 0.f;

    int nk = K / BK;   // >= 32 always here

    // prologue: stages 0 and 1
    #pragma unroll
    for (int ps = 0; ps < 2; ps++) {
        int k0 = ps * BK;
        #pragma unroll
        for (int w = 0; w < 4; w++) {
            unsigned soff = ((lr + 32 * w) * SPAD + lkc) * 4;
            cpa16(stgA[ps] + soff, Ab + (size_t)(32 * w) * K + k0);
            cpa16(stgW[ps] + soff, Wb + (size_t)(32 * w) * K + k0);
        }
        asm volatile("cp.async.commit_group;\n");
    }

    int lrow = lane & 15;
    int lcol = (lane >> 4) * 4;

    unsigned af[2][2][4], bf[2][4][4];

    for (int kt = 0; kt < nk; kt++) {
        if (kt < nk - 1) asm volatile("cp.async.wait_group 1;\n");
        else             asm volatile("cp.async.wait_group 0;\n");
        __syncthreads();

        // prefetch stage kt+2 (overwrites buffer last read at iter kt-1; barrier fences it)
        if (kt + 2 < nk) {
            int st = (kt + 2) % NSTG;
            int k0 = (kt + 2) * BK;
            #pragma unroll
            for (int w = 0; w < 4; w++) {
                unsigned soff = ((lr + 32 * w) * SPAD + lkc) * 4;
                cpa16(stgA[st] + soff, Ab + (size_t)(32 * w) * K + k0);
                cpa16(stgW[st] + soff, Wb + (size_t)(32 * w) * K + k0);
            }
            asm volatile("cp.async.commit_group;\n");
        }

        int st = kt % NSTG;
        unsigned sAu = stgA[st];
        unsigned sWu = stgW[st];

        auto load_frags = [&](int buf, int ks) {
            int kb = ks * 8;
            #pragma unroll
            for (int mi = 0; mi < 2; mi++)
                ldsm4(af[buf][mi][0], af[buf][mi][1], af[buf][mi][2], af[buf][mi][3],
                      sAu + ((wm + mi * 16 + lrow) * SPAD + kb + lcol) * 4);
            #pragma unroll
            for (int p = 0; p < 4; p++)
                ldsm4(bf[buf][p][0], bf[buf][p][1], bf[buf][p][2], bf[buf][p][3],
                      sWu + ((wn + p * 16 + lrow) * SPAD + kb + lcol) * 4);
        };

        load_frags(0, 0);
        #pragma unroll
        for (int ks = 0; ks < 4; ks++) {
            int cur = ks & 1;
            if (ks < 3) load_frags(cur ^ 1, ks + 1);
            // round fragments to tf32 rna (ALU pipe, overlaps tensor pipe)
            #pragma unroll
            for (int mi = 0; mi < 2; mi++)
                #pragma unroll
                for (int q = 0; q < 4; q++) af[cur][mi][q] = rna(af[cur][mi][q]);
            #pragma unroll
            for (int p = 0; p < 4; p++)
                #pragma unroll
                for (int q = 0; q < 4; q++) bf[cur][p][q] = rna(bf[cur][p][q]);
            #pragma unroll
            for (int mi = 0; mi < 2; mi++)
                #pragma unroll
                for (int p = 0; p < 4; p++) {
                    asm volatile(
                        "mma.sync.aligned.m16n8k8.row.col.f32.tf32.tf32.f32 "
                        "{%0,%1,%2,%3}, {%4,%5,%6,%7}, {%8,%9}, {%0,%1,%2,%3};"
                        : "+f"(c[mi][2*p][0]), "+f"(c[mi][2*p][1]),
                          "+f"(c[mi][2*p][2]), "+f"(c[mi][2*p][3])
                        : "r"(af[cur][mi][0]), "r"(af[cur][mi][1]),
                          "r"(af[cur][mi][2]), "r"(af[cur][mi][3]),
                          "r"(bf[cur][p][0]), "r"(bf[cur][p][2]));
                    asm volatile(
                        "mma.sync.aligned.m16n8k8.row.col.f32.tf32.tf32.f32 "
                        "{%0,%1,%2,%3}, {%4,%5,%6,%7}, {%8,%9}, {%0,%1,%2,%3};"
                        : "+f"(c[mi][2*p+1][0]), "+f"(c[mi][2*p+1][1]),
                          "+f"(c[mi][2*p+1][2]), "+f"(c[mi][2*p+1][3])
                        : "r"(af[cur][mi][0]), "r"(af[cur][mi][1]),
                          "r"(af[cur][mi][2]), "r"(af[cur][mi][3]),
                          "r"(bf[cur][p][1]), "r"(bf[cur][p][3]));
                }
        }
    }

    __syncthreads();   // protect smem before epilogue (none used, but cheap) & align exits

    bool use_relu = (flags & 1) != 0;
    bool use_res  = (flags & 2) != 0;
    #pragma unroll
    for (int mi = 0; mi < 2; mi++) {
        #pragma unroll
        for (int ni = 0; ni < 8; ni++) {
            int colg = col0 + wn + ni * 8 + tig * 2;
            int r0 = row0 + wm + mi * 16 + gid;
            int r1 = r0 + 8;
            float b0 = bias[colg], b1 = bias[colg + 1];
            float2 o0, o1;
            o0.x = c[mi][ni][0] + b0; o0.y = c[mi][ni][1] + b1;
            o1.x = c[mi][ni][2] + b0; o1.y = c[mi][ni][3] + b1;
            size_t i0 = (size_t)r0 * N + colg;
            size_t i1 = (size_t)r1 * N + colg;
            if (use_res) {
                float2 rv0 = *(const float2*)(res + i0);
                float2 rv1 = *(const float2*)(res + i1);
                o0.x += rv0.x; o0.y += rv0.y;
                o1.x += rv1.x; o1.y += rv1.y;
            }
            if (use_relu) {
                o0.x = fmaxf(o0.x, 0.f); o0.y = fmaxf(o0.y, 0.f);
                o1.x = fmaxf(o1.x, 0.f); o1.y = fmaxf(o1.y, 0.f);
            }
            *(float2*)(C + i0) = o0;
            *(float2*)(C + i1) = o1;
        }
    }
}

// ---------------- tiled flash attention ----------------
#define ATQ 64
#define ATK 64
#define APAD 68

__global__ __launch_bounds__(256) void attn2_kernel(const float* __restrict__ Q,
                                                    const float* __restrict__ Km,
                                                    const float* __restrict__ Vm,
                                                    float* __restrict__ O,
                                                    int Sq, int Sk, int causal) {
    extern __shared__ float sm[];
    float* Qs = sm;
    float* Ks = sm + ATQ * APAD;
    float* Vs = sm + 2 * ATQ * APAD;
    float* Ss = sm + 3 * ATQ * APAD;

    int qt = blockIdx.x, h = blockIdx.y, b = blockIdx.z;
    int tid = threadIdx.x;
    int qg = tid >> 4;
    int j  = tid & 15;

    {
        int qr = tid >> 2;
        int qgl = qt * ATQ + qr;
        int dq = (tid & 3) * 16;
        const float* src = Q + (((size_t)b * Sq + qgl) * NH + h) * (size_t)HD + dq;
        float4 z = {0.f, 0.f, 0.f, 0.f};
        #pragma unroll
        for (int i = 0; i < 4; i++) {
            float4 v = (qgl < Sq) ? *(const float4*)(src + i * 4) : z;
            *(float4*)&Qs[qr * APAD + dq + i * 4] = v;
        }
    }

    float m_i[4], l_i[4], acc[4][4];
    #pragma unroll
    for (int qi = 0; qi < 4; qi++) {
        m_i[qi] = -1e30f; l_i[qi] = 0.f;
        #pragma unroll
        for (int di = 0; di < 4; di++) acc[qi][di] = 0.f;
    }

    int q_hi = qt * ATQ + ATQ - 1;
    int keff = causal ? min(q_hi + 1, Sk) : Sk;
    int ntiles = (keff + ATK - 1) / ATK;

    int kr = tid >> 2;
    int dq = (tid & 3) * 16;
    float4 pk[4], pv[4];
    {
        int kg = kr;
        bool ok = kg < Sk;
        const float* ksrc = Km + (((size_t)b * Sk + kg) * NH + h) * (size_t)HD + dq;
        const float* vsrc = Vm + (((size_t)b * Sk + kg) * NH + h) * (size_t)HD + dq;
        float4 z = {0.f, 0.f, 0.f, 0.f};
        #pragma unroll
        for (int i = 0; i < 4; i++) {
            pk[i] = ok ? *(const float4*)(ksrc + i * 4) : z;
            pv[i] = ok ? *(const float4*)(vsrc + i * 4) : z;
        }
    }

    for (int kt = 0; kt < ntiles; kt++) {
        #pragma unroll
        for (int i = 0; i < 4; i++) {
            *(float4*)&Ks[kr * APAD + dq + i * 4] = pk[i];
            *(float4*)&Vs[kr * APAD + dq + i * 4] = pv[i];
        }
        __syncthreads();

        if (kt + 1 < ntiles) {
            int kg = (kt + 1) * ATK + kr;
            bool ok = kg < Sk;
            const float* ksrc = Km + (((size_t)b * Sk + kg) * NH + h) * (size_t)HD + dq;
            const float* vsrc = Vm + (((size_t)b * Sk + kg) * NH + h) * (size_t)HD + dq;
            float4 z = {0.f, 0.f, 0.f, 0.f};
            #pragma unroll
            for (int i = 0; i < 4; i++) {
                pk[i] = ok ? *(const float4*)(ksrc + i * 4) : z;
                pv[i] = ok ? *(const float4*)(vsrc + i * 4) : z;
            }
        }

        float s[4][4];
        #pragma unroll
        for (int qi = 0; qi < 4; qi++)
            #pragma unroll
            for (int ki = 0; ki < 4; ki++) s[qi][ki] = 0.f;

        #pragma unroll
        for (int d0 = 0; d0 < HD; d0 += 4) {
            float4 q4[4], k4[4];
            #pragma unroll
            for (int qi = 0; qi < 4; qi++)
                q4[qi] = *(const float4*)&Qs[(qg * 4 + qi) * APAD + d0];
            #pragma unroll
            for (int ki = 0; ki < 4; ki++)
                k4[ki] = *(const float4*)&Ks[(j + 16 * ki) * APAD + d0];
            #pragma unroll
            for (int qi = 0; qi < 4; qi++)
                #pragma unroll
                for (int ki = 0; ki < 4; ki++) {
                    s[qi][ki] += q4[qi].x * k4[ki].x + q4[qi].y * k4[ki].y
                               + q4[qi].z * k4[ki].z + q4[qi].w * k4[ki].w;
                }
        }

        #pragma unroll
        for (int qi = 0; qi < 4; qi++) {
            int qgl = qt * ATQ + qg * 4 + qi;
            int kvalid = causal ? min(qgl + 1, Sk) : Sk;
            #pragma unroll
            for (int ki = 0; ki < 4; ki++) {
                int kg = kt * ATK + j + 16 * ki;
                s[qi][ki] = (kg < kvalid) ? s[qi][ki] * 0.125f : -1e30f;
            }
            float tm = fmaxf(fmaxf(s[qi][0], s[qi][1]), fmaxf(s[qi][2], s[qi][3]));
            #pragma unroll
            for (int off = 1; off < 16; off <<= 1)
                tm = fmaxf(tm, __shfl_xor_sync(0xffffffffu, tm, off));
            float mn = fmaxf(m_i[qi], tm);
            float scale = __expf(m_i[qi] - mn);
            float ps = 0.f;
            #pragma unroll
            for (int ki = 0; ki < 4; ki++) {
                float p = __expf(s[qi][ki] - mn);
                s[qi][ki] = p;
                ps += p;
            }
            #pragma unroll
            for (int off = 1; off < 16; off <<= 1)
                ps += __shfl_xor_sync(0xffffffffu, ps, off);
            l_i[qi] = l_i[qi] * scale + ps;
            m_i[qi] = mn;
            #pragma unroll
            for (int di = 0; di < 4; di++) acc[qi][di] *= scale;
        }

        #pragma unroll
        for (int ki = 0; ki < 4; ki++)
            #pragma unroll
            for (int qi = 0; qi < 4; qi++)
                Ss[(j + 16 * ki) * APAD + qg * 4 + qi] = s[qi][ki];
        __syncthreads();

        #pragma unroll 8
        for (int k = 0; k < ATK; k++) {
            float4 p4 = *(const float4*)&Ss[k * APAD + qg * 4];
            float4 v4 = *(const float4*)&Vs[k * APAD + j * 4];
            acc[0][0] += p4.x * v4.x; acc[0][1] += p4.x * v4.y;
            acc[0][2] += p4.x * v4.z; acc[0][3] += p4.x * v4.w;
            acc[1][0] += p4.y * v4.x; acc[1][1] += p4.y * v4.y;
            acc[1][2] += p4.y * v4.z; acc[1][3] += p4.y * v4.w;
            acc[2][0] += p4.z * v4.x; acc[2][1] += p4.z * v4.y;
            acc[2][2] += p4.z * v4.z; acc[2][3] += p4.z * v4.w;
            acc[3][0] += p4.w * v4.x; acc[3][1] += p4.w * v4.y;
            acc[3][2] += p4.w * v4.z; acc[3][3] += p4.w * v4.w;
        }
        __syncthreads();
    }

    int dd = j * 4;
    #pragma unroll
    for (int qi = 0; qi < 4; qi++) {
        int qgl = qt * ATQ + qg * 4 + qi;
        if (qgl < Sq) {
            float inv = 1.0f / l_i[qi];
            float4 o;
            o.x = acc[qi][0] * inv; o.y = acc[qi][1] * inv;
            o.z = acc[qi][2] * inv; o.w = acc[qi][3] * inv;
            *(float4*)&O[(((size_t)b * Sq + qgl) * NH + h) * (size_t)HD + dd] = o;
        }
    }
}

// ---------------- host orchestration ----------------
extern "C" void kernel_launch(void* const* d_in, const int* in_sizes, int n_in,
                              void* d_out, int out_size) {
    const float* tgt      = (const float*)d_in[0];
    const float* memory   = (const float*)d_in[1];
    const float* sa_in_w  = (const float*)d_in[2];
    const float* sa_in_b  = (const float*)d_in[3];
    const float* sa_out_w = (const float*)d_in[4];
    const float* sa_out_b = (const float*)d_in[5];
    const float* ca_in_w  = (const float*)d_in[6];
    const float* ca_in_b  = (const float*)d_in[7];
    const float* ca_out_w = (const float*)d_in[8];
    const float* ca_out_b = (const float*)d_in[9];
    const float* ff1_w    = (const float*)d_in[10];
    const float* ff1_b    = (const float*)d_in[11];
    const float* ff2_w    = (const float*)d_in[12];
    const float* ff2_b    = (const float*)d_in[13];
    const float* ln1_g    = (const float*)d_in[14];
    const float* ln1_b    = (const float*)d_in[15];
    const float* ln2_g    = (const float*)d_in[16];
    const float* ln2_b    = (const float*)d_in[17];
    const float* ln3_g    = (const float*)d_in[18];
    const float* ln3_b    = (const float*)d_in[19];
    float* out = (float*)d_out;

    float *p_h, *p_roped, *p_q, *p_k, *p_v, *p_attn, *p_x, *p_ffh;
    cudaGetSymbolAddress((void**)&p_h,     g_h);
    cudaGetSymbolAddress((void**)&p_roped, g_roped);
    cudaGetSymbolAddress((void**)&p_q,     g_q);
    cudaGetSymbolAddress((void**)&p_k,     g_k);
    cudaGetSymbolAddress((void**)&p_v,     g_v);
    cudaGetSymbolAddress((void**)&p_attn,  g_attn);
    cudaGetSymbolAddress((void**)&p_x,     g_x);
    cudaGetSymbolAddress((void**)&p_ffh,   g_ffh);

    static int smem_set = 0;
    int attn_smem = 4 * ATQ * APAD * sizeof(float);
    if (!smem_set) {
        cudaFuncSetAttribute(attn2_kernel, cudaFuncAttributeMaxDynamicSharedMemorySize, attn_smem);
        cudaFuncSetAttribute(sgemm_tf32, cudaFuncAttributeMaxDynamicSharedMemorySize, GSMEM);
        smem_set = 1;
    }

    dim3 gemm_nt_d(DMODEL / 128, NT / 128);
    dim3 gemm_mt_d(DMODEL / 128, MTOK / 128);
    dim3 gemm_ff1(DFF / 128, NT / 128);
    int rope_blocks = (NT * (DMODEL / 2) + 255) / 256;
    int qtiles = (SQ + ATQ - 1) / ATQ;

    // ---- self-attention block ----
    ln_kernel<<<NT, 256>>>(tgt, ln1_g, ln1_b, p_h);
    rope_kernel<<<rope_blocks, 256>>>(p_h, p_roped);
    sgemm_tf32<<<gemm_nt_d, 256, GSMEM>>>(p_roped, sa_in_w,                           sa_in_b,            nullptr, p_q, NT, DMODEL, DMODEL, 0);
    sgemm_tf32<<<gemm_nt_d, 256, GSMEM>>>(p_roped, sa_in_w + (size_t)DMODEL*DMODEL,   sa_in_b + DMODEL,   nullptr, p_k, NT, DMODEL, DMODEL, 0);
    sgemm_tf32<<<gemm_nt_d, 256, GSMEM>>>(p_h,     sa_in_w + (size_t)2*DMODEL*DMODEL, sa_in_b + 2*DMODEL, nullptr, p_v, NT, DMODEL, DMODEL, 0);
    attn2_kernel<<<dim3(qtiles, NH, BB), 256, attn_smem>>>(p_q, p_k, p_v, p_attn, SQ, SQ, 1);
    sgemm_tf32<<<gemm_nt_d, 256, GSMEM>>>(p_attn, sa_out_w, sa_out_b, tgt, p_x, NT, DMODEL, DMODEL, 2);

    // ---- cross-attention block ----
    ln_kernel<<<NT, 256>>>(p_x, ln2_g, ln2_b, p_h);
    sgemm_tf32<<<gemm_nt_d, 256, GSMEM>>>(p_h,    ca_in_w,                           ca_in_b,            nullptr, p_q, NT,   DMODEL, DMODEL, 0);
    sgemm_tf32<<<gemm_mt_d, 256, GSMEM>>>(memory, ca_in_w + (size_t)DMODEL*DMODEL,   ca_in_b + DMODEL,   nullptr, p_k, MTOK, DMODEL, DMODEL, 0);
    sgemm_tf32<<<gemm_mt_d, 256, GSMEM>>>(memory, ca_in_w + (size_t)2*DMODEL*DMODEL, ca_in_b + 2*DMODEL, nullptr, p_v, MTOK, DMODEL, DMODEL, 0);
    attn2_kernel<<<dim3(qtiles, NH, BB), 256, attn_smem>>>(p_q, p_k, p_v, p_attn, SQ, SMEMLEN, 0);
    sgemm_tf32<<<gemm_nt_d, 256, GSMEM>>>(p_attn, ca_out_w, ca_out_b, p_x, p_x, NT, DMODEL, DMODEL, 2);

    // ---- feed-forward block ----
    ln_kernel<<<NT, 256>>>(p_x, ln3_g, ln3_b, p_h);
    sgemm_tf32<<<gemm_ff1, 256, GSMEM>>>(p_h,   ff1_w, ff1_b, nullptr, p_ffh, NT, DFF, DMODEL, 1);
    sgemm_tf32<<<gemm_nt_d, 256, GSMEM>>>(p_ffh, ff2_w, ff2_b, p_x, out, NT, DMODEL, DFF, 2);
}

// round 5
// speedup vs baseline: 1.0442x; 1.0442x over previous
#include <cuda_runtime.h>
#include <math.h>

#define BB 32
#define SQ 200
#define SMEMLEN 1024
#define DMODEL 1024
#define NH 16
#define HD 64
#define DFF 4096
#define NT (BB*SQ)        // 6400 target tokens
#define MTOK (BB*SMEMLEN) // 32768 memory tokens
#define EPS 1e-5f

// ---------------- scratch ----------------
__device__ float g_h[NT*DMODEL];
__device__ float g_roped[NT*DMODEL];
__device__ float g_q[NT*DMODEL];
__device__ float g_k[MTOK*DMODEL];
__device__ float g_v[MTOK*DMODEL];
__device__ float g_attn[NT*DMODEL];
__device__ float g_x[NT*DMODEL];
__device__ float g_ffh[NT*DFF];
__device__ float g_mem[MTOK*DMODEL];          // tf32-rounded memory
__device__ float g_w[16*1024*1024];           // tf32-rounded weights (packed)

// packed weight offsets (floats)
#define OW_SA_IN   0
#define OW_SA_OUT  3145728
#define OW_CA_IN   4194304
#define OW_CA_OUT  7340032
#define OW_FF1     8388608
#define OW_FF2     12582912

__device__ __forceinline__ float rnaf(float x) {
    unsigned r;
    asm("cvt.rna.tf32.f32 %0, %1;" : "=r"(r) : "f"(x));
    return __uint_as_float(r);
}

// ---------------- pre-round to tf32 (elementwise, float4) ----------------
__global__ void round_tf32_kernel(const float4* __restrict__ in,
                                  float4* __restrict__ out, int n4) {
    int i = blockIdx.x * blockDim.x + threadIdx.x;
    if (i < n4) {
        float4 v = in[i];
        v.x = rnaf(v.x); v.y = rnaf(v.y); v.z = rnaf(v.z); v.w = rnaf(v.w);
        out[i] = v;
    }
}

// ---------------- LayerNorm (output tf32-rounded; only feeds GEMMs/RoPE) ---------
__global__ __launch_bounds__(256) void ln_kernel(const float* __restrict__ x,
                                                 const float* __restrict__ g,
                                                 const float* __restrict__ b,
                                                 float* __restrict__ out,
                                                 int do_round) {
    __shared__ float rs[8], rss[8];
    int t = blockIdx.x;
    int tid = threadIdx.x;
    const float4* xr = (const float4*)(x + (size_t)t * DMODEL);
    float4 v = xr[tid];
    float s  = v.x + v.y + v.z + v.w;
    float ss = v.x*v.x + v.y*v.y + v.z*v.z + v.w*v.w;
    #pragma unroll
    for (int o = 16; o; o >>= 1) {
        s  += __shfl_xor_sync(0xffffffffu, s, o);
        ss += __shfl_xor_sync(0xffffffffu, ss, o);
    }
    int lane = tid & 31, wid = tid >> 5;
    if (lane == 0) { rs[wid] = s; rss[wid] = ss; }
    __syncthreads();
    float ts = 0.f, tss = 0.f;
    #pragma unroll
    for (int w = 0; w < 8; w++) { ts += rs[w]; tss += rss[w]; }
    float mu  = ts * (1.0f / DMODEL);
    float var = tss * (1.0f / DMODEL) - mu * mu;
    float r   = rsqrtf(var + EPS);
    float4 gv = ((const float4*)g)[tid];
    float4 bv = ((const float4*)b)[tid];
    float4 o;
    o.x = (v.x - mu) * r * gv.x + bv.x;
    o.y = (v.y - mu) * r * gv.y + bv.y;
    o.z = (v.z - mu) * r * gv.z + bv.z;
    o.w = (v.w - mu) * r * gv.w + bv.w;
    if (do_round) {
        o.x = rnaf(o.x); o.y = rnaf(o.y); o.z = rnaf(o.z); o.w = rnaf(o.w);
    }
    ((float4*)(out + (size_t)t * DMODEL))[tid] = o;
}

// ---------------- RoPE (output tf32-rounded; only feeds GEMMs) ----------------
__global__ void rope_kernel(const float* __restrict__ in, float* __restrict__ out) {
    int idx = blockIdx.x * blockDim.x + threadIdx.x;
    if (idx >= NT * (DMODEL / 2)) return;
    int t = idx / (DMODEL / 2);
    int p = idx - t * (DMODEL / 2);
    int i = p & 31;
    int s = t % SQ;
    float freq = __expf(-9.210340371976184f * (2.0f * i) * (1.0f / 64.0f));
    float ang = (float)s * freq;
    float sn, cs;
    sincosf(ang, &sn, &cs);
    const float2 xv = ((const float2*)in)[idx];
    float2 o;
    o.x = rnaf(xv.x * cs - xv.y * sn);
    o.y = rnaf(xv.y * cs + xv.x * sn);
    ((float2*)out)[idx] = o;
}

// ---------------- tf32 tensor-core GEMM (3-stage cp.async + ldmatrix) ----------
// Inputs MUST already be tf32-rounded. No cvt in mainloop.
// C[M,N] = A[M,K] @ W[N,K]^T + bias (+res flag2)(+relu flag1)(+round flag4)
#define BK 32
#define SPAD 36
#define NSTG 3
#define STAGEF (2 * 128 * SPAD)
#define GSMEM  (NSTG * STAGEF * 4)       // 110592 bytes

__device__ __forceinline__ void cpa16(unsigned dst, const void* src) {
    asm volatile("cp.async.cg.shared.global [%0], [%1], 16;\n" :: "r"(dst), "l"(src));
}
__device__ __forceinline__ void ldsm4(unsigned& r0, unsigned& r1, unsigned& r2, unsigned& r3,
                                      unsigned a) {
    asm volatile("ldmatrix.sync.aligned.m8n8.x4.shared.b16 {%0,%1,%2,%3}, [%4];"
                 : "=r"(r0), "=r"(r1), "=r"(r2), "=r"(r3) : "r"(a));
}

__global__ __launch_bounds__(256, 2) void sgemm_tf32(const float* __restrict__ A,
                                                     const float* __restrict__ W,
                                                     const float* __restrict__ bias,
                                                     const float* __restrict__ res,
                                                     float* __restrict__ C,
                                                     int M, int N, int K, int flags) {
    extern __shared__ float smx[];
    int tid = threadIdx.x;
    int wid = tid >> 5, lane = tid & 31;
    int gid = lane >> 2, tig = lane & 3;
    int row0 = blockIdx.y * 128;
    int col0 = blockIdx.x * 128;
    int wm = (wid & 3) * 32;
    int wn = (wid >> 2) * 64;

    unsigned sbase = (unsigned)__cvta_generic_to_shared(smx);
    unsigned stgA[NSTG], stgW[NSTG];
    #pragma unroll
    for (int s = 0; s < NSTG; s++) {
        stgA[s] = sbase + s * STAGEF * 4;
        stgW[s] = stgA[s] + 128 * SPAD * 4;
    }

    int lr  = tid >> 3;
    int lkc = (tid & 7) * 4;
    const float* Ab = A + (size_t)(row0 + lr) * K + lkc;
    const float* Wb = W + (size_t)(col0 + lr) * K + lkc;

    float c[2][8][4];
    #pragma unroll
    for (int mi = 0; mi < 2; mi++)
        #pragma unroll
        for (int ni = 0; ni < 8; ni++)
            #pragma unroll
            for (int q = 0; q < 4; q++) c[mi][ni][q] = 0.f;

    int nk = K / BK;

    #pragma unroll
    for (int ps = 0; ps < 2; ps++) {
        int k0 = ps * BK;
        #pragma unroll
        for (int w = 0; w < 4; w++) {
            unsigned soff = ((lr + 32 * w) * SPAD + lkc) * 4;
            cpa16(stgA[ps] + soff, Ab + (size_t)(32 * w) * K + k0);
            cpa16(stgW[ps] + soff, Wb + (size_t)(32 * w) * K + k0);
        }
        asm volatile("cp.async.commit_group;\n");
    }

    int lrow = lane & 15;
    int lcol = (lane >> 4) * 4;

    unsigned af[2][2][4], bf[2][4][4];

    for (int kt = 0; kt < nk; kt++) {
        if (kt < nk - 1) asm volatile("cp.async.wait_group 1;\n");
        else             asm volatile("cp.async.wait_group 0;\n");
        __syncthreads();

        if (kt + 2 < nk) {
            int st = (kt + 2) % NSTG;
            int k0 = (kt + 2) * BK;
            #pragma unroll
            for (int w = 0; w < 4; w++) {
                unsigned soff = ((lr + 32 * w) * SPAD + lkc) * 4;
                cpa16(stgA[st] + soff, Ab + (size_t)(32 * w) * K + k0);
                cpa16(stgW[st] + soff, Wb + (size_t)(32 * w) * K + k0);
            }
            asm volatile("cp.async.commit_group;\n");
        }

        int st = kt % NSTG;
        unsigned sAu = stgA[st];
        unsigned sWu = stgW[st];

        auto load_frags = [&](int buf, int ks) {
            int kb = ks * 8;
            #pragma unroll
            for (int mi = 0; mi < 2; mi++)
                ldsm4(af[buf][mi][0], af[buf][mi][1], af[buf][mi][2], af[buf][mi][3],
                      sAu + ((wm + mi * 16 + lrow) * SPAD + kb + lcol) * 4);
            #pragma unroll
            for (int p = 0; p < 4; p++)
                ldsm4(bf[buf][p][0], bf[buf][p][1], bf[buf][p][2], bf[buf][p][3],
                      sWu + ((wn + p * 16 + lrow) * SPAD + kb + lcol) * 4);
        };

        load_frags(0, 0);
        #pragma unroll
        for (int ks = 0; ks < 4; ks++) {
            int cur = ks & 1;
            if (ks < 3) load_frags(cur ^ 1, ks + 1);
            #pragma unroll
            for (int mi = 0; mi < 2; mi++)
                #pragma unroll
                for (int p = 0; p < 4; p++) {
                    asm volatile(
                        "mma.sync.aligned.m16n8k8.row.col.f32.tf32.tf32.f32 "
                        "{%0,%1,%2,%3}, {%4,%5,%6,%7}, {%8,%9}, {%0,%1,%2,%3};"
                        : "+f"(c[mi][2*p][0]), "+f"(c[mi][2*p][1]),
                          "+f"(c[mi][2*p][2]), "+f"(c[mi][2*p][3])
                        : "r"(af[cur][mi][0]), "r"(af[cur][mi][1]),
                          "r"(af[cur][mi][2]), "r"(af[cur][mi][3]),
                          "r"(bf[cur][p][0]), "r"(bf[cur][p][2]));
                    asm volatile(
                        "mma.sync.aligned.m16n8k8.row.col.f32.tf32.tf32.f32 "
                        "{%0,%1,%2,%3}, {%4,%5,%6,%7}, {%8,%9}, {%0,%1,%2,%3};"
                        : "+f"(c[mi][2*p+1][0]), "+f"(c[mi][2*p+1][1]),
                          "+f"(c[mi][2*p+1][2]), "+f"(c[mi][2*p+1][3])
                        : "r"(af[cur][mi][0]), "r"(af[cur][mi][1]),
                          "r"(af[cur][mi][2]), "r"(af[cur][mi][3]),
                          "r"(bf[cur][p][1]), "r"(bf[cur][p][3]));
                }
        }
    }

    bool use_relu  = (flags & 1) != 0;
    bool use_res   = (flags & 2) != 0;
    bool use_round = (flags & 4) != 0;
    #pragma unroll
    for (int mi = 0; mi < 2; mi++) {
        #pragma unroll
        for (int ni = 0; ni < 8; ni++) {
            int colg = col0 + wn + ni * 8 + tig * 2;
            int r0 = row0 + wm + mi * 16 + gid;
            int r1 = r0 + 8;
            float b0 = bias[colg], b1 = bias[colg + 1];
            float2 o0, o1;
            o0.x = c[mi][ni][0] + b0; o0.y = c[mi][ni][1] + b1;
            o1.x = c[mi][ni][2] + b0; o1.y = c[mi][ni][3] + b1;
            size_t i0 = (size_t)r0 * N + colg;
            size_t i1 = (size_t)r1 * N + colg;
            if (use_res) {
                float2 rv0 = *(const float2*)(res + i0);
                float2 rv1 = *(const float2*)(res + i1);
                o0.x += rv0.x; o0.y += rv0.y;
                o1.x += rv1.x; o1.y += rv1.y;
            }
            if (use_relu) {
                o0.x = fmaxf(o0.x, 0.f); o0.y = fmaxf(o0.y, 0.f);
                o1.x = fmaxf(o1.x, 0.f); o1.y = fmaxf(o1.y, 0.f);
            }
            if (use_round) {
                o0.x = rnaf(o0.x); o0.y = rnaf(o0.y);
                o1.x = rnaf(o1.x); o1.y = rnaf(o1.y);
            }
            *(float2*)(C + i0) = o0;
            *(float2*)(C + i1) = o1;
        }
    }
}

// ---------------- tiled flash attention (fp32; output tf32-rounded) -------------
#define ATQ 64
#define ATK 64
#define APAD 68

__global__ __launch_bounds__(256) void attn2_kernel(const float* __restrict__ Q,
                                                    const float* __restrict__ Km,
                                                    const float* __restrict__ Vm,
                                                    float* __restrict__ O,
                                                    int Sq, int Sk, int causal) {
    extern __shared__ float sm[];
    float* Qs = sm;
    float* Ks = sm + ATQ * APAD;
    float* Vs = sm + 2 * ATQ * APAD;
    float* Ss = sm + 3 * ATQ * APAD;

    int qt = blockIdx.x, h = blockIdx.y, b = blockIdx.z;
    int tid = threadIdx.x;
    int qg = tid >> 4;
    int j  = tid & 15;

    {
        int qr = tid >> 2;
        int qgl = qt * ATQ + qr;
        int dq = (tid & 3) * 16;
        const float* src = Q + (((size_t)b * Sq + qgl) * NH + h) * (size_t)HD + dq;
        float4 z = {0.f, 0.f, 0.f, 0.f};
        #pragma unroll
        for (int i = 0; i < 4; i++) {
            float4 v = (qgl < Sq) ? *(const float4*)(src + i * 4) : z;
            *(float4*)&Qs[qr * APAD + dq + i * 4] = v;
        }
    }

    float m_i[4], l_i[4], acc[4][4];
    #pragma unroll
    for (int qi = 0; qi < 4; qi++) {
        m_i[qi] = -1e30f; l_i[qi] = 0.f;
        #pragma unroll
        for (int di = 0; di < 4; di++) acc[qi][di] = 0.f;
    }

    int q_hi = qt * ATQ + ATQ - 1;
    int keff = causal ? min(q_hi + 1, Sk) : Sk;
    int ntiles = (keff + ATK - 1) / ATK;

    int kr = tid >> 2;
    int dq = (tid & 3) * 16;
    float4 pk[4], pv[4];
    {
        int kg = kr;
        bool ok = kg < Sk;
        const float* ksrc = Km + (((size_t)b * Sk + kg) * NH + h) * (size_t)HD + dq;
        const float* vsrc = Vm + (((size_t)b * Sk + kg) * NH + h) * (size_t)HD + dq;
        float4 z = {0.f, 0.f, 0.f, 0.f};
        #pragma unroll
        for (int i = 0; i < 4; i++) {
            pk[i] = ok ? *(const float4*)(ksrc + i * 4) : z;
            pv[i] = ok ? *(const float4*)(vsrc + i * 4) : z;
        }
    }

    for (int kt = 0; kt < ntiles; kt++) {
        #pragma unroll
        for (int i = 0; i < 4; i++) {
            *(float4*)&Ks[kr * APAD + dq + i * 4] = pk[i];
            *(float4*)&Vs[kr * APAD + dq + i * 4] = pv[i];
        }
        __syncthreads();

        if (kt + 1 < ntiles) {
            int kg = (kt + 1) * ATK + kr;
            bool ok = kg < Sk;
            const float* ksrc = Km + (((size_t)b * Sk + kg) * NH + h) * (size_t)HD + dq;
            const float* vsrc = Vm + (((size_t)b * Sk + kg) * NH + h) * (size_t)HD + dq;
            float4 z = {0.f, 0.f, 0.f, 0.f};
            #pragma unroll
            for (int i = 0; i < 4; i++) {
                pk[i] = ok ? *(const float4*)(ksrc + i * 4) : z;
                pv[i] = ok ? *(const float4*)(vsrc + i * 4) : z;
            }
        }

        float s[4][4];
        #pragma unroll
        for (int qi = 0; qi < 4; qi++)
            #pragma unroll
            for (int ki = 0; ki < 4; ki++) s[qi][ki] = 0.f;

        #pragma unroll
        for (int d0 = 0; d0 < HD; d0 += 4) {
            float4 q4[4], k4[4];
            #pragma unroll
            for (int qi = 0; qi < 4; qi++)
                q4[qi] = *(const float4*)&Qs[(qg * 4 + qi) * APAD + d0];
            #pragma unroll
            for (int ki = 0; ki < 4; ki++)
                k4[ki] = *(const float4*)&Ks[(j + 16 * ki) * APAD + d0];
            #pragma unroll
            for (int qi = 0; qi < 4; qi++)
                #pragma unroll
                for (int ki = 0; ki < 4; ki++) {
                    s[qi][ki] += q4[qi].x * k4[ki].x + q4[qi].y * k4[ki].y
                               + q4[qi].z * k4[ki].z + q4[qi].w * k4[ki].w;
                }
        }

        #pragma unroll
        for (int qi = 0; qi < 4; qi++) {
            int qgl = qt * ATQ + qg * 4 + qi;
            int kvalid = causal ? min(qgl + 1, Sk) : Sk;
            #pragma unroll
            for (int ki = 0; ki < 4; ki++) {
                int kg = kt * ATK + j + 16 * ki;
                s[qi][ki] = (kg < kvalid) ? s[qi][ki] * 0.125f : -1e30f;
            }
            float tm = fmaxf(fmaxf(s[qi][0], s[qi][1]), fmaxf(s[qi][2], s[qi][3]));
            #pragma unroll
            for (int off = 1; off < 16; off <<= 1)
                tm = fmaxf(tm, __shfl_xor_sync(0xffffffffu, tm, off));
            float mn = fmaxf(m_i[qi], tm);
            float scale = __expf(m_i[qi] - mn);
            float ps = 0.f;
            #pragma unroll
            for (int ki = 0; ki < 4; ki++) {
                float p = __expf(s[qi][ki] - mn);
                s[qi][ki] = p;
                ps += p;
            }
            #pragma unroll
            for (int off = 1; off < 16; off <<= 1)
                ps += __shfl_xor_sync(0xffffffffu, ps, off);
            l_i[qi] = l_i[qi] * scale + ps;
            m_i[qi] = mn;
            #pragma unroll
            for (int di = 0; di < 4; di++) acc[qi][di] *= scale;
        }

        #pragma unroll
        for (int ki = 0; ki < 4; ki++)
            #pragma unroll
            for (int qi = 0; qi < 4; qi++)
                Ss[(j + 16 * ki) * APAD + qg * 4 + qi] = s[qi][ki];
        __syncthreads();

        #pragma unroll 8
        for (int k = 0; k < ATK; k++) {
            float4 p4 = *(const float4*)&Ss[k * APAD + qg * 4];
            float4 v4 = *(const float4*)&Vs[k * APAD + j * 4];
            acc[0][0] += p4.x * v4.x; acc[0][1] += p4.x * v4.y;
            acc[0][2] += p4.x * v4.z; acc[0][3] += p4.x * v4.w;
            acc[1][0] += p4.y * v4.x; acc[1][1] += p4.y * v4.y;
            acc[1][2] += p4.y * v4.z; acc[1][3] += p4.y * v4.w;
            acc[2][0] += p4.z * v4.x; acc[2][1] += p4.z * v4.y;
            acc[2][2] += p4.z * v4.z; acc[2][3] += p4.z * v4.w;
            acc[3][0] += p4.w * v4.x; acc[3][1] += p4.w * v4.y;
            acc[3][2] += p4.w * v4.z; acc[3][3] += p4.w * v4.w;
        }
        __syncthreads();
    }

    int dd = j * 4;
    #pragma unroll
    for (int qi = 0; qi < 4; qi++) {
        int qgl = qt * ATQ + qg * 4 + qi;
        if (qgl < Sq) {
            float inv = 1.0f / l_i[qi];
            float4 o;
            o.x = rnaf(acc[qi][0] * inv); o.y = rnaf(acc[qi][1] * inv);
            o.z = rnaf(acc[qi][2] * inv); o.w = rnaf(acc[qi][3] * inv);
            *(float4*)&O[(((size_t)b * Sq + qgl) * NH + h) * (size_t)HD + dd] = o;
        }
    }
}

// ---------------- host orchestration ----------------
extern "C" void kernel_launch(void* const* d_in, const int* in_sizes, int n_in,
                              void* d_out, int out_size) {
    const float* tgt      = (const float*)d_in[0];
    const float* memory   = (const float*)d_in[1];
    const float* sa_in_w  = (const float*)d_in[2];
    const float* sa_in_b  = (const float*)d_in[3];
    const float* sa_out_w = (const float*)d_in[4];
    const float* sa_out_b = (const float*)d_in[5];
    const float* ca_in_w  = (const float*)d_in[6];
    const float* ca_in_b  = (const float*)d_in[7];
    const float* ca_out_w = (const float*)d_in[8];
    const float* ca_out_b = (const float*)d_in[9];
    const float* ff1_w    = (const float*)d_in[10];
    const float* ff1_b    = (const float*)d_in[11];
    const float* ff2_w    = (const float*)d_in[12];
    const float* ff2_b    = (const float*)d_in[13];
    const float* ln1_g    = (const float*)d_in[14];
    const float* ln1_b    = (const float*)d_in[15];
    const float* ln2_g    = (const float*)d_in[16];
    const float* ln2_b    = (const float*)d_in[17];
    const float* ln3_g    = (const float*)d_in[18];
    const float* ln3_b    = (const float*)d_in[19];
    float* out = (float*)d_out;

    float *p_h, *p_roped, *p_q, *p_k, *p_v, *p_attn, *p_x, *p_ffh, *p_mem, *p_w;
    cudaGetSymbolAddress((void**)&p_h,     g_h);
    cudaGetSymbolAddress((void**)&p_roped, g_roped);
    cudaGetSymbolAddress((void**)&p_q,     g_q);
    cudaGetSymbolAddress((void**)&p_k,     g_k);
    cudaGetSymbolAddress((void**)&p_v,     g_v);
    cudaGetSymbolAddress((void**)&p_attn,  g_attn);
    cudaGetSymbolAddress((void**)&p_x,     g_x);
    cudaGetSymbolAddress((void**)&p_ffh,   g_ffh);
    cudaGetSymbolAddress((void**)&p_mem,   g_mem);
    cudaGetSymbolAddress((void**)&p_w,     g_w);

    static int smem_set = 0;
    int attn_smem = 4 * ATQ * APAD * sizeof(float);
    if (!smem_set) {
        cudaFuncSetAttribute(attn2_kernel, cudaFuncAttributeMaxDynamicSharedMemorySize, attn_smem);
        cudaFuncSetAttribute(sgemm_tf32, cudaFuncAttributeMaxDynamicSharedMemorySize, GSMEM);
        smem_set = 1;
    }

    // ---- pre-round weights + memory to tf32 ----
    auto roundit = [](const float* src, float* dst, int n) {
        int n4 = n / 4;
        round_tf32_kernel<<<(n4 + 255) / 256, 256>>>((const float4*)src, (float4*)dst, n4);
    };
    roundit(sa_in_w,  p_w + OW_SA_IN,  3 * DMODEL * DMODEL);
    roundit(sa_out_w, p_w + OW_SA_OUT, DMODEL * DMODEL);
    roundit(ca_in_w,  p_w + OW_CA_IN,  3 * DMODEL * DMODEL);
    roundit(ca_out_w, p_w + OW_CA_OUT, DMODEL * DMODEL);
    roundit(ff1_w,    p_w + OW_FF1,    DFF * DMODEL);
    roundit(ff2_w,    p_w + OW_FF2,    DMODEL * DFF);
    roundit(memory,   p_mem,           MTOK * DMODEL);

    dim3 gemm_nt_d(DMODEL / 128, NT / 128);
    dim3 gemm_mt_d(DMODEL / 128, MTOK / 128);
    dim3 gemm_ff1(DFF / 128, NT / 128);
    int rope_blocks = (NT * (DMODEL / 2) + 255) / 256;
    int qtiles = (SQ + ATQ - 1) / ATQ;

    // ---- self-attention block ----
    ln_kernel<<<NT, 256>>>(tgt, ln1_g, ln1_b, p_h, 1);
    rope_kernel<<<rope_blocks, 256>>>(p_h, p_roped);
    sgemm_tf32<<<gemm_nt_d, 256, GSMEM>>>(p_roped, p_w + OW_SA_IN,                          sa_in_b,            nullptr, p_q, NT, DMODEL, DMODEL, 0);
    sgemm_tf32<<<gemm_nt_d, 256, GSMEM>>>(p_roped, p_w + OW_SA_IN + (size_t)DMODEL*DMODEL,  sa_in_b + DMODEL,   nullptr, p_k, NT, DMODEL, DMODEL, 0);
    sgemm_tf32<<<gemm_nt_d, 256, GSMEM>>>(p_h,     p_w + OW_SA_IN + (size_t)2*DMODEL*DMODEL,sa_in_b + 2*DMODEL, nullptr, p_v, NT, DMODEL, DMODEL, 0);
    attn2_kernel<<<dim3(qtiles, NH, BB), 256, attn_smem>>>(p_q, p_k, p_v, p_attn, SQ, SQ, 1);
    sgemm_tf32<<<gemm_nt_d, 256, GSMEM>>>(p_attn, p_w + OW_SA_OUT, sa_out_b, tgt, p_x, NT, DMODEL, DMODEL, 2);

    // ---- cross-attention block ----
    ln_kernel<<<NT, 256>>>(p_x, ln2_g, ln2_b, p_h, 1);
    sgemm_tf32<<<gemm_nt_d, 256, GSMEM>>>(p_h,   p_w + OW_CA_IN,                           ca_in_b,            nullptr, p_q, NT,   DMODEL, DMODEL, 0);
    sgemm_tf32<<<gemm_mt_d, 256, GSMEM>>>(p_mem, p_w + OW_CA_IN + (size_t)DMODEL*DMODEL,   ca_in_b + DMODEL,   nullptr, p_k, MTOK, DMODEL, DMODEL, 0);
    sgemm_tf32<<<gemm_mt_d, 256, GSMEM>>>(p_mem, p_w + OW_CA_IN + (size_t)2*DMODEL*DMODEL, ca_in_b + 2*DMODEL, nullptr, p_v, MTOK, DMODEL, DMODEL, 0);
    attn2_kernel<<<dim3(qtiles, NH, BB), 256, attn_smem>>>(p_q, p_k, p_v, p_attn, SQ, SMEMLEN, 0);
    sgemm_tf32<<<gemm_nt_d, 256, GSMEM>>>(p_attn, p_w + OW_CA_OUT, ca_out_b, p_x, p_x, NT, DMODEL, DMODEL, 2);

    // ---- feed-forward block ----
    ln_kernel<<<NT, 256>>>(p_x, ln3_g, ln3_b, p_h, 1);
    sgemm_tf32<<<gemm_ff1, 256, GSMEM>>>(p_h,   p_w + OW_FF1, ff1_b, nullptr, p_ffh, NT, DFF, DMODEL, 1 | 4);
    sgemm_tf32<<<gemm_nt_d, 256, GSMEM>>>(p_ffh, p_w + OW_FF2, ff2_b, p_x, out, NT, DMODEL, DFF, 2);
}

// round 6
// speedup vs baseline: 1.3205x; 1.2646x over previous
#include <cuda_runtime.h>
#include <cuda_fp16.h>
#include <math.h>

#define BB 32
#define SQ 200
#define SMEMLEN 1024
#define DMODEL 1024
#define NH 16
#define HD 64
#define DFF 4096
#define NT (BB*SQ)        // 6400 target tokens
#define MTOK (BB*SMEMLEN) // 32768 memory tokens
#define EPS 1e-5f

// ---------------- scratch ----------------
__device__ float  g_q[NT*DMODEL];
__device__ float  g_k[MTOK*DMODEL];
__device__ float  g_v[MTOK*DMODEL];
__device__ float  g_x[NT*DMODEL];
__device__ __half g_hh[NT*DMODEL];
__device__ __half g_ropedh[NT*DMODEL];
__device__ __half g_attnh[NT*DMODEL];
__device__ __half g_ffhh[NT*DFF];
__device__ __half g_memh[MTOK*DMODEL];
__device__ __half g_wh[16*1024*1024];   // fp16 weights (packed)

// packed weight offsets (elements)
#define OW_SA_IN   0
#define OW_SA_OUT  3145728
#define OW_CA_IN   4194304
#define OW_CA_OUT  7340032
#define OW_FF1     8388608
#define OW_FF2     12582912

// ---------------- fp32 -> fp16 convert (elementwise) ----------------
__global__ void to_half_kernel(const float4* __restrict__ in,
                               uint2* __restrict__ out, int n4) {
    int i = blockIdx.x * blockDim.x + threadIdx.x;
    if (i < n4) {
        float4 v = in[i];
        __half2 h0 = __floats2half2_rn(v.x, v.y);
        __half2 h1 = __floats2half2_rn(v.z, v.w);
        uint2 o;
        o.x = *(unsigned*)&h0;
        o.y = *(unsigned*)&h1;
        out[i] = o;
    }
}

// ---------------- LayerNorm (fp32 in, fp16 out) ----------------
__global__ __launch_bounds__(256) void ln_kernel(const float* __restrict__ x,
                                                 const float* __restrict__ g,
                                                 const float* __restrict__ b,
                                                 __half* __restrict__ out) {
    __shared__ float rs[8], rss[8];
    int t = blockIdx.x;
    int tid = threadIdx.x;
    const float4* xr = (const float4*)(x + (size_t)t * DMODEL);
    float4 v = xr[tid];
    float s  = v.x + v.y + v.z + v.w;
    float ss = v.x*v.x + v.y*v.y + v.z*v.z + v.w*v.w;
    #pragma unroll
    for (int o = 16; o; o >>= 1) {
        s  += __shfl_xor_sync(0xffffffffu, s, o);
        ss += __shfl_xor_sync(0xffffffffu, ss, o);
    }
    int lane = tid & 31, wid = tid >> 5;
    if (lane == 0) { rs[wid] = s; rss[wid] = ss; }
    __syncthreads();
    float ts = 0.f, tss = 0.f;
    #pragma unroll
    for (int w = 0; w < 8; w++) { ts += rs[w]; tss += rss[w]; }
    float mu  = ts * (1.0f / DMODEL);
    float var = tss * (1.0f / DMODEL) - mu * mu;
    float r   = rsqrtf(var + EPS);
    float4 gv = ((const float4*)g)[tid];
    float4 bv = ((const float4*)b)[tid];
    float ox = (v.x - mu) * r * gv.x + bv.x;
    float oy = (v.y - mu) * r * gv.y + bv.y;
    float oz = (v.z - mu) * r * gv.z + bv.z;
    float ow = (v.w - mu) * r * gv.w + bv.w;
    __half2 h0 = __floats2half2_rn(ox, oy);
    __half2 h1 = __floats2half2_rn(oz, ow);
    uint2 o;
    o.x = *(unsigned*)&h0;
    o.y = *(unsigned*)&h1;
    ((uint2*)(out + (size_t)t * DMODEL))[tid] = o;
}

// ---------------- RoPE (fp16 in/out, fp32 math) ----------------
__global__ void rope_kernel(const __half* __restrict__ in, __half* __restrict__ out) {
    int idx = blockIdx.x * blockDim.x + threadIdx.x;   // pair index
    if (idx >= NT * (DMODEL / 2)) return;
    int t = idx / (DMODEL / 2);
    int p = idx - t * (DMODEL / 2);
    int i = p & 31;
    int s = t % SQ;
    float freq = __expf(-9.210340371976184f * (2.0f * i) * (1.0f / 64.0f));
    float ang = (float)s * freq;
    float sn, cs;
    sincosf(ang, &sn, &cs);
    __half2 xv = ((const __half2*)in)[idx];
    float2 xf = __half22float2(xv);
    float ox = xf.x * cs - xf.y * sn;
    float oy = xf.y * cs + xf.x * sn;
    ((__half2*)out)[idx] = __floats2half2_rn(ox, oy);
}

// ---------------- fp16 tensor-core GEMM (3-stage cp.async + ldmatrix) ----------
// C[M,N] = A[M,K] @ W[N,K]^T + bias  (+relu flag1)(+res fp32 flag2)(out fp16 flag4)
// 128x128 tile, BK=64 halves, 8 warps, warp tile 32x64, m16n8k16.
#define BKH 64
#define RSH 72                           // halves per smem row (8-half pad)
#define NSTG 3
#define STGH (2 * 128 * RSH)             // halves per stage (A+W) = 18432
#define GSMEM (NSTG * STGH * 2)          // 110592 bytes

__device__ __forceinline__ void cpa16(unsigned dst, const void* src) {
    asm volatile("cp.async.cg.shared.global [%0], [%1], 16;\n" :: "r"(dst), "l"(src));
}
__device__ __forceinline__ void ldsm4(unsigned& r0, unsigned& r1, unsigned& r2, unsigned& r3,
                                      unsigned a) {
    asm volatile("ldmatrix.sync.aligned.m8n8.x4.shared.b16 {%0,%1,%2,%3}, [%4];"
                 : "=r"(r0), "=r"(r1), "=r"(r2), "=r"(r3) : "r"(a));
}

__global__ __launch_bounds__(256, 2) void hgemm(const __half* __restrict__ A,
                                                const __half* __restrict__ W,
                                                const float* __restrict__ bias,
                                                const float* __restrict__ res,
                                                void* __restrict__ Cout,
                                                int M, int N, int K, int flags) {
    extern __shared__ __half smh[];
    int tid = threadIdx.x;
    int wid = tid >> 5, lane = tid & 31;
    int gid = lane >> 2, tig = lane & 3;
    int row0 = blockIdx.y * 128;
    int col0 = blockIdx.x * 128;
    int wm = (wid & 3) * 32;
    int wn = (wid >> 2) * 64;

    unsigned sbase = (unsigned)__cvta_generic_to_shared(smh);
    unsigned stgA[NSTG], stgW[NSTG];
    #pragma unroll
    for (int s = 0; s < NSTG; s++) {
        stgA[s] = sbase + s * STGH * 2;
        stgW[s] = stgA[s] + 128 * RSH * 2;
    }

    // loader: thread -> row = tid>>1, half-offset (tid&1)*32, 4 chunks of 8 halves
    int lr = tid >> 1;
    int lc = (tid & 1) * 32;
    const __half* Ab = A + (size_t)(row0 + lr) * K + lc;
    const __half* Wb = W + (size_t)(col0 + lr) * K + lc;

    float c[2][8][4];
    #pragma unroll
    for (int mi = 0; mi < 2; mi++)
        #pragma unroll
        for (int ni = 0; ni < 8; ni++)
            #pragma unroll
            for (int q = 0; q < 4; q++) c[mi][ni][q] = 0.f;

    int nk = K / BKH;

    #pragma unroll
    for (int ps = 0; ps < 2; ps++) {
        int k0 = ps * BKH;
        #pragma unroll
        for (int cch = 0; cch < 4; cch++) {
            unsigned soff = (lr * RSH + lc + cch * 8) * 2;
            cpa16(stgA[ps] + soff, Ab + k0 + cch * 8);
            cpa16(stgW[ps] + soff, Wb + k0 + cch * 8);
        }
        asm volatile("cp.async.commit_group;\n");
    }

    // fragment address components
    int a_row = lane & 15;               // A: rows 0..15 within 16-row block
    int a_col = (lane >> 4) * 8;         // A: +8 halves for upper 16 lanes
    int b_row = (lane & 7) + ((lane & 16) >> 1);   // B: n row 0..7 (+8 for lanes>=16)
    int b_col = lane & 8;                // B: +8 halves for lanes 8-15, 24-31

    unsigned af[2][2][4], bf[2][4][4];

    for (int kt = 0; kt < nk; kt++) {
        if (kt < nk - 1) asm volatile("cp.async.wait_group 1;\n");
        else             asm volatile("cp.async.wait_group 0;\n");
        __syncthreads();

        if (kt + 2 < nk) {
            int st = (kt + 2) % NSTG;
            int k0 = (kt + 2) * BKH;
            #pragma unroll
            for (int cch = 0; cch < 4; cch++) {
                unsigned soff = (lr * RSH + lc + cch * 8) * 2;
                cpa16(stgA[st] + soff, Ab + k0 + cch * 8);
                cpa16(stgW[st] + soff, Wb + k0 + cch * 8);
            }
            asm volatile("cp.async.commit_group;\n");
        }

        int st = kt % NSTG;
        unsigned sAu = stgA[st];
        unsigned sWu = stgW[st];

        auto load_frags = [&](int buf, int ks) {
            int kb = ks * 16;
            #pragma unroll
            for (int mi = 0; mi < 2; mi++)
                ldsm4(af[buf][mi][0], af[buf][mi][1], af[buf][mi][2], af[buf][mi][3],
                      sAu + ((wm + mi * 16 + a_row) * RSH + kb + a_col) * 2);
            #pragma unroll
            for (int p = 0; p < 4; p++)
                ldsm4(bf[buf][p][0], bf[buf][p][1], bf[buf][p][2], bf[buf][p][3],
                      sWu + ((wn + p * 16 + b_row) * RSH + kb + b_col) * 2);
        };

        load_frags(0, 0);
        #pragma unroll
        for (int ks = 0; ks < 4; ks++) {
            int cur = ks & 1;
            if (ks < 3) load_frags(cur ^ 1, ks + 1);
            #pragma unroll
            for (int mi = 0; mi < 2; mi++)
                #pragma unroll
                for (int p = 0; p < 4; p++) {
                    asm volatile(
                        "mma.sync.aligned.m16n8k16.row.col.f32.f16.f16.f32 "
                        "{%0,%1,%2,%3}, {%4,%5,%6,%7}, {%8,%9}, {%0,%1,%2,%3};"
                        : "+f"(c[mi][2*p][0]), "+f"(c[mi][2*p][1]),
                          "+f"(c[mi][2*p][2]), "+f"(c[mi][2*p][3])
                        : "r"(af[cur][mi][0]), "r"(af[cur][mi][1]),
                          "r"(af[cur][mi][2]), "r"(af[cur][mi][3]),
                          "r"(bf[cur][p][0]), "r"(bf[cur][p][1]));
                    asm volatile(
                        "mma.sync.aligned.m16n8k16.row.col.f32.f16.f16.f32 "
                        "{%0,%1,%2,%3}, {%4,%5,%6,%7}, {%8,%9}, {%0,%1,%2,%3};"
                        : "+f"(c[mi][2*p+1][0]), "+f"(c[mi][2*p+1][1]),
                          "+f"(c[mi][2*p+1][2]), "+f"(c[mi][2*p+1][3])
                        : "r"(af[cur][mi][0]), "r"(af[cur][mi][1]),
                          "r"(af[cur][mi][2]), "r"(af[cur][mi][3]),
                          "r"(bf[cur][p][2]), "r"(bf[cur][p][3]));
                }
        }
    }

    bool use_relu = (flags & 1) != 0;
    bool use_res  = (flags & 2) != 0;
    bool out_h    = (flags & 4) != 0;
    float* Cf = (float*)Cout;
    __half* Ch = (__half*)Cout;
    #pragma unroll
    for (int mi = 0; mi < 2; mi++) {
        #pragma unroll
        for (int ni = 0; ni < 8; ni++) {
            int colg = col0 + wn + ni * 8 + tig * 2;
            int r0 = row0 + wm + mi * 16 + gid;
            int r1 = r0 + 8;
            float b0 = bias[colg], b1 = bias[colg + 1];
            float2 o0, o1;
            o0.x = c[mi][ni][0] + b0; o0.y = c[mi][ni][1] + b1;
            o1.x = c[mi][ni][2] + b0; o1.y = c[mi][ni][3] + b1;
            size_t i0 = (size_t)r0 * N + colg;
            size_t i1 = (size_t)r1 * N + colg;
            if (use_res) {
                float2 rv0 = *(const float2*)(res + i0);
                float2 rv1 = *(const float2*)(res + i1);
                o0.x += rv0.x; o0.y += rv0.y;
                o1.x += rv1.x; o1.y += rv1.y;
            }
            if (use_relu) {
                o0.x = fmaxf(o0.x, 0.f); o0.y = fmaxf(o0.y, 0.f);
                o1.x = fmaxf(o1.x, 0.f); o1.y = fmaxf(o1.y, 0.f);
            }
            if (out_h) {
                __half2 h0 = __floats2half2_rn(o0.x, o0.y);
                __half2 h1 = __floats2half2_rn(o1.x, o1.y);
                *(unsigned*)(Ch + i0) = *(unsigned*)&h0;
                *(unsigned*)(Ch + i1) = *(unsigned*)&h1;
            } else {
                *(float2*)(Cf + i0) = o0;
                *(float2*)(Cf + i1) = o1;
            }
        }
    }
}

// ---------------- tiled flash attention (fp32 math, fp16 output) -------------
#define ATQ 64
#define ATK 64
#define APAD 68

__global__ __launch_bounds__(256) void attn2_kernel(const float* __restrict__ Q,
                                                    const float* __restrict__ Km,
                                                    const float* __restrict__ Vm,
                                                    __half* __restrict__ O,
                                                    int Sq, int Sk, int causal) {
    extern __shared__ float sm[];
    float* Qs = sm;
    float* Ks = sm + ATQ * APAD;
    float* Vs = sm + 2 * ATQ * APAD;
    float* Ss = sm + 3 * ATQ * APAD;

    int qt = blockIdx.x, h = blockIdx.y, b = blockIdx.z;
    int tid = threadIdx.x;
    int qg = tid >> 4;
    int j  = tid & 15;

    {
        int qr = tid >> 2;
        int qgl = qt * ATQ + qr;
        int dq = (tid & 3) * 16;
        const float* src = Q + (((size_t)b * Sq + qgl) * NH + h) * (size_t)HD + dq;
        float4 z = {0.f, 0.f, 0.f, 0.f};
        #pragma unroll
        for (int i = 0; i < 4; i++) {
            float4 v = (qgl < Sq) ? *(const float4*)(src + i * 4) : z;
            *(float4*)&Qs[qr * APAD + dq + i * 4] = v;
        }
    }

    float m_i[4], l_i[4], acc[4][4];
    #pragma unroll
    for (int qi = 0; qi < 4; qi++) {
        m_i[qi] = -1e30f; l_i[qi] = 0.f;
        #pragma unroll
        for (int di = 0; di < 4; di++) acc[qi][di] = 0.f;
    }

    int q_hi = qt * ATQ + ATQ - 1;
    int keff = causal ? min(q_hi + 1, Sk) : Sk;
    int ntiles = (keff + ATK - 1) / ATK;

    int kr = tid >> 2;
    int dq = (tid & 3) * 16;
    float4 pk[4], pv[4];
    {
        int kg = kr;
        bool ok = kg < Sk;
        const float* ksrc = Km + (((size_t)b * Sk + kg) * NH + h) * (size_t)HD + dq;
        const float* vsrc = Vm + (((size_t)b * Sk + kg) * NH + h) * (size_t)HD + dq;
        float4 z = {0.f, 0.f, 0.f, 0.f};
        #pragma unroll
        for (int i = 0; i < 4; i++) {
            pk[i] = ok ? *(const float4*)(ksrc + i * 4) : z;
            pv[i] = ok ? *(const float4*)(vsrc + i * 4) : z;
        }
    }

    for (int kt = 0; kt < ntiles; kt++) {
        #pragma unroll
        for (int i = 0; i < 4; i++) {
            *(float4*)&Ks[kr * APAD + dq + i * 4] = pk[i];
            *(float4*)&Vs[kr * APAD + dq + i * 4] = pv[i];
        }
        __syncthreads();

        if (kt + 1 < ntiles) {
            int kg = (kt + 1) * ATK + kr;
            bool ok = kg < Sk;
            const float* ksrc = Km + (((size_t)b * Sk + kg) * NH + h) * (size_t)HD + dq;
            const float* vsrc = Vm + (((size_t)b * Sk + kg) * NH + h) * (size_t)HD + dq;
            float4 z = {0.f, 0.f, 0.f, 0.f};
            #pragma unroll
            for (int i = 0; i < 4; i++) {
                pk[i] = ok ? *(const float4*)(ksrc + i * 4) : z;
                pv[i] = ok ? *(const float4*)(vsrc + i * 4) : z;
            }
        }

        float s[4][4];
        #pragma unroll
        for (int qi = 0; qi < 4; qi++)
            #pragma unroll
            for (int ki = 0; ki < 4; ki++) s[qi][ki] = 0.f;

        #pragma unroll
        for (int d0 = 0; d0 < HD; d0 += 4) {
            float4 q4[4], k4[4];
            #pragma unroll
            for (int qi = 0; qi < 4; qi++)
                q4[qi] = *(const float4*)&Qs[(qg * 4 + qi) * APAD + d0];
            #pragma unroll
            for (int ki = 0; ki < 4; ki++)
                k4[ki] = *(const float4*)&Ks[(j + 16 * ki) * APAD + d0];
            #pragma unroll
            for (int qi = 0; qi < 4; qi++)
                #pragma unroll
                for (int ki = 0; ki < 4; ki++) {
                    s[qi][ki] += q4[qi].x * k4[ki].x + q4[qi].y * k4[ki].y
                               + q4[qi].z * k4[ki].z + q4[qi].w * k4[ki].w;
                }
        }

        #pragma unroll
        for (int qi = 0; qi < 4; qi++) {
            int qgl = qt * ATQ + qg * 4 + qi;
            int kvalid = causal ? min(qgl + 1, Sk) : Sk;
            #pragma unroll
            for (int ki = 0; ki < 4; ki++) {
                int kg = kt * ATK + j + 16 * ki;
                s[qi][ki] = (kg < kvalid) ? s[qi][ki] * 0.125f : -1e30f;
            }
            float tm = fmaxf(fmaxf(s[qi][0], s[qi][1]), fmaxf(s[qi][2], s[qi][3]));
            #pragma unroll
            for (int off = 1; off < 16; off <<= 1)
                tm = fmaxf(tm, __shfl_xor_sync(0xffffffffu, tm, off));
            float mn = fmaxf(m_i[qi], tm);
            float scale = __expf(m_i[qi] - mn);
            float ps = 0.f;
            #pragma unroll
            for (int ki = 0; ki < 4; ki++) {
                float p = __expf(s[qi][ki] - mn);
                s[qi][ki] = p;
                ps += p;
            }
            #pragma unroll
            for (int off = 1; off < 16; off <<= 1)
                ps += __shfl_xor_sync(0xffffffffu, ps, off);
            l_i[qi] = l_i[qi] * scale + ps;
            m_i[qi] = mn;
            #pragma unroll
            for (int di = 0; di < 4; di++) acc[qi][di] *= scale;
        }

        #pragma unroll
        for (int ki = 0; ki < 4; ki++)
            #pragma unroll
            for (int qi = 0; qi < 4; qi++)
                Ss[(j + 16 * ki) * APAD + qg * 4 + qi] = s[qi][ki];
        __syncthreads();

        #pragma unroll 8
        for (int k = 0; k < ATK; k++) {
            float4 p4 = *(const float4*)&Ss[k * APAD + qg * 4];
            float4 v4 = *(const float4*)&Vs[k * APAD + j * 4];
            acc[0][0] += p4.x * v4.x; acc[0][1] += p4.x * v4.y;
            acc[0][2] += p4.x * v4.z; acc[0][3] += p4.x * v4.w;
            acc[1][0] += p4.y * v4.x; acc[1][1] += p4.y * v4.y;
            acc[1][2] += p4.y * v4.z; acc[1][3] += p4.y * v4.w;
            acc[2][0] += p4.z * v4.x; acc[2][1] += p4.z * v4.y;
            acc[2][2] += p4.z * v4.z; acc[2][3] += p4.z * v4.w;
            acc[3][0] += p4.w * v4.x; acc[3][1] += p4.w * v4.y;
            acc[3][2] += p4.w * v4.z; acc[3][3] += p4.w * v4.w;
        }
        __syncthreads();
    }

    int dd = j * 4;
    #pragma unroll
    for (int qi = 0; qi < 4; qi++) {
        int qgl = qt * ATQ + qg * 4 + qi;
        if (qgl < Sq) {
            float inv = 1.0f / l_i[qi];
            __half2 h0 = __floats2half2_rn(acc[qi][0] * inv, acc[qi][1] * inv);
            __half2 h1 = __floats2half2_rn(acc[qi][2] * inv, acc[qi][3] * inv);
            __half* dst = O + (((size_t)b * Sq + qgl) * NH + h) * (size_t)HD + dd;
            *(unsigned*)(dst)     = *(unsigned*)&h0;
            *(unsigned*)(dst + 2) = *(unsigned*)&h1;
        }
    }
}

// ---------------- host orchestration ----------------
extern "C" void kernel_launch(void* const* d_in, const int* in_sizes, int n_in,
                              void* d_out, int out_size) {
    const float* tgt      = (const float*)d_in[0];
    const float* memory   = (const float*)d_in[1];
    const float* sa_in_w  = (const float*)d_in[2];
    const float* sa_in_b  = (const float*)d_in[3];
    const float* sa_out_w = (const float*)d_in[4];
    const float* sa_out_b = (const float*)d_in[5];
    const float* ca_in_w  = (const float*)d_in[6];
    const float* ca_in_b  = (const float*)d_in[7];
    const float* ca_out_w = (const float*)d_in[8];
    const float* ca_out_b = (const float*)d_in[9];
    const float* ff1_w    = (const float*)d_in[10];
    const float* ff1_b    = (const float*)d_in[11];
    const float* ff2_w    = (const float*)d_in[12];
    const float* ff2_b    = (const float*)d_in[13];
    const float* ln1_g    = (const float*)d_in[14];
    const float* ln1_b    = (const float*)d_in[15];
    const float* ln2_g    = (const float*)d_in[16];
    const float* ln2_b    = (const float*)d_in[17];
    const float* ln3_g    = (const float*)d_in[18];
    const float* ln3_b    = (const float*)d_in[19];
    float* out = (float*)d_out;

    float *p_q, *p_k, *p_v, *p_x;
    __half *p_hh, *p_ropedh, *p_attnh, *p_ffhh, *p_memh, *p_wh;
    cudaGetSymbolAddress((void**)&p_q,      g_q);
    cudaGetSymbolAddress((void**)&p_k,      g_k);
    cudaGetSymbolAddress((void**)&p_v,      g_v);
    cudaGetSymbolAddress((void**)&p_x,      g_x);
    cudaGetSymbolAddress((void**)&p_hh,     g_hh);
    cudaGetSymbolAddress((void**)&p_ropedh, g_ropedh);
    cudaGetSymbolAddress((void**)&p_attnh,  g_attnh);
    cudaGetSymbolAddress((void**)&p_ffhh,   g_ffhh);
    cudaGetSymbolAddress((void**)&p_memh,   g_memh);
    cudaGetSymbolAddress((void**)&p_wh,     g_wh);

    static int smem_set = 0;
    int attn_smem = 4 * ATQ * APAD * sizeof(float);
    if (!smem_set) {
        cudaFuncSetAttribute(attn2_kernel, cudaFuncAttributeMaxDynamicSharedMemorySize, attn_smem);
        cudaFuncSetAttribute(hgemm, cudaFuncAttributeMaxDynamicSharedMemorySize, GSMEM);
        smem_set = 1;
    }

    // ---- convert weights + memory to fp16 ----
    auto tohalf = [](const float* src, __half* dst, int n) {
        int n4 = n / 4;
        to_half_kernel<<<(n4 + 255) / 256, 256>>>((const float4*)src, (uint2*)dst, n4);
    };
    tohalf(sa_in_w,  p_wh + OW_SA_IN,  3 * DMODEL * DMODEL);
    tohalf(sa_out_w, p_wh + OW_SA_OUT, DMODEL * DMODEL);
    tohalf(ca_in_w,  p_wh + OW_CA_IN,  3 * DMODEL * DMODEL);
    tohalf(ca_out_w, p_wh + OW_CA_OUT, DMODEL * DMODEL);
    tohalf(ff1_w,    p_wh + OW_FF1,    DFF * DMODEL);
    tohalf(ff2_w,    p_wh + OW_FF2,    DMODEL * DFF);
    tohalf(memory,   p_memh,           MTOK * DMODEL);

    dim3 gemm_nt_d(DMODEL / 128, NT / 128);      // (8, 50)
    dim3 gemm_mt_d(DMODEL / 128, MTOK / 128);    // (8, 256)
    dim3 gemm_ff1(DFF / 128, NT / 128);          // (32, 50)
    int rope_blocks = (NT * (DMODEL / 2) + 255) / 256;
    int qtiles = (SQ + ATQ - 1) / ATQ;

    // ---- self-attention block ----
    ln_kernel<<<NT, 256>>>(tgt, ln1_g, ln1_b, p_hh);
    rope_kernel<<<rope_blocks, 256>>>(p_hh, p_ropedh);
    hgemm<<<gemm_nt_d, 256, GSMEM>>>(p_ropedh, p_wh + OW_SA_IN,                           sa_in_b,            nullptr, p_q, NT, DMODEL, DMODEL, 0);
    hgemm<<<gemm_nt_d, 256, GSMEM>>>(p_ropedh, p_wh + OW_SA_IN + (size_t)DMODEL*DMODEL,   sa_in_b + DMODEL,   nullptr, p_k, NT, DMODEL, DMODEL, 0);
    hgemm<<<gemm_nt_d, 256, GSMEM>>>(p_hh,     p_wh + OW_SA_IN + (size_t)2*DMODEL*DMODEL, sa_in_b + 2*DMODEL, nullptr, p_v, NT, DMODEL, DMODEL, 0);
    attn2_kernel<<<dim3(qtiles, NH, BB), 256, attn_smem>>>(p_q, p_k, p_v, p_attnh, SQ, SQ, 1);
    hgemm<<<gemm_nt_d, 256, GSMEM>>>(p_attnh, p_wh + OW_SA_OUT, sa_out_b, tgt, p_x, NT, DMODEL, DMODEL, 2);

    // ---- cross-attention block ----
    ln_kernel<<<NT, 256>>>(p_x, ln2_g, ln2_b, p_hh);
    hgemm<<<gemm_nt_d, 256, GSMEM>>>(p_hh,   p_wh + OW_CA_IN,                           ca_in_b,            nullptr, p_q, NT,   DMODEL, DMODEL, 0);
    hgemm<<<gemm_mt_d, 256, GSMEM>>>(p_memh, p_wh + OW_CA_IN + (size_t)DMODEL*DMODEL,   ca_in_b + DMODEL,   nullptr, p_k, MTOK, DMODEL, DMODEL, 0);
    hgemm<<<gemm_mt_d, 256, GSMEM>>>(p_memh, p_wh + OW_CA_IN + (size_t)2*DMODEL*DMODEL, ca_in_b + 2*DMODEL, nullptr, p_v, MTOK, DMODEL, DMODEL, 0);
    attn2_kernel<<<dim3(qtiles, NH, BB), 256, attn_smem>>>(p_q, p_k, p_v, p_attnh, SQ, SMEMLEN, 0);
    hgemm<<<gemm_nt_d, 256, GSMEM>>>(p_attnh, p_wh + OW_CA_OUT, ca_out_b, p_x, p_x, NT, DMODEL, DMODEL, 2);

    // ---- feed-forward block ----
    ln_kernel<<<NT, 256>>>(p_x, ln3_g, ln3_b, p_hh);
    hgemm<<<gemm_ff1, 256, GSMEM>>>(p_hh,   p_wh + OW_FF1, ff1_b, nullptr, p_ffhh, NT, DFF, DMODEL, 1 | 4);
    hgemm<<<gemm_nt_d, 256, GSMEM>>>(p_ffhh, p_wh + OW_FF2, ff2_b, p_x, out, NT, DMODEL, DFF, 2);
}

// round 9
// speedup vs baseline: 2.0396x; 1.5446x over previous
#include <cuda_runtime.h>
#include <cuda_fp16.h>
#include <math.h>

#define BB 32
#define SQ 200
#define SMEMLEN 1024
#define DMODEL 1024
#define NH 16
#define HD 64
#define DFF 4096
#define NT (BB*SQ)        // 6400 target tokens
#define MTOK (BB*SMEMLEN) // 32768 memory tokens
#define EPS 1e-5f

// ---------------- scratch ----------------
__device__ float  g_x[NT*DMODEL];
__device__ __half g_qh[NT*DMODEL];
__device__ __half g_kh[MTOK*DMODEL];
__device__ __half g_vh[MTOK*DMODEL];
__device__ __half g_hh[NT*DMODEL];
__device__ __half g_ropedh[NT*DMODEL];
__device__ __half g_attnh[NT*DMODEL];
__device__ __half g_ffhh[NT*DFF];
__device__ __half g_memh[MTOK*DMODEL];
__device__ __half g_wh[16*1024*1024];   // fp16 weights (packed)

#define OW_SA_IN   0
#define OW_SA_OUT  3145728
#define OW_CA_IN   4194304
#define OW_CA_OUT  7340032
#define OW_FF1     8388608
#define OW_FF2     12582912

// ---------------- fp32 -> fp16 convert ----------------
__global__ void to_half_kernel(const float4* __restrict__ in,
                               uint2* __restrict__ out, int n4) {
    int i = blockIdx.x * blockDim.x + threadIdx.x;
    if (i < n4) {
        float4 v = in[i];
        __half2 h0 = __floats2half2_rn(v.x, v.y);
        __half2 h1 = __floats2half2_rn(v.z, v.w);
        uint2 o;
        o.x = *(unsigned*)&h0;
        o.y = *(unsigned*)&h1;
        out[i] = o;
    }
}

// ---------------- LayerNorm (fp32 in, fp16 out) ----------------
__global__ __launch_bounds__(256) void ln_kernel(const float* __restrict__ x,
                                                 const float* __restrict__ g,
                                                 const float* __restrict__ b,
                                                 __half* __restrict__ out) {
    __shared__ float rs[8], rss[8];
    int t = blockIdx.x;
    int tid = threadIdx.x;
    const float4* xr = (const float4*)(x + (size_t)t * DMODEL);
    float4 v = xr[tid];
    float s  = v.x + v.y + v.z + v.w;
    float ss = v.x*v.x + v.y*v.y + v.z*v.z + v.w*v.w;
    #pragma unroll
    for (int o = 16; o; o >>= 1) {
        s  += __shfl_xor_sync(0xffffffffu, s, o);
        ss += __shfl_xor_sync(0xffffffffu, ss, o);
    }
    int lane = tid & 31, wid = tid >> 5;
    if (lane == 0) { rs[wid] = s; rss[wid] = ss; }
    __syncthreads();
    float ts = 0.f, tss = 0.f;
    #pragma unroll
    for (int w = 0; w < 8; w++) { ts += rs[w]; tss += rss[w]; }
    float mu  = ts * (1.0f / DMODEL);
    float var = tss * (1.0f / DMODEL) - mu * mu;
    float r   = rsqrtf(var + EPS);
    float4 gv = ((const float4*)g)[tid];
    float4 bv = ((const float4*)b)[tid];
    float ox = (v.x - mu) * r * gv.x + bv.x;
    float oy = (v.y - mu) * r * gv.y + bv.y;
    float oz = (v.z - mu) * r * gv.z + bv.z;
    float ow = (v.w - mu) * r * gv.w + bv.w;
    __half2 h0 = __floats2half2_rn(ox, oy);
    __half2 h1 = __floats2half2_rn(oz, ow);
    uint2 o;
    o.x = *(unsigned*)&h0;
    o.y = *(unsigned*)&h1;
    ((uint2*)(out + (size_t)t * DMODEL))[tid] = o;
}

// ---------------- RoPE (fp16 in/out, fp32 math) ----------------
__global__ void rope_kernel(const __half* __restrict__ in, __half* __restrict__ out) {
    int idx = blockIdx.x * blockDim.x + threadIdx.x;
    if (idx >= NT * (DMODEL / 2)) return;
    int t = idx / (DMODEL / 2);
    int p = idx - t * (DMODEL / 2);
    int i = p & 31;
    int s = t % SQ;
    float freq = __expf(-9.210340371976184f * (2.0f * i) * (1.0f / 64.0f));
    float ang = (float)s * freq;
    float sn, cs;
    sincosf(ang, &sn, &cs);
    __half2 xv = ((const __half2*)in)[idx];
    float2 xf = __half22float2(xv);
    float ox = xf.x * cs - xf.y * sn;
    float oy = xf.y * cs + xf.x * sn;
    ((__half2*)out)[idx] = __floats2half2_rn(ox, oy);
}

// ---------------- common mma helpers ----------------
__device__ __forceinline__ void cpa16(unsigned dst, const void* src) {
    asm volatile("cp.async.cg.shared.global [%0], [%1], 16;\n" :: "r"(dst), "l"(src));
}
__device__ __forceinline__ void ldsm4(unsigned& r0, unsigned& r1, unsigned& r2, unsigned& r3,
                                      unsigned a) {
    asm volatile("ldmatrix.sync.aligned.m8n8.x4.shared.b16 {%0,%1,%2,%3}, [%4];"
                 : "=r"(r0), "=r"(r1), "=r"(r2), "=r"(r3) : "r"(a));
}
__device__ __forceinline__ void ldsm4t(unsigned& r0, unsigned& r1, unsigned& r2, unsigned& r3,
                                       unsigned a) {
    asm volatile("ldmatrix.sync.aligned.m8n8.x4.trans.shared.b16 {%0,%1,%2,%3}, [%4];"
                 : "=r"(r0), "=r"(r1), "=r"(r2), "=r"(r3) : "r"(a));
}
__device__ __forceinline__ void mma16816(float* c, unsigned a0, unsigned a1, unsigned a2,
                                         unsigned a3, unsigned b0, unsigned b1) {
    asm volatile(
        "mma.sync.aligned.m16n8k16.row.col.f32.f16.f16.f32 "
        "{%0,%1,%2,%3}, {%4,%5,%6,%7}, {%8,%9}, {%0,%1,%2,%3};"
        : "+f"(c[0]), "+f"(c[1]), "+f"(c[2]), "+f"(c[3])
        : "r"(a0), "r"(a1), "r"(a2), "r"(a3), "r"(b0), "r"(b1));
}

// ---------------- fp16 tensor-core GEMM (3-stage cp.async + ldmatrix) ----------
#define BKH 64
#define RSH 72
#define NSTG 3
#define STGH (2 * 128 * RSH)
#define GSMEM (NSTG * STGH * 2)          // 110592 bytes

__global__ __launch_bounds__(256, 2) void hgemm(const __half* __restrict__ A,
                                                const __half* __restrict__ W,
                                                const float* __restrict__ bias,
                                                const float* __restrict__ res,
                                                void* __restrict__ Cout,
                                                int M, int N, int K, int flags) {
    extern __shared__ __half smh[];
    int tid = threadIdx.x;
    int wid = tid >> 5, lane = tid & 31;
    int gid = lane >> 2, tig = lane & 3;
    int row0 = blockIdx.y * 128;
    int col0 = blockIdx.x * 128;
    int wm = (wid & 3) * 32;
    int wn = (wid >> 2) * 64;

    unsigned sbase = (unsigned)__cvta_generic_to_shared(smh);
    unsigned stgA[NSTG], stgW[NSTG];
    #pragma unroll
    for (int s = 0; s < NSTG; s++) {
        stgA[s] = sbase + s * STGH * 2;
        stgW[s] = stgA[s] + 128 * RSH * 2;
    }

    int lr = tid >> 1;
    int lc = (tid & 1) * 32;
    const __half* Ab = A + (size_t)(row0 + lr) * K + lc;
    const __half* Wb = W + (size_t)(col0 + lr) * K + lc;

    float c[2][8][4];
    #pragma unroll
    for (int mi = 0; mi < 2; mi++)
        #pragma unroll
        for (int ni = 0; ni < 8; ni++)
            #pragma unroll
            for (int q = 0; q < 4; q++) c[mi][ni][q] = 0.f;

    int nk = K / BKH;

    #pragma unroll
    for (int ps = 0; ps < 2; ps++) {
        int k0 = ps * BKH;
        #pragma unroll
        for (int cch = 0; cch < 4; cch++) {
            unsigned soff = (lr * RSH + lc + cch * 8) * 2;
            cpa16(stgA[ps] + soff, Ab + k0 + cch * 8);
            cpa16(stgW[ps] + soff, Wb + k0 + cch * 8);
        }
        asm volatile("cp.async.commit_group;\n");
    }

    int a_row = lane & 15;
    int a_col = (lane >> 4) * 8;
    int b_row = (lane & 7) + ((lane & 16) >> 1);
    int b_col = lane & 8;

    unsigned af[2][2][4], bf[2][4][4];

    for (int kt = 0; kt < nk; kt++) {
        if (kt < nk - 1) asm volatile("cp.async.wait_group 1;\n");
        else             asm volatile("cp.async.wait_group 0;\n");
        __syncthreads();

        if (kt + 2 < nk) {
            int st = (kt + 2) % NSTG;
            int k0 = (kt + 2) * BKH;
            #pragma unroll
            for (int cch = 0; cch < 4; cch++) {
                unsigned soff = (lr * RSH + lc + cch * 8) * 2;
                cpa16(stgA[st] + soff, Ab + k0 + cch * 8);
                cpa16(stgW[st] + soff, Wb + k0 + cch * 8);
            }
            asm volatile("cp.async.commit_group;\n");
        }

        int st = kt % NSTG;
        unsigned sAu = stgA[st];
        unsigned sWu = stgW[st];

        auto load_frags = [&](int buf, int ks) {
            int kb = ks * 16;
            #pragma unroll
            for (int mi = 0; mi < 2; mi++)
                ldsm4(af[buf][mi][0], af[buf][mi][1], af[buf][mi][2], af[buf][mi][3],
                      sAu + ((wm + mi * 16 + a_row) * RSH + kb + a_col) * 2);
            #pragma unroll
            for (int p = 0; p < 4; p++)
                ldsm4(bf[buf][p][0], bf[buf][p][1], bf[buf][p][2], bf[buf][p][3],
                      sWu + ((wn + p * 16 + b_row) * RSH + kb + b_col) * 2);
        };

        load_frags(0, 0);
        #pragma unroll
        for (int ks = 0; ks < 4; ks++) {
            int cur = ks & 1;
            if (ks < 3) load_frags(cur ^ 1, ks + 1);
            #pragma unroll
            for (int mi = 0; mi < 2; mi++)
                #pragma unroll
                for (int p = 0; p < 4; p++) {
                    mma16816(c[mi][2*p],   af[cur][mi][0], af[cur][mi][1], af[cur][mi][2],
                             af[cur][mi][3], bf[cur][p][0], bf[cur][p][1]);
                    mma16816(c[mi][2*p+1], af[cur][mi][0], af[cur][mi][1], af[cur][mi][2],
                             af[cur][mi][3], bf[cur][p][2], bf[cur][p][3]);
                }
        }
    }

    bool use_relu = (flags & 1) != 0;
    bool use_res  = (flags & 2) != 0;
    bool out_h    = (flags & 4) != 0;
    float* Cf = (float*)Cout;
    __half* Ch = (__half*)Cout;
    #pragma unroll
    for (int mi = 0; mi < 2; mi++) {
        #pragma unroll
        for (int ni = 0; ni < 8; ni++) {
            int colg = col0 + wn + ni * 8 + tig * 2;
            int r0 = row0 + wm + mi * 16 + gid;
            int r1 = r0 + 8;
            float b0 = bias[colg], b1 = bias[colg + 1];
            float2 o0, o1;
            o0.x = c[mi][ni][0] + b0; o0.y = c[mi][ni][1] + b1;
            o1.x = c[mi][ni][2] + b0; o1.y = c[mi][ni][3] + b1;
            size_t i0 = (size_t)r0 * N + colg;
            size_t i1 = (size_t)r1 * N + colg;
            if (use_res) {
                float2 rv0 = *(const float2*)(res + i0);
                float2 rv1 = *(const float2*)(res + i1);
                o0.x += rv0.x; o0.y += rv0.y;
                o1.x += rv1.x; o1.y += rv1.y;
            }
            if (use_relu) {
                o0.x = fmaxf(o0.x, 0.f); o0.y = fmaxf(o0.y, 0.f);
                o1.x = fmaxf(o1.x, 0.f); o1.y = fmaxf(o1.y, 0.f);
            }
            if (out_h) {
                __half2 h0 = __floats2half2_rn(o0.x, o0.y);
                __half2 h1 = __floats2half2_rn(o1.x, o1.y);
                *(unsigned*)(Ch + i0) = *(unsigned*)&h0;
                *(unsigned*)(Ch + i1) = *(unsigned*)&h1;
            } else {
                *(float2*)(Cf + i0) = o0;
                *(float2*)(Cf + i1) = o1;
            }
        }
    }
}

// ---------------- fp16 tensor-core flash attention ----------------
// block = 128 thr / 4 warps; 64 q rows per block; warp w owns q rows w*16..+15.
// K tiles of 64 keys. S via m16n8k16 (K frags = hgemm W path), online softmax on
// fragments, P repacked reg-to-reg, PV via ldmatrix.trans V fragments.
#define AQ 64
#define AK 64
#define AH 72   // halves per smem row

__global__ __launch_bounds__(128) void attn_h(const __half* __restrict__ Q,
                                              const __half* __restrict__ Km,
                                              const __half* __restrict__ Vm,
                                              __half* __restrict__ O,
                                              int Sq, int Sk, int causal) {
    __shared__ __half Qs[AQ*AH], Ks[AK*AH], Vs[AK*AH];

    int qt = blockIdx.x, h = blockIdx.y, b = blockIdx.z;
    int tid = threadIdx.x;
    int wid = tid >> 5, lane = tid & 31;

    unsigned sQ = (unsigned)__cvta_generic_to_shared(Qs);
    unsigned sK = (unsigned)__cvta_generic_to_shared(Ks);
    unsigned sV = (unsigned)__cvta_generic_to_shared(Vs);

    // ---- load Q tile to smem (fp16), zero-fill rows >= Sq ----
    {
        int r = tid >> 1;
        int cb = (tid & 1) * 32;
        int qgl = qt * AQ + r;
        const __half* src = Q + ((size_t)(b * Sq + qgl)) * DMODEL + h * HD + cb;
        uint4 z = {0u, 0u, 0u, 0u};
        #pragma unroll
        for (int i = 0; i < 4; i++) {
            uint4 v = (qgl < Sq) ? *(const uint4*)(src + i * 8) : z;
            *(uint4*)&Qs[r * AH + cb + i * 8] = v;
        }
    }
    __syncthreads();

    // ---- Q fragments (all 4 k-steps), same addressing as hgemm A ----
    int a_row = lane & 15;
    int a_col = (lane >> 4) * 8;
    unsigned aq[4][4];
    #pragma unroll
    for (int ks = 0; ks < 4; ks++)
        ldsm4(aq[ks][0], aq[ks][1], aq[ks][2], aq[ks][3],
              sQ + ((wid * 16 + a_row) * AH + ks * 16 + a_col) * 2);

    int b_row = (lane & 7) + ((lane & 16) >> 1);
    int b_col = lane & 8;

    // per-thread softmax state: rows r0 = lane>>2, r1 = r0+8 within warp m16
    int r0 = lane >> 2, tig = lane & 3;
    int qgl0 = qt * AQ + wid * 16 + r0;
    int qgl1 = qgl0 + 8;
    float m0 = -1e30f, m1 = -1e30f, l0 = 0.f, l1 = 0.f;
    float o[8][4];
    #pragma unroll
    for (int j = 0; j < 8; j++)
        #pragma unroll
        for (int q = 0; q < 4; q++) o[j][q] = 0.f;

    int q_hi = qt * AQ + AQ - 1;
    int keff = causal ? min(q_hi + 1, Sk) : Sk;
    int ntiles = (keff + AK - 1) / AK;

    // K/V register prefetch (tile 0)
    int kvr = tid >> 1;
    int kvc = (tid & 1) * 32;
    uint4 pk[4], pv[4];
    {
        int kg = kvr;
        bool ok = kg < Sk;
        const __half* ks = Km + ((size_t)(b * Sk + kg)) * DMODEL + h * HD + kvc;
        const __half* vs = Vm + ((size_t)(b * Sk + kg)) * DMODEL + h * HD + kvc;
        uint4 z = {0u, 0u, 0u, 0u};
        #pragma unroll
        for (int i = 0; i < 4; i++) {
            pk[i] = ok ? *(const uint4*)(ks + i * 8) : z;
            pv[i] = ok ? *(const uint4*)(vs + i * 8) : z;
        }
    }

    for (int kt = 0; kt < ntiles; kt++) {
        #pragma unroll
        for (int i = 0; i < 4; i++) {
            *(uint4*)&Ks[kvr * AH + kvc + i * 8] = pk[i];
            *(uint4*)&Vs[kvr * AH + kvc + i * 8] = pv[i];
        }
        __syncthreads();

        if (kt + 1 < ntiles) {
            int kg = (kt + 1) * AK + kvr;
            bool ok = kg < Sk;
            const __half* ks = Km + ((size_t)(b * Sk + kg)) * DMODEL + h * HD + kvc;
            const __half* vs = Vm + ((size_t)(b * Sk + kg)) * DMODEL + h * HD + kvc;
            uint4 z = {0u, 0u, 0u, 0u};
            #pragma unroll
            for (int i = 0; i < 4; i++) {
                pk[i] = ok ? *(const uint4*)(ks + i * 8) : z;
                pv[i] = ok ? *(const uint4*)(vs + i * 8) : z;
            }
        }

        // ---- S = Q @ K^T : s[8][4] fp32 (8 n8-tiles over 64 keys) ----
        float s[8][4];
        #pragma unroll
        for (int j = 0; j < 8; j++)
            #pragma unroll
            for (int q = 0; q < 4; q++) s[j][q] = 0.f;

        #pragma unroll
        for (int ks = 0; ks < 4; ks++) {
            #pragma unroll
            for (int p = 0; p < 4; p++) {
                unsigned bf0, bf1, bf2, bf3;
                ldsm4(bf0, bf1, bf2, bf3,
                      sK + ((p * 16 + b_row) * AH + ks * 16 + b_col) * 2);
                mma16816(s[2*p],   aq[ks][0], aq[ks][1], aq[ks][2], aq[ks][3], bf0, bf1);
                mma16816(s[2*p+1], aq[ks][0], aq[ks][1], aq[ks][2], aq[ks][3], bf2, bf3);
            }
        }

        // ---- mask + online softmax on fragments ----
        int kvalid0 = causal ? min(qgl0 + 1, Sk) : Sk;
        int kvalid1 = causal ? min(qgl1 + 1, Sk) : Sk;
        int kgb = kt * AK + tig * 2;
        float tm0 = -1e30f, tm1 = -1e30f;
        #pragma unroll
        for (int j = 0; j < 8; j++) {
            int kg = kgb + j * 8;
            s[j][0] = (kg     < kvalid0) ? s[j][0] * 0.125f : -1e30f;
            s[j][1] = (kg + 1 < kvalid0) ? s[j][1] * 0.125f : -1e30f;
            s[j][2] = (kg     < kvalid1) ? s[j][2] * 0.125f : -1e30f;
            s[j][3] = (kg + 1 < kvalid1) ? s[j][3] * 0.125f : -1e30f;
            tm0 = fmaxf(tm0, fmaxf(s[j][0], s[j][1]));
            tm1 = fmaxf(tm1, fmaxf(s[j][2], s[j][3]));
        }
        tm0 = fmaxf(tm0, __shfl_xor_sync(0xffffffffu, tm0, 1));
        tm0 = fmaxf(tm0, __shfl_xor_sync(0xffffffffu, tm0, 2));
        tm1 = fmaxf(tm1, __shfl_xor_sync(0xffffffffu, tm1, 1));
        tm1 = fmaxf(tm1, __shfl_xor_sync(0xffffffffu, tm1, 2));

        float mn0 = fmaxf(m0, tm0), mn1 = fmaxf(m1, tm1);
        float sc0 = __expf(m0 - mn0), sc1 = __expf(m1 - mn1);
        float ps0 = 0.f, ps1 = 0.f;
        #pragma unroll
        for (int j = 0; j < 8; j++) {
            s[j][0] = __expf(s[j][0] - mn0);
            s[j][1] = __expf(s[j][1] - mn0);
            s[j][2] = __expf(s[j][2] - mn1);
            s[j][3] = __expf(s[j][3] - mn1);
            ps0 += s[j][0] + s[j][1];
            ps1 += s[j][2] + s[j][3];
        }
        ps0 += __shfl_xor_sync(0xffffffffu, ps0, 1);
        ps0 += __shfl_xor_sync(0xffffffffu, ps0, 2);
        ps1 += __shfl_xor_sync(0xffffffffu, ps1, 1);
        ps1 += __shfl_xor_sync(0xffffffffu, ps1, 2);
        l0 = l0 * sc0 + ps0;  m0 = mn0;
        l1 = l1 * sc1 + ps1;  m1 = mn1;
        #pragma unroll
        for (int j = 0; j < 8; j++) {
            o[j][0] *= sc0; o[j][1] *= sc0;
            o[j][2] *= sc1; o[j][3] *= sc1;
        }

        // ---- P fragments (reg repack: C(m16n8)x2 -> A(m16k16)) ----
        unsigned pa[4][4];
        #pragma unroll
        for (int t = 0; t < 4; t++) {
            __half2 h0 = __floats2half2_rn(s[2*t][0],   s[2*t][1]);
            __half2 h1 = __floats2half2_rn(s[2*t][2],   s[2*t][3]);
            __half2 h2 = __floats2half2_rn(s[2*t+1][0], s[2*t+1][1]);
            __half2 h3 = __floats2half2_rn(s[2*t+1][2], s[2*t+1][3]);
            pa[t][0] = *(unsigned*)&h0;
            pa[t][1] = *(unsigned*)&h1;
            pa[t][2] = *(unsigned*)&h2;
            pa[t][3] = *(unsigned*)&h3;
        }

        // ---- O += P @ V : V B-frags via ldmatrix.trans on [k][n] ----
        #pragma unroll
        for (int t = 0; t < 4; t++) {
            #pragma unroll
            for (int p = 0; p < 4; p++) {
                unsigned bv0, bv1, bv2, bv3;
                ldsm4t(bv0, bv1, bv2, bv3,
                       sV + ((t * 16 + (lane & 15)) * AH + p * 16 + (lane >> 4) * 8) * 2);
                mma16816(o[2*p],   pa[t][0], pa[t][1], pa[t][2], pa[t][3], bv0, bv1);
                mma16816(o[2*p+1], pa[t][0], pa[t][1], pa[t][2], pa[t][3], bv2, bv3);
            }
        }
        __syncthreads();
    }

    // ---- write O (fp16) ----
    float inv0 = 1.0f / l0, inv1 = 1.0f / l1;
    #pragma unroll
    for (int j = 0; j < 8; j++) {
        int d = j * 8 + tig * 2;
        if (qgl0 < Sq) {
            __half2 h0 = __floats2half2_rn(o[j][0] * inv0, o[j][1] * inv0);
            *(unsigned*)(O + ((size_t)(b * Sq + qgl0)) * DMODEL + h * HD + d) = *(unsigned*)&h0;
        }
        if (qgl1 < Sq) {
            __half2 h1 = __floats2half2_rn(o[j][2] * inv1, o[j][3] * inv1);
            *(unsigned*)(O + ((size_t)(b * Sq + qgl1)) * DMODEL + h * HD + d) = *(unsigned*)&h1;
        }
    }
}

// ---------------- host orchestration ----------------
extern "C" void kernel_launch(void* const* d_in, const int* in_sizes, int n_in,
                              void* d_out, int out_size) {
    const float* tgt      = (const float*)d_in[0];
    const float* memory   = (const float*)d_in[1];
    const float* sa_in_w  = (const float*)d_in[2];
    const float* sa_in_b  = (const float*)d_in[3];
    const float* sa_out_w = (const float*)d_in[4];
    const float* sa_out_b = (const float*)d_in[5];
    const float* ca_in_w  = (const float*)d_in[6];
    const float* ca_in_b  = (const float*)d_in[7];
    const float* ca_out_w = (const float*)d_in[8];
    const float* ca_out_b = (const float*)d_in[9];
    const float* ff1_w    = (const float*)d_in[10];
    const float* ff1_b    = (const float*)d_in[11];
    const float* ff2_w    = (const float*)d_in[12];
    const float* ff2_b    = (const float*)d_in[13];
    const float* ln1_g    = (const float*)d_in[14];
    const float* ln1_b    = (const float*)d_in[15];
    const float* ln2_g    = (const float*)d_in[16];
    const float* ln2_b    = (const float*)d_in[17];
    const float* ln3_g    = (const float*)d_in[18];
    const float* ln3_b    = (const float*)d_in[19];
    float* out = (float*)d_out;

    float *p_x;
    __half *p_qh, *p_kh, *p_vh, *p_hh, *p_ropedh, *p_attnh, *p_ffhh, *p_memh, *p_wh;
    cudaGetSymbolAddress((void**)&p_x,      g_x);
    cudaGetSymbolAddress((void**)&p_qh,     g_qh);
    cudaGetSymbolAddress((void**)&p_kh,     g_kh);
    cudaGetSymbolAddress((void**)&p_vh,     g_vh);
    cudaGetSymbolAddress((void**)&p_hh,     g_hh);
    cudaGetSymbolAddress((void**)&p_ropedh, g_ropedh);
    cudaGetSymbolAddress((void**)&p_attnh,  g_attnh);
    cudaGetSymbolAddress((void**)&p_ffhh,   g_ffhh);
    cudaGetSymbolAddress((void**)&p_memh,   g_memh);
    cudaGetSymbolAddress((void**)&p_wh,     g_wh);

    static int smem_set = 0;
    if (!smem_set) {
        cudaFuncSetAttribute(hgemm, cudaFuncAttributeMaxDynamicSharedMemorySize, GSMEM);
        smem_set = 1;
    }

    auto tohalf = [](const float* src, __half* dst, int n) {
        int n4 = n / 4;
        to_half_kernel<<<(n4 + 255) / 256, 256>>>((const float4*)src, (uint2*)dst, n4);
    };
    tohalf(sa_in_w,  p_wh + OW_SA_IN,  3 * DMODEL * DMODEL);
    tohalf(sa_out_w, p_wh + OW_SA_OUT, DMODEL * DMODEL);
    tohalf(ca_in_w,  p_wh + OW_CA_IN,  3 * DMODEL * DMODEL);
    tohalf(ca_out_w, p_wh + OW_CA_OUT, DMODEL * DMODEL);
    tohalf(ff1_w,    p_wh + OW_FF1,    DFF * DMODEL);
    tohalf(ff2_w,    p_wh + OW_FF2,    DMODEL * DFF);
    tohalf(memory,   p_memh,           MTOK * DMODEL);

    dim3 gemm_nt_d(DMODEL / 128, NT / 128);
    dim3 gemm_mt_d(DMODEL / 128, MTOK / 128);
    dim3 gemm_ff1(DFF / 128, NT / 128);
    int rope_blocks = (NT * (DMODEL / 2) + 255) / 256;
    int qtiles = (SQ + AQ - 1) / AQ;   // 4

    // ---- self-attention block ----
    ln_kernel<<<NT, 256>>>(tgt, ln1_g, ln1_b, p_hh);
    rope_kernel<<<rope_blocks, 256>>>(p_hh, p_ropedh);
    hgemm<<<gemm_nt_d, 256, GSMEM>>>(p_ropedh, p_wh + OW_SA_IN,                           sa_in_b,            nullptr, p_qh, NT, DMODEL, DMODEL, 4);
    hgemm<<<gemm_nt_d, 256, GSMEM>>>(p_ropedh, p_wh + OW_SA_IN + (size_t)DMODEL*DMODEL,   sa_in_b + DMODEL,   nullptr, p_kh, NT, DMODEL, DMODEL, 4);
    hgemm<<<gemm_nt_d, 256, GSMEM>>>(p_hh,     p_wh + OW_SA_IN + (size_t)2*DMODEL*DMODEL, sa_in_b + 2*DMODEL, nullptr, p_vh, NT, DMODEL, DMODEL, 4);
    attn_h<<<dim3(qtiles, NH, BB), 128>>>(p_qh, p_kh, p_vh, p_attnh, SQ, SQ, 1);
    hgemm<<<gemm_nt_d, 256, GSMEM>>>(p_attnh, p_wh + OW_SA_OUT, sa_out_b, tgt, p_x, NT, DMODEL, DMODEL, 2);

    // ---- cross-attention block ----
    ln_kernel<<<NT, 256>>>(p_x, ln2_g, ln2_b, p_hh);
    hgemm<<<gemm_nt_d, 256, GSMEM>>>(p_hh,   p_wh + OW_CA_IN,                           ca_in_b,            nullptr, p_qh, NT,   DMODEL, DMODEL, 4);
    hgemm<<<gemm_mt_d, 256, GSMEM>>>(p_memh, p_wh + OW_CA_IN + (size_t)DMODEL*DMODEL,   ca_in_b + DMODEL,   nullptr, p_kh, MTOK, DMODEL, DMODEL, 4);
    hgemm<<<gemm_mt_d, 256, GSMEM>>>(p_memh, p_wh + OW_CA_IN + (size_t)2*DMODEL*DMODEL, ca_in_b + 2*DMODEL, nullptr, p_vh, MTOK, DMODEL, DMODEL, 4);
    attn_h<<<dim3(qtiles, NH, BB), 128>>>(p_qh, p_kh, p_vh, p_attnh, SQ, SMEMLEN, 0);
    hgemm<<<gemm_nt_d, 256, GSMEM>>>(p_attnh, p_wh + OW_CA_OUT, ca_out_b, p_x, p_x, NT, DMODEL, DMODEL, 2);

    // ---- feed-forward block ----
    ln_kernel<<<NT, 256>>>(p_x, ln3_g, ln3_b, p_hh);
    hgemm<<<gemm_ff1, 256, GSMEM>>>(p_hh,   p_wh + OW_FF1, ff1_b, nullptr, p_ffhh, NT, DFF, DMODEL, 1 | 4);
    hgemm<<<gemm_nt_d, 256, GSMEM>>>(p_ffhh, p_wh + OW_FF2, ff2_b, p_x, out, NT, DMODEL, DFF, 2);
}

// round 11
// speedup vs baseline: 2.0436x; 1.0020x over previous
#include <cuda_runtime.h>
#include <cuda_fp16.h>
#include <math.h>

#define BB 32
#define SQ 200
#define SMEMLEN 1024
#define DMODEL 1024
#define NH 16
#define HD 64
#define DFF 4096
#define NT (BB*SQ)        // 6400 target tokens
#define MTOK (BB*SMEMLEN) // 32768 memory tokens
#define EPS 1e-5f

// ---------------- scratch ----------------
__device__ float  g_x[NT*DMODEL];
__device__ __half g_qh[NT*DMODEL];
__device__ __half g_kh[MTOK*DMODEL];
__device__ __half g_vh[MTOK*DMODEL];
__device__ __half g_hh[NT*DMODEL];
__device__ __half g_ropedh[NT*DMODEL];
__device__ __half g_attnh[NT*DMODEL];
__device__ __half g_ffhh[NT*DFF];
__device__ __half g_memh[MTOK*DMODEL];
__device__ __half g_wh[16*1024*1024];   // fp16 weights (packed)

#define OW_SA_IN   0
#define OW_SA_OUT  3145728
#define OW_CA_IN   4194304
#define OW_CA_OUT  7340032
#define OW_FF1     8388608
#define OW_FF2     12582912

// ---------------- fp32 -> fp16 convert (MLP=4 grid-stride) ----------------
__global__ void to_half_kernel(const float4* __restrict__ in,
                               uint2* __restrict__ out, int n4) {
    int idx = blockIdx.x * blockDim.x + threadIdx.x;
    int T = gridDim.x * blockDim.x;
    for (int base = idx; base < n4; base += 4 * T) {
        float4 v[4];
        int k1 = base + T, k2 = base + 2 * T, k3 = base + 3 * T;
        v[0] = in[base];
        if (k1 < n4) v[1] = in[k1];
        if (k2 < n4) v[2] = in[k2];
        if (k3 < n4) v[3] = in[k3];
        {
            __half2 h0 = __floats2half2_rn(v[0].x, v[0].y);
            __half2 h1 = __floats2half2_rn(v[0].z, v[0].w);
            uint2 o; o.x = *(unsigned*)&h0; o.y = *(unsigned*)&h1;
            out[base] = o;
        }
        if (k1 < n4) {
            __half2 h0 = __floats2half2_rn(v[1].x, v[1].y);
            __half2 h1 = __floats2half2_rn(v[1].z, v[1].w);
            uint2 o; o.x = *(unsigned*)&h0; o.y = *(unsigned*)&h1;
            out[k1] = o;
        }
        if (k2 < n4) {
            __half2 h0 = __floats2half2_rn(v[2].x, v[2].y);
            __half2 h1 = __floats2half2_rn(v[2].z, v[2].w);
            uint2 o; o.x = *(unsigned*)&h0; o.y = *(unsigned*)&h1;
            out[k2] = o;
        }
        if (k3 < n4) {
            __half2 h0 = __floats2half2_rn(v[3].x, v[3].y);
            __half2 h1 = __floats2half2_rn(v[3].z, v[3].w);
            uint2 o; o.x = *(unsigned*)&h0; o.y = *(unsigned*)&h1;
            out[k3] = o;
        }
    }
}

// ---------------- LayerNorm (fp32 in, fp16 out) ----------------
__global__ __launch_bounds__(256) void ln_kernel(const float* __restrict__ x,
                                                 const float* __restrict__ g,
                                                 const float* __restrict__ b,
                                                 __half* __restrict__ out) {
    __shared__ float rs[8], rss[8];
    int t = blockIdx.x;
    int tid = threadIdx.x;
    const float4* xr = (const float4*)(x + (size_t)t * DMODEL);
    float4 v = xr[tid];
    float s  = v.x + v.y + v.z + v.w;
    float ss = v.x*v.x + v.y*v.y + v.z*v.z + v.w*v.w;
    #pragma unroll
    for (int o = 16; o; o >>= 1) {
        s  += __shfl_xor_sync(0xffffffffu, s, o);
        ss += __shfl_xor_sync(0xffffffffu, ss, o);
    }
    int lane = tid & 31, wid = tid >> 5;
    if (lane == 0) { rs[wid] = s; rss[wid] = ss; }
    __syncthreads();
    float ts = 0.f, tss = 0.f;
    #pragma unroll
    for (int w = 0; w < 8; w++) { ts += rs[w]; tss += rss[w]; }
    float mu  = ts * (1.0f / DMODEL);
    float var = tss * (1.0f / DMODEL) - mu * mu;
    float r   = rsqrtf(var + EPS);
    float4 gv = ((const float4*)g)[tid];
    float4 bv = ((const float4*)b)[tid];
    float ox = (v.x - mu) * r * gv.x + bv.x;
    float oy = (v.y - mu) * r * gv.y + bv.y;
    float oz = (v.z - mu) * r * gv.z + bv.z;
    float ow = (v.w - mu) * r * gv.w + bv.w;
    __half2 h0 = __floats2half2_rn(ox, oy);
    __half2 h1 = __floats2half2_rn(oz, ow);
    uint2 o;
    o.x = *(unsigned*)&h0;
    o.y = *(unsigned*)&h1;
    ((uint2*)(out + (size_t)t * DMODEL))[tid] = o;
}

// ---------------- RoPE (fp16 in/out, fp32 math) ----------------
__global__ void rope_kernel(const __half* __restrict__ in, __half* __restrict__ out) {
    int idx = blockIdx.x * blockDim.x + threadIdx.x;
    if (idx >= NT * (DMODEL / 2)) return;
    int t = idx / (DMODEL / 2);
    int p = idx - t * (DMODEL / 2);
    int i = p & 31;
    int s = t % SQ;
    float freq = __expf(-9.210340371976184f * (2.0f * i) * (1.0f / 64.0f));
    float ang = (float)s * freq;
    float sn, cs;
    sincosf(ang, &sn, &cs);
    __half2 xv = ((const __half2*)in)[idx];
    float2 xf = __half22float2(xv);
    float ox = xf.x * cs - xf.y * sn;
    float oy = xf.y * cs + xf.x * sn;
    ((__half2*)out)[idx] = __floats2half2_rn(ox, oy);
}

// ---------------- common mma helpers ----------------
__device__ __forceinline__ void cpa16(unsigned dst, const void* src) {
    asm volatile("cp.async.cg.shared.global [%0], [%1], 16;\n" :: "r"(dst), "l"(src));
}
__device__ __forceinline__ void ldsm4(unsigned& r0, unsigned& r1, unsigned& r2, unsigned& r3,
                                      unsigned a) {
    asm volatile("ldmatrix.sync.aligned.m8n8.x4.shared.b16 {%0,%1,%2,%3}, [%4];"
                 : "=r"(r0), "=r"(r1), "=r"(r2), "=r"(r3) : "r"(a));
}
__device__ __forceinline__ void ldsm4t(unsigned& r0, unsigned& r1, unsigned& r2, unsigned& r3,
                                       unsigned a) {
    asm volatile("ldmatrix.sync.aligned.m8n8.x4.trans.shared.b16 {%0,%1,%2,%3}, [%4];"
                 : "=r"(r0), "=r"(r1), "=r"(r2), "=r"(r3) : "r"(a));
}
__device__ __forceinline__ void mma16816(float* c, unsigned a0, unsigned a1, unsigned a2,
                                         unsigned a3, unsigned b0, unsigned b1) {
    asm volatile(
        "mma.sync.aligned.m16n8k16.row.col.f32.f16.f16.f32 "
        "{%0,%1,%2,%3}, {%4,%5,%6,%7}, {%8,%9}, {%0,%1,%2,%3};"
        : "+f"(c[0]), "+f"(c[1]), "+f"(c[2]), "+f"(c[3])
        : "r"(a0), "r"(a1), "r"(a2), "r"(a3), "r"(b0), "r"(b1));
}

// ---------------- fp16 tensor-core GEMM (3-stage cp.async + ldmatrix) ----------
#define BKH 64
#define RSH 72
#define NSTG 3
#define STGH (2 * 128 * RSH)
#define GSMEM (NSTG * STGH * 2)          // 110592 bytes

__global__ __launch_bounds__(256, 2) void hgemm(const __half* __restrict__ A,
                                                const __half* __restrict__ W,
                                                const float* __restrict__ bias,
                                                const float* __restrict__ res,
                                                void* __restrict__ Cout,
                                                int M, int N, int K, int flags) {
    extern __shared__ __half smh[];
    int tid = threadIdx.x;
    int wid = tid >> 5, lane = tid & 31;
    int gid = lane >> 2, tig = lane & 3;
    int row0 = blockIdx.y * 128;
    int col0 = blockIdx.x * 128;
    int wm = (wid & 3) * 32;
    int wn = (wid >> 2) * 64;

    unsigned sbase = (unsigned)__cvta_generic_to_shared(smh);
    unsigned stgA[NSTG], stgW[NSTG];
    #pragma unroll
    for (int s = 0; s < NSTG; s++) {
        stgA[s] = sbase + s * STGH * 2;
        stgW[s] = stgA[s] + 128 * RSH * 2;
    }

    int lr = tid >> 1;
    int lc = (tid & 1) * 32;
    const __half* Ab = A + (size_t)(row0 + lr) * K + lc;
    const __half* Wb = W + (size_t)(col0 + lr) * K + lc;

    float c[2][8][4];
    #pragma unroll
    for (int mi = 0; mi < 2; mi++)
        #pragma unroll
        for (int ni = 0; ni < 8; ni++)
            #pragma unroll
            for (int q = 0; q < 4; q++) c[mi][ni][q] = 0.f;

    int nk = K / BKH;

    #pragma unroll
    for (int ps = 0; ps < 2; ps++) {
        int k0 = ps * BKH;
        #pragma unroll
        for (int cch = 0; cch < 4; cch++) {
            unsigned soff = (lr * RSH + lc + cch * 8) * 2;
            cpa16(stgA[ps] + soff, Ab + k0 + cch * 8);
            cpa16(stgW[ps] + soff, Wb + k0 + cch * 8);
        }
        asm volatile("cp.async.commit_group;\n");
    }

    int a_row = lane & 15;
    int a_col = (lane >> 4) * 8;
    int b_row = (lane & 7) + ((lane & 16) >> 1);
    int b_col = lane & 8;

    unsigned af[2][2][4], bf[2][4][4];

    for (int kt = 0; kt < nk; kt++) {
        if (kt < nk - 1) asm volatile("cp.async.wait_group 1;\n");
        else             asm volatile("cp.async.wait_group 0;\n");
        __syncthreads();

        if (kt + 2 < nk) {
            int st = (kt + 2) % NSTG;
            int k0 = (kt + 2) * BKH;
            #pragma unroll
            for (int cch = 0; cch < 4; cch++) {
                unsigned soff = (lr * RSH + lc + cch * 8) * 2;
                cpa16(stgA[st] + soff, Ab + k0 + cch * 8);
                cpa16(stgW[st] + soff, Wb + k0 + cch * 8);
            }
            asm volatile("cp.async.commit_group;\n");
        }

        int st = kt % NSTG;
        unsigned sAu = stgA[st];
        unsigned sWu = stgW[st];

        auto load_frags = [&](int buf, int ks) {
            int kb = ks * 16;
            #pragma unroll
            for (int mi = 0; mi < 2; mi++)
                ldsm4(af[buf][mi][0], af[buf][mi][1], af[buf][mi][2], af[buf][mi][3],
                      sAu + ((wm + mi * 16 + a_row) * RSH + kb + a_col) * 2);
            #pragma unroll
            for (int p = 0; p < 4; p++)
                ldsm4(bf[buf][p][0], bf[buf][p][1], bf[buf][p][2], bf[buf][p][3],
                      sWu + ((wn + p * 16 + b_row) * RSH + kb + b_col) * 2);
        };

        load_frags(0, 0);
        #pragma unroll
        for (int ks = 0; ks < 4; ks++) {
            int cur = ks & 1;
            if (ks < 3) load_frags(cur ^ 1, ks + 1);
            #pragma unroll
            for (int mi = 0; mi < 2; mi++)
                #pragma unroll
                for (int p = 0; p < 4; p++) {
                    mma16816(c[mi][2*p],   af[cur][mi][0], af[cur][mi][1], af[cur][mi][2],
                             af[cur][mi][3], bf[cur][p][0], bf[cur][p][1]);
                    mma16816(c[mi][2*p+1], af[cur][mi][0], af[cur][mi][1], af[cur][mi][2],
                             af[cur][mi][3], bf[cur][p][2], bf[cur][p][3]);
                }
        }
    }

    bool use_relu = (flags & 1) != 0;
    bool use_res  = (flags & 2) != 0;
    bool out_h    = (flags & 4) != 0;
    float* Cf = (float*)Cout;
    __half* Ch = (__half*)Cout;
    #pragma unroll
    for (int mi = 0; mi < 2; mi++) {
        #pragma unroll
        for (int ni = 0; ni < 8; ni++) {
            int colg = col0 + wn + ni * 8 + tig * 2;
            int r0 = row0 + wm + mi * 16 + gid;
            int r1 = r0 + 8;
            float b0 = bias[colg], b1 = bias[colg + 1];
            float2 o0, o1;
            o0.x = c[mi][ni][0] + b0; o0.y = c[mi][ni][1] + b1;
            o1.x = c[mi][ni][2] + b0; o1.y = c[mi][ni][3] + b1;
            size_t i0 = (size_t)r0 * N + colg;
            size_t i1 = (size_t)r1 * N + colg;
            if (use_res) {
                float2 rv0 = *(const float2*)(res + i0);
                float2 rv1 = *(const float2*)(res + i1);
                o0.x += rv0.x; o0.y += rv0.y;
                o1.x += rv1.x; o1.y += rv1.y;
            }
            if (use_relu) {
                o0.x = fmaxf(o0.x, 0.f); o0.y = fmaxf(o0.y, 0.f);
                o1.x = fmaxf(o1.x, 0.f); o1.y = fmaxf(o1.y, 0.f);
            }
            if (out_h) {
                __half2 h0 = __floats2half2_rn(o0.x, o0.y);
                __half2 h1 = __floats2half2_rn(o1.x, o1.y);
                *(unsigned*)(Ch + i0) = *(unsigned*)&h0;
                *(unsigned*)(Ch + i1) = *(unsigned*)&h1;
            } else {
                *(float2*)(Cf + i0) = o0;
                *(float2*)(Cf + i1) = o1;
            }
        }
    }
}

// ---------------- fp16 tensor-core flash attention ----------------
#define AQ 64
#define AK 64
#define AH 72   // halves per smem row

__global__ __launch_bounds__(128) void attn_h(const __half* __restrict__ Q,
                                              const __half* __restrict__ Km,
                                              const __half* __restrict__ Vm,
                                              __half* __restrict__ O,
                                              int Sq, int Sk, int causal) {
    __shared__ __half Qs[AQ*AH], Ks[AK*AH], Vs[AK*AH];

    int qt = blockIdx.x, h = blockIdx.y, b = blockIdx.z;
    int tid = threadIdx.x;
    int wid = tid >> 5, lane = tid & 31;

    unsigned sQ = (unsigned)__cvta_generic_to_shared(Qs);
    unsigned sK = (unsigned)__cvta_generic_to_shared(Ks);
    unsigned sV = (unsigned)__cvta_generic_to_shared(Vs);

    {
        int r = tid >> 1;
        int cb = (tid & 1) * 32;
        int qgl = qt * AQ + r;
        const __half* src = Q + ((size_t)(b * Sq + qgl)) * DMODEL + h * HD + cb;
        uint4 z = {0u, 0u, 0u, 0u};
        #pragma unroll
        for (int i = 0; i < 4; i++) {
            uint4 v = (qgl < Sq) ? *(const uint4*)(src + i * 8) : z;
            *(uint4*)&Qs[r * AH + cb + i * 8] = v;
        }
    }
    __syncthreads();

    int a_row = lane & 15;
    int a_col = (lane >> 4) * 8;
    unsigned aq[4][4];
    #pragma unroll
    for (int ks = 0; ks < 4; ks++)
        ldsm4(aq[ks][0], aq[ks][1], aq[ks][2], aq[ks][3],
              sQ + ((wid * 16 + a_row) * AH + ks * 16 + a_col) * 2);

    int b_row = (lane & 7) + ((lane & 16) >> 1);
    int b_col = lane & 8;

    int r0 = lane >> 2, tig = lane & 3;
    int qgl0 = qt * AQ + wid * 16 + r0;
    int qgl1 = qgl0 + 8;
    float m0 = -1e30f, m1 = -1e30f, l0 = 0.f, l1 = 0.f;
    float o[8][4];
    #pragma unroll
    for (int j = 0; j < 8; j++)
        #pragma unroll
        for (int q = 0; q < 4; q++) o[j][q] = 0.f;

    int q_hi = qt * AQ + AQ - 1;
    int keff = causal ? min(q_hi + 1, Sk) : Sk;
    int ntiles = (keff + AK - 1) / AK;

    int kvr = tid >> 1;
    int kvc = (tid & 1) * 32;
    uint4 pk[4], pv[4];
    {
        int kg = kvr;
        bool ok = kg < Sk;
        const __half* ks = Km + ((size_t)(b * Sk + kg)) * DMODEL + h * HD + kvc;
        const __half* vs = Vm + ((size_t)(b * Sk + kg)) * DMODEL + h * HD + kvc;
        uint4 z = {0u, 0u, 0u, 0u};
        #pragma unroll
        for (int i = 0; i < 4; i++) {
            pk[i] = ok ? *(const uint4*)(ks + i * 8) : z;
            pv[i] = ok ? *(const uint4*)(vs + i * 8) : z;
        }
    }

    for (int kt = 0; kt < ntiles; kt++) {
        #pragma unroll
        for (int i = 0; i < 4; i++) {
            *(uint4*)&Ks[kvr * AH + kvc + i * 8] = pk[i];
            *(uint4*)&Vs[kvr * AH + kvc + i * 8] = pv[i];
        }
        __syncthreads();

        if (kt + 1 < ntiles) {
            int kg = (kt + 1) * AK + kvr;
            bool ok = kg < Sk;
            const __half* ks = Km + ((size_t)(b * Sk + kg)) * DMODEL + h * HD + kvc;
            const __half* vs = Vm + ((size_t)(b * Sk + kg)) * DMODEL + h * HD + kvc;
            uint4 z = {0u, 0u, 0u, 0u};
            #pragma unroll
            for (int i = 0; i < 4; i++) {
                pk[i] = ok ? *(const uint4*)(ks + i * 8) : z;
                pv[i] = ok ? *(const uint4*)(vs + i * 8) : z;
            }
        }

        float s[8][4];
        #pragma unroll
        for (int j = 0; j < 8; j++)
            #pragma unroll
            for (int q = 0; q < 4; q++) s[j][q] = 0.f;

        #pragma unroll
        for (int ks = 0; ks < 4; ks++) {
            #pragma unroll
            for (int p = 0; p < 4; p++) {
                unsigned bf0, bf1, bf2, bf3;
                ldsm4(bf0, bf1, bf2, bf3,
                      sK + ((p * 16 + b_row) * AH + ks * 16 + b_col) * 2);
                mma16816(s[2*p],   aq[ks][0], aq[ks][1], aq[ks][2], aq[ks][3], bf0, bf1);
                mma16816(s[2*p+1], aq[ks][0], aq[ks][1], aq[ks][2], aq[ks][3], bf2, bf3);
            }
        }

        int kvalid0 = causal ? min(qgl0 + 1, Sk) : Sk;
        int kvalid1 = causal ? min(qgl1 + 1, Sk) : Sk;
        int kgb = kt * AK + tig * 2;
        float tm0 = -1e30f, tm1 = -1e30f;
        #pragma unroll
        for (int j = 0; j < 8; j++) {
            int kg = kgb + j * 8;
            s[j][0] = (kg     < kvalid0) ? s[j][0] * 0.125f : -1e30f;
            s[j][1] = (kg + 1 < kvalid0) ? s[j][1] * 0.125f : -1e30f;
            s[j][2] = (kg     < kvalid1) ? s[j][2] * 0.125f : -1e30f;
            s[j][3] = (kg + 1 < kvalid1) ? s[j][3] * 0.125f : -1e30f;
            tm0 = fmaxf(tm0, fmaxf(s[j][0], s[j][1]));
            tm1 = fmaxf(tm1, fmaxf(s[j][2], s[j][3]));
        }
        tm0 = fmaxf(tm0, __shfl_xor_sync(0xffffffffu, tm0, 1));
        tm0 = fmaxf(tm0, __shfl_xor_sync(0xffffffffu, tm0, 2));
        tm1 = fmaxf(tm1, __shfl_xor_sync(0xffffffffu, tm1, 1));
        tm1 = fmaxf(tm1, __shfl_xor_sync(0xffffffffu, tm1, 2));

        float mn0 = fmaxf(m0, tm0), mn1 = fmaxf(m1, tm1);
        float sc0 = __expf(m0 - mn0), sc1 = __expf(m1 - mn1);
        float ps0 = 0.f, ps1 = 0.f;
        #pragma unroll
        for (int j = 0; j < 8; j++) {
            s[j][0] = __expf(s[j][0] - mn0);
            s[j][1] = __expf(s[j][1] - mn0);
            s[j][2] = __expf(s[j][2] - mn1);
            s[j][3] = __expf(s[j][3] - mn1);
            ps0 += s[j][0] + s[j][1];
            ps1 += s[j][2] + s[j][3];
        }
        ps0 += __shfl_xor_sync(0xffffffffu, ps0, 1);
        ps0 += __shfl_xor_sync(0xffffffffu, ps0, 2);
        ps1 += __shfl_xor_sync(0xffffffffu, ps1, 1);
        ps1 += __shfl_xor_sync(0xffffffffu, ps1, 2);
        l0 = l0 * sc0 + ps0;  m0 = mn0;
        l1 = l1 * sc1 + ps1;  m1 = mn1;
        #pragma unroll
        for (int j = 0; j < 8; j++) {
            o[j][0] *= sc0; o[j][1] *= sc0;
            o[j][2] *= sc1; o[j][3] *= sc1;
        }

        unsigned pa[4][4];
        #pragma unroll
        for (int t = 0; t < 4; t++) {
            __half2 h0 = __floats2half2_rn(s[2*t][0],   s[2*t][1]);
            __half2 h1 = __floats2half2_rn(s[2*t][2],   s[2*t][3]);
            __half2 h2 = __floats2half2_rn(s[2*t+1][0], s[2*t+1][1]);
            __half2 h3 = __floats2half2_rn(s[2*t+1][2], s[2*t+1][3]);
            pa[t][0] = *(unsigned*)&h0;
            pa[t][1] = *(unsigned*)&h1;
            pa[t][2] = *(unsigned*)&h2;
            pa[t][3] = *(unsigned*)&h3;
        }

        #pragma unroll
        for (int t = 0; t < 4; t++) {
            #pragma unroll
            for (int p = 0; p < 4; p++) {
                unsigned bv0, bv1, bv2, bv3;
                ldsm4t(bv0, bv1, bv2, bv3,
                       sV + ((t * 16 + (lane & 15)) * AH + p * 16 + (lane >> 4) * 8) * 2);
                mma16816(o[2*p],   pa[t][0], pa[t][1], pa[t][2], pa[t][3], bv0, bv1);
                mma16816(o[2*p+1], pa[t][0], pa[t][1], pa[t][2], pa[t][3], bv2, bv3);
            }
        }
        __syncthreads();
    }

    float inv0 = 1.0f / l0, inv1 = 1.0f / l1;
    #pragma unroll
    for (int j = 0; j < 8; j++) {
        int d = j * 8 + tig * 2;
        if (qgl0 < Sq) {
            __half2 h0 = __floats2half2_rn(o[j][0] * inv0, o[j][1] * inv0);
            *(unsigned*)(O + ((size_t)(b * Sq + qgl0)) * DMODEL + h * HD + d) = *(unsigned*)&h0;
        }
        if (qgl1 < Sq) {
            __half2 h1 = __floats2half2_rn(o[j][2] * inv1, o[j][3] * inv1);
            *(unsigned*)(O + ((size_t)(b * Sq + qgl1)) * DMODEL + h * HD + d) = *(unsigned*)&h1;
        }
    }
}

// ---------------- host orchestration ----------------
extern "C" void kernel_launch(void* const* d_in, const int* in_sizes, int n_in,
                              void* d_out, int out_size) {
    const float* tgt      = (const float*)d_in[0];
    const float* memory   = (const float*)d_in[1];
    const float* sa_in_w  = (const float*)d_in[2];
    const float* sa_in_b  = (const float*)d_in[3];
    const float* sa_out_w = (const float*)d_in[4];
    const float* sa_out_b = (const float*)d_in[5];
    const float* ca_in_w  = (const float*)d_in[6];
    const float* ca_in_b  = (const float*)d_in[7];
    const float* ca_out_w = (const float*)d_in[8];
    const float* ca_out_b = (const float*)d_in[9];
    const float* ff1_w    = (const float*)d_in[10];
    const float* ff1_b    = (const float*)d_in[11];
    const float* ff2_w    = (const float*)d_in[12];
    const float* ff2_b    = (const float*)d_in[13];
    const float* ln1_g    = (const float*)d_in[14];
    const float* ln1_b    = (const float*)d_in[15];
    const float* ln2_g    = (const float*)d_in[16];
    const float* ln2_b    = (const float*)d_in[17];
    const float* ln3_g    = (const float*)d_in[18];
    const float* ln3_b    = (const float*)d_in[19];
    float* out = (float*)d_out;

    float *p_x;
    __half *p_qh, *p_kh, *p_vh, *p_hh, *p_ropedh, *p_attnh, *p_ffhh, *p_memh, *p_wh;
    cudaGetSymbolAddress((void**)&p_x,      g_x);
    cudaGetSymbolAddress((void**)&p_qh,     g_qh);
    cudaGetSymbolAddress((void**)&p_kh,     g_kh);
    cudaGetSymbolAddress((void**)&p_vh,     g_vh);
    cudaGetSymbolAddress((void**)&p_hh,     g_hh);
    cudaGetSymbolAddress((void**)&p_ropedh, g_ropedh);
    cudaGetSymbolAddress((void**)&p_attnh,  g_attnh);
    cudaGetSymbolAddress((void**)&p_ffhh,   g_ffhh);
    cudaGetSymbolAddress((void**)&p_memh,   g_memh);
    cudaGetSymbolAddress((void**)&p_wh,     g_wh);

    static int smem_set = 0;
    if (!smem_set) {
        cudaFuncSetAttribute(hgemm, cudaFuncAttributeMaxDynamicSharedMemorySize, GSMEM);
        smem_set = 1;
    }

    auto tohalf = [](const float* src, __half* dst, int n) {
        int n4 = n / 4;
        int blocks = (n4 + 1023) / 1024;   // 256 thr x 4 elems each
        to_half_kernel<<<blocks, 256>>>((const float4*)src, (uint2*)dst, n4);
    };
    tohalf(sa_in_w,  p_wh + OW_SA_IN,  3 * DMODEL * DMODEL);
    tohalf(sa_out_w, p_wh + OW_SA_OUT, DMODEL * DMODEL);
    tohalf(ca_in_w,  p_wh + OW_CA_IN,  3 * DMODEL * DMODEL);
    tohalf(ca_out_w, p_wh + OW_CA_OUT, DMODEL * DMODEL);
    tohalf(ff1_w,    p_wh + OW_FF1,    DFF * DMODEL);
    tohalf(ff2_w,    p_wh + OW_FF2,    DMODEL * DFF);
    tohalf(memory,   p_memh,           MTOK * DMODEL);

    dim3 gemm_nt_d(DMODEL / 128, NT / 128);
    dim3 gemm_mt_d(DMODEL / 128, MTOK / 128);
    dim3 gemm_ff1(DFF / 128, NT / 128);
    int rope_blocks = (NT * (DMODEL / 2) + 255) / 256;
    int qtiles = (SQ + AQ - 1) / AQ;   // 4

    // ---- self-attention block ----
    ln_kernel<<<NT, 256>>>(tgt, ln1_g, ln1_b, p_hh);
    rope_kernel<<<rope_blocks, 256>>>(p_hh, p_ropedh);
    hgemm<<<gemm_nt_d, 256, GSMEM>>>(p_ropedh, p_wh + OW_SA_IN,                           sa_in_b,            nullptr, p_qh, NT, DMODEL, DMODEL, 4);
    hgemm<<<gemm_nt_d, 256, GSMEM>>>(p_ropedh, p_wh + OW_SA_IN + (size_t)DMODEL*DMODEL,   sa_in_b + DMODEL,   nullptr, p_kh, NT, DMODEL, DMODEL, 4);
    hgemm<<<gemm_nt_d, 256, GSMEM>>>(p_hh,     p_wh + OW_SA_IN + (size_t)2*DMODEL*DMODEL, sa_in_b + 2*DMODEL, nullptr, p_vh, NT, DMODEL, DMODEL, 4);
    attn_h<<<dim3(qtiles, NH, BB), 128>>>(p_qh, p_kh, p_vh, p_attnh, SQ, SQ, 1);
    hgemm<<<gemm_nt_d, 256, GSMEM>>>(p_attnh, p_wh + OW_SA_OUT, sa_out_b, tgt, p_x, NT, DMODEL, DMODEL, 2);

    // ---- cross-attention block ----
    ln_kernel<<<NT, 256>>>(p_x, ln2_g, ln2_b, p_hh);
    hgemm<<<gemm_nt_d, 256, GSMEM>>>(p_hh,   p_wh + OW_CA_IN,                           ca_in_b,            nullptr, p_qh, NT,   DMODEL, DMODEL, 4);
    hgemm<<<gemm_mt_d, 256, GSMEM>>>(p_memh, p_wh + OW_CA_IN + (size_t)DMODEL*DMODEL,   ca_in_b + DMODEL,   nullptr, p_kh, MTOK, DMODEL, DMODEL, 4);
    hgemm<<<gemm_mt_d, 256, GSMEM>>>(p_memh, p_wh + OW_CA_IN + (size_t)2*DMODEL*DMODEL, ca_in_b + 2*DMODEL, nullptr, p_vh, MTOK, DMODEL, DMODEL, 4);
    attn_h<<<dim3(qtiles, NH, BB), 128>>>(p_qh, p_kh, p_vh, p_attnh, SQ, SMEMLEN, 0);
    hgemm<<<gemm_nt_d, 256, GSMEM>>>(p_attnh, p_wh + OW_CA_OUT, ca_out_b, p_x, p_x, NT, DMODEL, DMODEL, 2);

    // ---- feed-forward block ----
    ln_kernel<<<NT, 256>>>(p_x, ln3_g, ln3_b, p_hh);
    hgemm<<<gemm_ff1, 256, GSMEM>>>(p_hh,   p_wh + OW_FF1, ff1_b, nullptr, p_ffhh, NT, DFF, DMODEL, 1 | 4);
    hgemm<<<gemm_nt_d, 256, GSMEM>>>(p_ffhh, p_wh + OW_FF2, ff2_b, p_x, out, NT, DMODEL, DFF, 2);
}

// round 12
// speedup vs baseline: 2.1042x; 1.0296x over previous
#include <cuda_runtime.h>
#include <cuda_fp16.h>
#include <math.h>

#define BB 32
#define SQ 200
#define SMEMLEN 1024
#define DMODEL 1024
#define NH 16
#define HD 64
#define DFF 4096
#define NT (BB*SQ)        // 6400 target tokens
#define MTOK (BB*SMEMLEN) // 32768 memory tokens
#define EPS 1e-5f

// ---------------- scratch ----------------
__device__ float  g_x[NT*DMODEL];
__device__ __half g_qkh[NT*2048];       // SA q|k packed (row stride 2048)
__device__ __half g_vh[NT*DMODEL];      // SA v
__device__ __half g_qh[NT*DMODEL];      // CA q
__device__ __half g_kvh[MTOK*2048];     // CA k|v packed (row stride 2048)
__device__ __half g_hh[NT*DMODEL];
__device__ __half g_ropedh[NT*DMODEL];
__device__ __half g_attnh[NT*DMODEL];
__device__ __half g_ffhh[NT*DFF];
__device__ __half g_memh[MTOK*DMODEL];
__device__ __half g_wh[16*1024*1024];   // fp16 weights (packed)

#define OW_SA_IN   0
#define OW_SA_OUT  3145728
#define OW_CA_IN   4194304
#define OW_CA_OUT  7340032
#define OW_FF1     8388608
#define OW_FF2     12582912

// ---------------- fp32 -> fp16 convert (MLP=4 grid-stride) ----------------
__global__ void to_half_kernel(const float4* __restrict__ in,
                               uint2* __restrict__ out, int n4) {
    int idx = blockIdx.x * blockDim.x + threadIdx.x;
    int T = gridDim.x * blockDim.x;
    for (int base = idx; base < n4; base += 4 * T) {
        float4 v[4];
        int k1 = base + T, k2 = base + 2 * T, k3 = base + 3 * T;
        v[0] = in[base];
        if (k1 < n4) v[1] = in[k1];
        if (k2 < n4) v[2] = in[k2];
        if (k3 < n4) v[3] = in[k3];
        {
            __half2 h0 = __floats2half2_rn(v[0].x, v[0].y);
            __half2 h1 = __floats2half2_rn(v[0].z, v[0].w);
            uint2 o; o.x = *(unsigned*)&h0; o.y = *(unsigned*)&h1;
            out[base] = o;
        }
        if (k1 < n4) {
            __half2 h0 = __floats2half2_rn(v[1].x, v[1].y);
            __half2 h1 = __floats2half2_rn(v[1].z, v[1].w);
            uint2 o; o.x = *(unsigned*)&h0; o.y = *(unsigned*)&h1;
            out[k1] = o;
        }
        if (k2 < n4) {
            __half2 h0 = __floats2half2_rn(v[2].x, v[2].y);
            __half2 h1 = __floats2half2_rn(v[2].z, v[2].w);
            uint2 o; o.x = *(unsigned*)&h0; o.y = *(unsigned*)&h1;
            out[k2] = o;
        }
        if (k3 < n4) {
            __half2 h0 = __floats2half2_rn(v[3].x, v[3].y);
            __half2 h1 = __floats2half2_rn(v[3].z, v[3].w);
            uint2 o; o.x = *(unsigned*)&h0; o.y = *(unsigned*)&h1;
            out[k3] = o;
        }
    }
}

// ---------------- LayerNorm (fp32 in, fp16 out; optional fused RoPE out) -------
__global__ __launch_bounds__(256) void ln_kernel(const float* __restrict__ x,
                                                 const float* __restrict__ g,
                                                 const float* __restrict__ b,
                                                 __half* __restrict__ out,
                                                 __half* __restrict__ out_roped) {
    __shared__ float rs[8], rss[8];
    int t = blockIdx.x;
    int tid = threadIdx.x;
    const float4* xr = (const float4*)(x + (size_t)t * DMODEL);
    float4 v = xr[tid];
    float s  = v.x + v.y + v.z + v.w;
    float ss = v.x*v.x + v.y*v.y + v.z*v.z + v.w*v.w;
    #pragma unroll
    for (int o = 16; o; o >>= 1) {
        s  += __shfl_xor_sync(0xffffffffu, s, o);
        ss += __shfl_xor_sync(0xffffffffu, ss, o);
    }
    int lane = tid & 31, wid = tid >> 5;
    if (lane == 0) { rs[wid] = s; rss[wid] = ss; }
    __syncthreads();
    float ts = 0.f, tss = 0.f;
    #pragma unroll
    for (int w = 0; w < 8; w++) { ts += rs[w]; tss += rss[w]; }
    float mu  = ts * (1.0f / DMODEL);
    float var = tss * (1.0f / DMODEL) - mu * mu;
    float r   = rsqrtf(var + EPS);
    float4 gv = ((const float4*)g)[tid];
    float4 bv = ((const float4*)b)[tid];
    float ox = (v.x - mu) * r * gv.x + bv.x;
    float oy = (v.y - mu) * r * gv.y + bv.y;
    float oz = (v.z - mu) * r * gv.z + bv.z;
    float ow = (v.w - mu) * r * gv.w + bv.w;
    {
        __half2 h0 = __floats2half2_rn(ox, oy);
        __half2 h1 = __floats2half2_rn(oz, ow);
        uint2 o;
        o.x = *(unsigned*)&h0;
        o.y = *(unsigned*)&h1;
        ((uint2*)(out + (size_t)t * DMODEL))[tid] = o;
    }
    if (out_roped) {
        // thread holds elements e0=4*tid..e0+3 -> two complete RoPE pairs
        int e0 = tid * 4;
        int i0 = (e0 & 63) >> 1;        // pair index in head (0..31), second pair = i0+1
        int spos = t % SQ;
        float f0 = __expf(-9.210340371976184f * (2.0f * i0) * (1.0f / 64.0f));
        float f1 = __expf(-9.210340371976184f * (2.0f * (i0 + 1)) * (1.0f / 64.0f));
        float sn0, cs0, sn1, cs1;
        sincosf((float)spos * f0, &sn0, &cs0);
        sincosf((float)spos * f1, &sn1, &cs1);
        float r0x = ox * cs0 - oy * sn0;
        float r0y = oy * cs0 + ox * sn0;
        float r1x = oz * cs1 - ow * sn1;
        float r1y = ow * cs1 + oz * sn1;
        __half2 h0 = __floats2half2_rn(r0x, r0y);
        __half2 h1 = __floats2half2_rn(r1x, r1y);
        uint2 o;
        o.x = *(unsigned*)&h0;
        o.y = *(unsigned*)&h1;
        ((uint2*)(out_roped + (size_t)t * DMODEL))[tid] = o;
    }
}

// ---------------- common mma helpers ----------------
__device__ __forceinline__ void cpa16(unsigned dst, const void* src) {
    asm volatile("cp.async.cg.shared.global [%0], [%1], 16;\n" :: "r"(dst), "l"(src));
}
__device__ __forceinline__ void ldsm4(unsigned& r0, unsigned& r1, unsigned& r2, unsigned& r3,
                                      unsigned a) {
    asm volatile("ldmatrix.sync.aligned.m8n8.x4.shared.b16 {%0,%1,%2,%3}, [%4];"
                 : "=r"(r0), "=r"(r1), "=r"(r2), "=r"(r3) : "r"(a));
}
__device__ __forceinline__ void ldsm4t(unsigned& r0, unsigned& r1, unsigned& r2, unsigned& r3,
                                       unsigned a) {
    asm volatile("ldmatrix.sync.aligned.m8n8.x4.trans.shared.b16 {%0,%1,%2,%3}, [%4];"
                 : "=r"(r0), "=r"(r1), "=r"(r2), "=r"(r3) : "r"(a));
}
__device__ __forceinline__ void mma16816(float* c, unsigned a0, unsigned a1, unsigned a2,
                                         unsigned a3, unsigned b0, unsigned b1) {
    asm volatile(
        "mma.sync.aligned.m16n8k16.row.col.f32.f16.f16.f32 "
        "{%0,%1,%2,%3}, {%4,%5,%6,%7}, {%8,%9}, {%0,%1,%2,%3};"
        : "+f"(c[0]), "+f"(c[1]), "+f"(c[2]), "+f"(c[3])
        : "r"(a0), "r"(a1), "r"(a2), "r"(a3), "r"(b0), "r"(b1));
}

// ---------------- fp16 tensor-core GEMM (3-stage cp.async + ldmatrix) ----------
#define BKH 64
#define RSH 72
#define NSTG 3
#define STGH (2 * 128 * RSH)
#define GSMEM (NSTG * STGH * 2)          // 110592 bytes

__global__ __launch_bounds__(256, 2) void hgemm(const __half* __restrict__ A,
                                                const __half* __restrict__ W,
                                                const float* __restrict__ bias,
                                                const float* __restrict__ res,
                                                void* __restrict__ Cout,
                                                int M, int N, int K, int flags) {
    extern __shared__ __half smh[];
    int tid = threadIdx.x;
    int wid = tid >> 5, lane = tid & 31;
    int gid = lane >> 2, tig = lane & 3;
    int row0 = blockIdx.y * 128;
    int col0 = blockIdx.x * 128;
    int wm = (wid & 3) * 32;
    int wn = (wid >> 2) * 64;

    unsigned sbase = (unsigned)__cvta_generic_to_shared(smh);
    unsigned stgA[NSTG], stgW[NSTG];
    #pragma unroll
    for (int s = 0; s < NSTG; s++) {
        stgA[s] = sbase + s * STGH * 2;
        stgW[s] = stgA[s] + 128 * RSH * 2;
    }

    int lr = tid >> 1;
    int lc = (tid & 1) * 32;
    const __half* Ab = A + (size_t)(row0 + lr) * K + lc;
    const __half* Wb = W + (size_t)(col0 + lr) * K + lc;

    float c[2][8][4];
    #pragma unroll
    for (int mi = 0; mi < 2; mi++)
        #pragma unroll
        for (int ni = 0; ni < 8; ni++)
            #pragma unroll
            for (int q = 0; q < 4; q++) c[mi][ni][q] = 0.f;

    int nk = K / BKH;

    #pragma unroll
    for (int ps = 0; ps < 2; ps++) {
        int k0 = ps * BKH;
        #pragma unroll
        for (int cch = 0; cch < 4; cch++) {
            unsigned soff = (lr * RSH + lc + cch * 8) * 2;
            cpa16(stgA[ps] + soff, Ab + k0 + cch * 8);
            cpa16(stgW[ps] + soff, Wb + k0 + cch * 8);
        }
        asm volatile("cp.async.commit_group;\n");
    }

    int a_row = lane & 15;
    int a_col = (lane >> 4) * 8;
    int b_row = (lane & 7) + ((lane & 16) >> 1);
    int b_col = lane & 8;

    unsigned af[2][2][4], bf[2][4][4];

    for (int kt = 0; kt < nk; kt++) {
        if (kt < nk - 1) asm volatile("cp.async.wait_group 1;\n");
        else             asm volatile("cp.async.wait_group 0;\n");
        __syncthreads();

        if (kt + 2 < nk) {
            int st = (kt + 2) % NSTG;
            int k0 = (kt + 2) * BKH;
            #pragma unroll
            for (int cch = 0; cch < 4; cch++) {
                unsigned soff = (lr * RSH + lc + cch * 8) * 2;
                cpa16(stgA[st] + soff, Ab + k0 + cch * 8);
                cpa16(stgW[st] + soff, Wb + k0 + cch * 8);
            }
            asm volatile("cp.async.commit_group;\n");
        }

        int st = kt % NSTG;
        unsigned sAu = stgA[st];
        unsigned sWu = stgW[st];

        auto load_frags = [&](int buf, int ks) {
            int kb = ks * 16;
            #pragma unroll
            for (int mi = 0; mi < 2; mi++)
                ldsm4(af[buf][mi][0], af[buf][mi][1], af[buf][mi][2], af[buf][mi][3],
                      sAu + ((wm + mi * 16 + a_row) * RSH + kb + a_col) * 2);
            #pragma unroll
            for (int p = 0; p < 4; p++)
                ldsm4(bf[buf][p][0], bf[buf][p][1], bf[buf][p][2], bf[buf][p][3],
                      sWu + ((wn + p * 16 + b_row) * RSH + kb + b_col) * 2);
        };

        load_frags(0, 0);
        #pragma unroll
        for (int ks = 0; ks < 4; ks++) {
            int cur = ks & 1;
            if (ks < 3) load_frags(cur ^ 1, ks + 1);
            #pragma unroll
            for (int mi = 0; mi < 2; mi++)
                #pragma unroll
                for (int p = 0; p < 4; p++) {
                    mma16816(c[mi][2*p],   af[cur][mi][0], af[cur][mi][1], af[cur][mi][2],
                             af[cur][mi][3], bf[cur][p][0], bf[cur][p][1]);
                    mma16816(c[mi][2*p+1], af[cur][mi][0], af[cur][mi][1], af[cur][mi][2],
                             af[cur][mi][3], bf[cur][p][2], bf[cur][p][3]);
                }
        }
    }

    bool use_relu = (flags & 1) != 0;
    bool use_res  = (flags & 2) != 0;
    bool out_h    = (flags & 4) != 0;
    float* Cf = (float*)Cout;
    __half* Ch = (__half*)Cout;
    #pragma unroll
    for (int mi = 0; mi < 2; mi++) {
        #pragma unroll
        for (int ni = 0; ni < 8; ni++) {
            int colg = col0 + wn + ni * 8 + tig * 2;
            int r0 = row0 + wm + mi * 16 + gid;
            int r1 = r0 + 8;
            float b0 = bias[colg], b1 = bias[colg + 1];
            float2 o0, o1;
            o0.x = c[mi][ni][0] + b0; o0.y = c[mi][ni][1] + b1;
            o1.x = c[mi][ni][2] + b0; o1.y = c[mi][ni][3] + b1;
            size_t i0 = (size_t)r0 * N + colg;
            size_t i1 = (size_t)r1 * N + colg;
            if (use_res) {
                float2 rv0 = *(const float2*)(res + i0);
                float2 rv1 = *(const float2*)(res + i1);
                o0.x += rv0.x; o0.y += rv0.y;
                o1.x += rv1.x; o1.y += rv1.y;
            }
            if (use_relu) {
                o0.x = fmaxf(o0.x, 0.f); o0.y = fmaxf(o0.y, 0.f);
                o1.x = fmaxf(o1.x, 0.f); o1.y = fmaxf(o1.y, 0.f);
            }
            if (out_h) {
                __half2 h0 = __floats2half2_rn(o0.x, o0.y);
                __half2 h1 = __floats2half2_rn(o1.x, o1.y);
                *(unsigned*)(Ch + i0) = *(unsigned*)&h0;
                *(unsigned*)(Ch + i1) = *(unsigned*)&h1;
            } else {
                *(float2*)(Cf + i0) = o0;
                *(float2*)(Cf + i1) = o1;
            }
        }
    }
}

// ---------------- fp16 tensor-core flash attention (AQ=128, 8 warps) ----------
// block = 256 thr / 8 warps; 128 q rows per block; warp w owns q rows w*16..+15.
// K tiles of 64 keys. Per-tensor row strides (packed qk / kv buffers supported).
#define AQ 128
#define AK 64
#define AH 72   // halves per smem row

__global__ __launch_bounds__(256) void attn_h(const __half* __restrict__ Q,
                                              const __half* __restrict__ Km,
                                              const __half* __restrict__ Vm,
                                              __half* __restrict__ O,
                                              int Sq, int Sk, int causal,
                                              int qstr, int kstr, int vstr) {
    __shared__ __half Qs[AQ*AH], Ks[AK*AH], Vs[AK*AH];

    int qt = blockIdx.x, h = blockIdx.y, b = blockIdx.z;
    int tid = threadIdx.x;
    int wid = tid >> 5, lane = tid & 31;

    unsigned sQ = (unsigned)__cvta_generic_to_shared(Qs);
    unsigned sK = (unsigned)__cvta_generic_to_shared(Ks);
    unsigned sV = (unsigned)__cvta_generic_to_shared(Vs);

    // ---- load Q tile (128 rows x 64 halves), zero-fill rows >= Sq ----
    {
        int r = tid >> 1;
        int cb = (tid & 1) * 32;
        int qgl = qt * AQ + r;
        const __half* src = Q + ((size_t)(b * Sq + qgl)) * qstr + h * HD + cb;
        uint4 z = {0u, 0u, 0u, 0u};
        #pragma unroll
        for (int i = 0; i < 4; i++) {
            uint4 v = (qgl < Sq) ? *(const uint4*)(src + i * 8) : z;
            *(uint4*)&Qs[r * AH + cb + i * 8] = v;
        }
    }
    __syncthreads();

    int a_row = lane & 15;
    int a_col = (lane >> 4) * 8;
    unsigned aq[4][4];
    #pragma unroll
    for (int ks = 0; ks < 4; ks++)
        ldsm4(aq[ks][0], aq[ks][1], aq[ks][2], aq[ks][3],
              sQ + ((wid * 16 + a_row) * AH + ks * 16 + a_col) * 2);

    int b_row = (lane & 7) + ((lane & 16) >> 1);
    int b_col = lane & 8;

    int r0 = lane >> 2, tig = lane & 3;
    int qgl0 = qt * AQ + wid * 16 + r0;
    int qgl1 = qgl0 + 8;
    float m0 = -1e30f, m1 = -1e30f, l0 = 0.f, l1 = 0.f;
    float o[8][4];
    #pragma unroll
    for (int j = 0; j < 8; j++)
        #pragma unroll
        for (int q = 0; q < 4; q++) o[j][q] = 0.f;

    int q_hi = qt * AQ + AQ - 1;
    int keff = causal ? min(q_hi + 1, Sk) : Sk;
    int ntiles = (keff + AK - 1) / AK;

    // K/V loader: 64 rows x 64 halves = 512 x 8-half chunks; 256 thr -> 2 chunks each
    int kr = tid >> 3;                // 0..31
    int kc = (tid & 7) * 8;           // 0..56
    uint4 pk[2], pv[2];
    {
        uint4 z = {0u, 0u, 0u, 0u};
        #pragma unroll
        for (int j2 = 0; j2 < 2; j2++) {
            int kg = kr + 32 * j2;
            bool ok = kg < Sk;
            pk[j2] = ok ? *(const uint4*)(Km + ((size_t)(b * Sk + kg)) * kstr + h * HD + kc) : z;
            pv[j2] = ok ? *(const uint4*)(Vm + ((size_t)(b * Sk + kg)) * vstr + h * HD + kc) : z;
        }
    }

    for (int kt = 0; kt < ntiles; kt++) {
        #pragma unroll
        for (int j2 = 0; j2 < 2; j2++) {
            *(uint4*)&Ks[(kr + 32 * j2) * AH + kc] = pk[j2];
            *(uint4*)&Vs[(kr + 32 * j2) * AH + kc] = pv[j2];
        }
        __syncthreads();

        if (kt + 1 < ntiles) {
            uint4 z = {0u, 0u, 0u, 0u};
            #pragma unroll
            for (int j2 = 0; j2 < 2; j2++) {
                int kg = (kt + 1) * AK + kr + 32 * j2;
                bool ok = kg < Sk;
                pk[j2] = ok ? *(const uint4*)(Km + ((size_t)(b * Sk + kg)) * kstr + h * HD + kc) : z;
                pv[j2] = ok ? *(const uint4*)(Vm + ((size_t)(b * Sk + kg)) * vstr + h * HD + kc) : z;
            }
        }

        float s[8][4];
        #pragma unroll
        for (int j = 0; j < 8; j++)
            #pragma unroll
            for (int q = 0; q < 4; q++) s[j][q] = 0.f;

        #pragma unroll
        for (int ks = 0; ks < 4; ks++) {
            #pragma unroll
            for (int p = 0; p < 4; p++) {
                unsigned bf0, bf1, bf2, bf3;
                ldsm4(bf0, bf1, bf2, bf3,
                      sK + ((p * 16 + b_row) * AH + ks * 16 + b_col) * 2);
                mma16816(s[2*p],   aq[ks][0], aq[ks][1], aq[ks][2], aq[ks][3], bf0, bf1);
                mma16816(s[2*p+1], aq[ks][0], aq[ks][1], aq[ks][2], aq[ks][3], bf2, bf3);
            }
        }

        int kvalid0 = causal ? min(qgl0 + 1, Sk) : Sk;
        int kvalid1 = causal ? min(qgl1 + 1, Sk) : Sk;
        int kgb = kt * AK + tig * 2;
        float tm0 = -1e30f, tm1 = -1e30f;
        #pragma unroll
        for (int j = 0; j < 8; j++) {
            int kg = kgb + j * 8;
            s[j][0] = (kg     < kvalid0) ? s[j][0] * 0.125f : -1e30f;
            s[j][1] = (kg + 1 < kvalid0) ? s[j][1] * 0.125f : -1e30f;
            s[j][2] = (kg     < kvalid1) ? s[j][2] * 0.125f : -1e30f;
            s[j][3] = (kg + 1 < kvalid1) ? s[j][3] * 0.125f : -1e30f;
            tm0 = fmaxf(tm0, fmaxf(s[j][0], s[j][1]));
            tm1 = fmaxf(tm1, fmaxf(s[j][2], s[j][3]));
        }
        tm0 = fmaxf(tm0, __shfl_xor_sync(0xffffffffu, tm0, 1));
        tm0 = fmaxf(tm0, __shfl_xor_sync(0xffffffffu, tm0, 2));
        tm1 = fmaxf(tm1, __shfl_xor_sync(0xffffffffu, tm1, 1));
        tm1 = fmaxf(tm1, __shfl_xor_sync(0xffffffffu, tm1, 2));

        float mn0 = fmaxf(m0, tm0), mn1 = fmaxf(m1, tm1);
        float sc0 = __expf(m0 - mn0), sc1 = __expf(m1 - mn1);
        float ps0 = 0.f, ps1 = 0.f;
        #pragma unroll
        for (int j = 0; j < 8; j++) {
            s[j][0] = __expf(s[j][0] - mn0);
            s[j][1] = __expf(s[j][1] - mn0);
            s[j][2] = __expf(s[j][2] - mn1);
            s[j][3] = __expf(s[j][3] - mn1);
            ps0 += s[j][0] + s[j][1];
            ps1 += s[j][2] + s[j][3];
        }
        ps0 += __shfl_xor_sync(0xffffffffu, ps0, 1);
        ps0 += __shfl_xor_sync(0xffffffffu, ps0, 2);
        ps1 += __shfl_xor_sync(0xffffffffu, ps1, 1);
        ps1 += __shfl_xor_sync(0xffffffffu, ps1, 2);
        l0 = l0 * sc0 + ps0;  m0 = mn0;
        l1 = l1 * sc1 + ps1;  m1 = mn1;
        #pragma unroll
        for (int j = 0; j < 8; j++) {
            o[j][0] *= sc0; o[j][1] *= sc0;
            o[j][2] *= sc1; o[j][3] *= sc1;
        }

        unsigned pa[4][4];
        #pragma unroll
        for (int t = 0; t < 4; t++) {
            __half2 h0 = __floats2half2_rn(s[2*t][0],   s[2*t][1]);
            __half2 h1 = __floats2half2_rn(s[2*t][2],   s[2*t][3]);
            __half2 h2 = __floats2half2_rn(s[2*t+1][0], s[2*t+1][1]);
            __half2 h3 = __floats2half2_rn(s[2*t+1][2], s[2*t+1][3]);
            pa[t][0] = *(unsigned*)&h0;
            pa[t][1] = *(unsigned*)&h1;
            pa[t][2] = *(unsigned*)&h2;
            pa[t][3] = *(unsigned*)&h3;
        }

        #pragma unroll
        for (int t = 0; t < 4; t++) {
            #pragma unroll
            for (int p = 0; p < 4; p++) {
                unsigned bv0, bv1, bv2, bv3;
                ldsm4t(bv0, bv1, bv2, bv3,
                       sV + ((t * 16 + (lane & 15)) * AH + p * 16 + (lane >> 4) * 8) * 2);
                mma16816(o[2*p],   pa[t][0], pa[t][1], pa[t][2], pa[t][3], bv0, bv1);
                mma16816(o[2*p+1], pa[t][0], pa[t][1], pa[t][2], pa[t][3], bv2, bv3);
            }
        }
        __syncthreads();
    }

    float inv0 = 1.0f / l0, inv1 = 1.0f / l1;
    #pragma unroll
    for (int j = 0; j < 8; j++) {
        int d = j * 8 + tig * 2;
        if (qgl0 < Sq) {
            __half2 h0 = __floats2half2_rn(o[j][0] * inv0, o[j][1] * inv0);
            *(unsigned*)(O + ((size_t)(b * Sq + qgl0)) * DMODEL + h * HD + d) = *(unsigned*)&h0;
        }
        if (qgl1 < Sq) {
            __half2 h1 = __floats2half2_rn(o[j][2] * inv1, o[j][3] * inv1);
            *(unsigned*)(O + ((size_t)(b * Sq + qgl1)) * DMODEL + h * HD + d) = *(unsigned*)&h1;
        }
    }
}

// ---------------- host orchestration ----------------
extern "C" void kernel_launch(void* const* d_in, const int* in_sizes, int n_in,
                              void* d_out, int out_size) {
    const float* tgt      = (const float*)d_in[0];
    const float* memory   = (const float*)d_in[1];
    const float* sa_in_w  = (const float*)d_in[2];
    const float* sa_in_b  = (const float*)d_in[3];
    const float* sa_out_w = (const float*)d_in[4];
    const float* sa_out_b = (const float*)d_in[5];
    const float* ca_in_w  = (const float*)d_in[6];
    const float* ca_in_b  = (const float*)d_in[7];
    const float* ca_out_w = (const float*)d_in[8];
    const float* ca_out_b = (const float*)d_in[9];
    const float* ff1_w    = (const float*)d_in[10];
    const float* ff1_b    = (const float*)d_in[11];
    const float* ff2_w    = (const float*)d_in[12];
    const float* ff2_b    = (const float*)d_in[13];
    const float* ln1_g    = (const float*)d_in[14];
    const float* ln1_b    = (const float*)d_in[15];
    const float* ln2_g    = (const float*)d_in[16];
    const float* ln2_b    = (const float*)d_in[17];
    const float* ln3_g    = (const float*)d_in[18];
    const float* ln3_b    = (const float*)d_in[19];
    float* out = (float*)d_out;

    float *p_x;
    __half *p_qkh, *p_vh, *p_qh, *p_kvh, *p_hh, *p_ropedh, *p_attnh, *p_ffhh, *p_memh, *p_wh;
    cudaGetSymbolAddress((void**)&p_x,      g_x);
    cudaGetSymbolAddress((void**)&p_qkh,    g_qkh);
    cudaGetSymbolAddress((void**)&p_vh,     g_vh);
    cudaGetSymbolAddress((void**)&p_qh,     g_qh);
    cudaGetSymbolAddress((void**)&p_kvh,    g_kvh);
    cudaGetSymbolAddress((void**)&p_hh,     g_hh);
    cudaGetSymbolAddress((void**)&p_ropedh, g_ropedh);
    cudaGetSymbolAddress((void**)&p_attnh,  g_attnh);
    cudaGetSymbolAddress((void**)&p_ffhh,   g_ffhh);
    cudaGetSymbolAddress((void**)&p_memh,   g_memh);
    cudaGetSymbolAddress((void**)&p_wh,     g_wh);

    static int smem_set = 0;
    if (!smem_set) {
        cudaFuncSetAttribute(hgemm, cudaFuncAttributeMaxDynamicSharedMemorySize, GSMEM);
        smem_set = 1;
    }

    auto tohalf = [](const float* src, __half* dst, int n) {
        int n4 = n / 4;
        int blocks = (n4 + 1023) / 1024;
        to_half_kernel<<<blocks, 256>>>((const float4*)src, (uint2*)dst, n4);
    };
    tohalf(sa_in_w,  p_wh + OW_SA_IN,  3 * DMODEL * DMODEL);
    tohalf(sa_out_w, p_wh + OW_SA_OUT, DMODEL * DMODEL);
    tohalf(ca_in_w,  p_wh + OW_CA_IN,  3 * DMODEL * DMODEL);
    tohalf(ca_out_w, p_wh + OW_CA_OUT, DMODEL * DMODEL);
    tohalf(ff1_w,    p_wh + OW_FF1,    DFF * DMODEL);
    tohalf(ff2_w,    p_wh + OW_FF2,    DMODEL * DFF);
    tohalf(memory,   p_memh,           MTOK * DMODEL);

    dim3 gemm_nt_d(DMODEL / 128, NT / 128);         // (8, 50)
    dim3 gemm_nt_2d(2048 / 128, NT / 128);          // (16, 50) merged q+k
    dim3 gemm_mt_2d(2048 / 128, MTOK / 128);        // (16, 256) merged k+v
    dim3 gemm_ff1(DFF / 128, NT / 128);
    int qtiles = (SQ + AQ - 1) / AQ;                // 2

    // ---- self-attention block ----
    ln_kernel<<<NT, 256>>>(tgt, ln1_g, ln1_b, p_hh, p_ropedh);   // fused LN+RoPE
    hgemm<<<gemm_nt_2d, 256, GSMEM>>>(p_ropedh, p_wh + OW_SA_IN, sa_in_b, nullptr, p_qkh, NT, 2048, DMODEL, 4);
    hgemm<<<gemm_nt_d, 256, GSMEM>>>(p_hh, p_wh + OW_SA_IN + (size_t)2*DMODEL*DMODEL, sa_in_b + 2*DMODEL, nullptr, p_vh, NT, DMODEL, DMODEL, 4);
    attn_h<<<dim3(qtiles, NH, BB), 256>>>(p_qkh, p_qkh + 1024, p_vh, p_attnh, SQ, SQ, 1, 2048, 2048, 1024);
    hgemm<<<gemm_nt_d, 256, GSMEM>>>(p_attnh, p_wh + OW_SA_OUT, sa_out_b, tgt, p_x, NT, DMODEL, DMODEL, 2);

    // ---- cross-attention block ----
    ln_kernel<<<NT, 256>>>(p_x, ln2_g, ln2_b, p_hh, nullptr);
    hgemm<<<gemm_nt_d, 256, GSMEM>>>(p_hh, p_wh + OW_CA_IN, ca_in_b, nullptr, p_qh, NT, DMODEL, DMODEL, 4);
    hgemm<<<gemm_mt_2d, 256, GSMEM>>>(p_memh, p_wh + OW_CA_IN + (size_t)DMODEL*DMODEL, ca_in_b + DMODEL, nullptr, p_kvh, MTOK, 2048, DMODEL, 4);
    attn_h<<<dim3(qtiles, NH, BB), 256>>>(p_qh, p_kvh, p_kvh + 1024, p_attnh, SQ, SMEMLEN, 0, 1024, 2048, 2048);
    hgemm<<<gemm_nt_d, 256, GSMEM>>>(p_attnh, p_wh + OW_CA_OUT, ca_out_b, p_x, p_x, NT, DMODEL, DMODEL, 2);

    // ---- feed-forward block ----
    ln_kernel<<<NT, 256>>>(p_x, ln3_g, ln3_b, p_hh, nullptr);
    hgemm<<<gemm_ff1, 256, GSMEM>>>(p_hh,   p_wh + OW_FF1, ff1_b, nullptr, p_ffhh, NT, DFF, DMODEL, 1 | 4);
    hgemm<<<gemm_nt_d, 256, GSMEM>>>(p_ffhh, p_wh + OW_FF2, ff2_b, p_x, out, NT, DMODEL, DFF, 2);
}

// round 13
// speedup vs baseline: 2.1208x; 1.0079x over previous
#include <cuda_runtime.h>
#include <cuda_fp16.h>
#include <math.h>

#define BB 32
#define SQ 200
#define SMEMLEN 1024
#define DMODEL 1024
#define NH 16
#define HD 64
#define DFF 4096
#define NT (BB*SQ)        // 6400 target tokens
#define MTOK (BB*SMEMLEN) // 32768 memory tokens
#define EPS 1e-5f

// ---------------- scratch ----------------
__device__ float  g_x[NT*DMODEL];
__device__ __half g_qkh[NT*2048];       // SA q|k packed (row stride 2048)
__device__ __half g_vh[NT*DMODEL];      // SA v
__device__ __half g_qh[NT*DMODEL];      // CA q
__device__ __half g_kvh[MTOK*2048];     // CA k|v packed (row stride 2048)
__device__ __half g_hh[NT*DMODEL];
__device__ __half g_ropedh[NT*DMODEL];
__device__ __half g_attnh[NT*DMODEL];
__device__ __half g_ffhh[NT*DFF];
__device__ __half g_memh[MTOK*DMODEL];
__device__ __half g_wh[16*1024*1024];   // fp16 weights (packed)

#define OW_SA_IN   0
#define OW_SA_OUT  3145728
#define OW_CA_IN   4194304
#define OW_CA_OUT  7340032
#define OW_FF1     8388608
#define OW_FF2     12582912

// ---------------- fp32 -> fp16 convert (MLP=4 grid-stride) ----------------
__global__ void to_half_kernel(const float4* __restrict__ in,
                               uint2* __restrict__ out, int n4) {
    int idx = blockIdx.x * blockDim.x + threadIdx.x;
    int T = gridDim.x * blockDim.x;
    for (int base = idx; base < n4; base += 4 * T) {
        float4 v[4];
        int k1 = base + T, k2 = base + 2 * T, k3 = base + 3 * T;
        v[0] = in[base];
        if (k1 < n4) v[1] = in[k1];
        if (k2 < n4) v[2] = in[k2];
        if (k3 < n4) v[3] = in[k3];
        {
            __half2 h0 = __floats2half2_rn(v[0].x, v[0].y);
            __half2 h1 = __floats2half2_rn(v[0].z, v[0].w);
            uint2 o; o.x = *(unsigned*)&h0; o.y = *(unsigned*)&h1;
            out[base] = o;
        }
        if (k1 < n4) {
            __half2 h0 = __floats2half2_rn(v[1].x, v[1].y);
            __half2 h1 = __floats2half2_rn(v[1].z, v[1].w);
            uint2 o; o.x = *(unsigned*)&h0; o.y = *(unsigned*)&h1;
            out[k1] = o;
        }
        if (k2 < n4) {
            __half2 h0 = __floats2half2_rn(v[2].x, v[2].y);
            __half2 h1 = __floats2half2_rn(v[2].z, v[2].w);
            uint2 o; o.x = *(unsigned*)&h0; o.y = *(unsigned*)&h1;
            out[k2] = o;
        }
        if (k3 < n4) {
            __half2 h0 = __floats2half2_rn(v[3].x, v[3].y);
            __half2 h1 = __floats2half2_rn(v[3].z, v[3].w);
            uint2 o; o.x = *(unsigned*)&h0; o.y = *(unsigned*)&h1;
            out[k3] = o;
        }
    }
}

// ---------------- LayerNorm (fp32 in, fp16 out; optional fused RoPE out) -------
__global__ __launch_bounds__(256) void ln_kernel(const float* __restrict__ x,
                                                 const float* __restrict__ g,
                                                 const float* __restrict__ b,
                                                 __half* __restrict__ out,
                                                 __half* __restrict__ out_roped) {
    __shared__ float rs[8], rss[8];
    int t = blockIdx.x;
    int tid = threadIdx.x;
    const float4* xr = (const float4*)(x + (size_t)t * DMODEL);
    float4 v = xr[tid];
    float s  = v.x + v.y + v.z + v.w;
    float ss = v.x*v.x + v.y*v.y + v.z*v.z + v.w*v.w;
    #pragma unroll
    for (int o = 16; o; o >>= 1) {
        s  += __shfl_xor_sync(0xffffffffu, s, o);
        ss += __shfl_xor_sync(0xffffffffu, ss, o);
    }
    int lane = tid & 31, wid = tid >> 5;
    if (lane == 0) { rs[wid] = s; rss[wid] = ss; }
    __syncthreads();
    float ts = 0.f, tss = 0.f;
    #pragma unroll
    for (int w = 0; w < 8; w++) { ts += rs[w]; tss += rss[w]; }
    float mu  = ts * (1.0f / DMODEL);
    float var = tss * (1.0f / DMODEL) - mu * mu;
    float r   = rsqrtf(var + EPS);
    float4 gv = ((const float4*)g)[tid];
    float4 bv = ((const float4*)b)[tid];
    float ox = (v.x - mu) * r * gv.x + bv.x;
    float oy = (v.y - mu) * r * gv.y + bv.y;
    float oz = (v.z - mu) * r * gv.z + bv.z;
    float ow = (v.w - mu) * r * gv.w + bv.w;
    {
        __half2 h0 = __floats2half2_rn(ox, oy);
        __half2 h1 = __floats2half2_rn(oz, ow);
        uint2 o;
        o.x = *(unsigned*)&h0;
        o.y = *(unsigned*)&h1;
        ((uint2*)(out + (size_t)t * DMODEL))[tid] = o;
    }
    if (out_roped) {
        int e0 = tid * 4;
        int i0 = (e0 & 63) >> 1;
        int spos = t % SQ;
        float f0 = __expf(-9.210340371976184f * (2.0f * i0) * (1.0f / 64.0f));
        float f1 = __expf(-9.210340371976184f * (2.0f * (i0 + 1)) * (1.0f / 64.0f));
        float sn0, cs0, sn1, cs1;
        sincosf((float)spos * f0, &sn0, &cs0);
        sincosf((float)spos * f1, &sn1, &cs1);
        float r0x = ox * cs0 - oy * sn0;
        float r0y = oy * cs0 + ox * sn0;
        float r1x = oz * cs1 - ow * sn1;
        float r1y = ow * cs1 + oz * sn1;
        __half2 h0 = __floats2half2_rn(r0x, r0y);
        __half2 h1 = __floats2half2_rn(r1x, r1y);
        uint2 o;
        o.x = *(unsigned*)&h0;
        o.y = *(unsigned*)&h1;
        ((uint2*)(out_roped + (size_t)t * DMODEL))[tid] = o;
    }
}

// ---------------- common mma helpers ----------------
__device__ __forceinline__ void cpa16(unsigned dst, const void* src) {
    asm volatile("cp.async.cg.shared.global [%0], [%1], 16;\n" :: "r"(dst), "l"(src));
}
__device__ __forceinline__ void ldsm4(unsigned& r0, unsigned& r1, unsigned& r2, unsigned& r3,
                                      unsigned a) {
    asm volatile("ldmatrix.sync.aligned.m8n8.x4.shared.b16 {%0,%1,%2,%3}, [%4];"
                 : "=r"(r0), "=r"(r1), "=r"(r2), "=r"(r3) : "r"(a));
}
__device__ __forceinline__ void ldsm4t(unsigned& r0, unsigned& r1, unsigned& r2, unsigned& r3,
                                       unsigned a) {
    asm volatile("ldmatrix.sync.aligned.m8n8.x4.trans.shared.b16 {%0,%1,%2,%3}, [%4];"
                 : "=r"(r0), "=r"(r1), "=r"(r2), "=r"(r3) : "r"(a));
}
__device__ __forceinline__ void mma16816(float* c, unsigned a0, unsigned a1, unsigned a2,
                                         unsigned a3, unsigned b0, unsigned b1) {
    asm volatile(
        "mma.sync.aligned.m16n8k16.row.col.f32.f16.f16.f32 "
        "{%0,%1,%2,%3}, {%4,%5,%6,%7}, {%8,%9}, {%0,%1,%2,%3};"
        : "+f"(c[0]), "+f"(c[1]), "+f"(c[2]), "+f"(c[3])
        : "r"(a0), "r"(a1), "r"(a2), "r"(a3), "r"(b0), "r"(b1));
}

// ---------------- fp16 tensor-core GEMM (3-stage cp.async + ldmatrix) ----------
#define BKH 64
#define RSH 72
#define NSTG 3
#define STGH (2 * 128 * RSH)
#define GSMEM (NSTG * STGH * 2)          // 110592 bytes

__global__ __launch_bounds__(256, 2) void hgemm(const __half* __restrict__ A,
                                                const __half* __restrict__ W,
                                                const float* __restrict__ bias,
                                                const float* __restrict__ res,
                                                void* __restrict__ Cout,
                                                int M, int N, int K, int flags) {
    extern __shared__ __half smh[];
    int tid = threadIdx.x;
    int wid = tid >> 5, lane = tid & 31;
    int gid = lane >> 2, tig = lane & 3;
    int row0 = blockIdx.y * 128;
    int col0 = blockIdx.x * 128;
    int wm = (wid & 3) * 32;
    int wn = (wid >> 2) * 64;

    unsigned sbase = (unsigned)__cvta_generic_to_shared(smh);
    unsigned stgA[NSTG], stgW[NSTG];
    #pragma unroll
    for (int s = 0; s < NSTG; s++) {
        stgA[s] = sbase + s * STGH * 2;
        stgW[s] = stgA[s] + 128 * RSH * 2;
    }

    int lr = tid >> 1;
    int lc = (tid & 1) * 32;
    const __half* Ab = A + (size_t)(row0 + lr) * K + lc;
    const __half* Wb = W + (size_t)(col0 + lr) * K + lc;

    float c[2][8][4];
    #pragma unroll
    for (int mi = 0; mi < 2; mi++)
        #pragma unroll
        for (int ni = 0; ni < 8; ni++)
            #pragma unroll
            for (int q = 0; q < 4; q++) c[mi][ni][q] = 0.f;

    int nk = K / BKH;

    #pragma unroll
    for (int ps = 0; ps < 2; ps++) {
        int k0 = ps * BKH;
        #pragma unroll
        for (int cch = 0; cch < 4; cch++) {
            unsigned soff = (lr * RSH + lc + cch * 8) * 2;
            cpa16(stgA[ps] + soff, Ab + k0 + cch * 8);
            cpa16(stgW[ps] + soff, Wb + k0 + cch * 8);
        }
        asm volatile("cp.async.commit_group;\n");
    }

    int a_row = lane & 15;
    int a_col = (lane >> 4) * 8;
    int b_row = (lane & 7) + ((lane & 16) >> 1);
    int b_col = lane & 8;

    unsigned af[2][2][4], bf[2][4][4];

    for (int kt = 0; kt < nk; kt++) {
        if (kt < nk - 1) asm volatile("cp.async.wait_group 1;\n");
        else             asm volatile("cp.async.wait_group 0;\n");
        __syncthreads();

        if (kt + 2 < nk) {
            int st = (kt + 2) % NSTG;
            int k0 = (kt + 2) * BKH;
            #pragma unroll
            for (int cch = 0; cch < 4; cch++) {
                unsigned soff = (lr * RSH + lc + cch * 8) * 2;
                cpa16(stgA[st] + soff, Ab + k0 + cch * 8);
                cpa16(stgW[st] + soff, Wb + k0 + cch * 8);
            }
            asm volatile("cp.async.commit_group;\n");
        }

        int st = kt % NSTG;
        unsigned sAu = stgA[st];
        unsigned sWu = stgW[st];

        auto load_frags = [&](int buf, int ks) {
            int kb = ks * 16;
            #pragma unroll
            for (int mi = 0; mi < 2; mi++)
                ldsm4(af[buf][mi][0], af[buf][mi][1], af[buf][mi][2], af[buf][mi][3],
                      sAu + ((wm + mi * 16 + a_row) * RSH + kb + a_col) * 2);
            #pragma unroll
            for (int p = 0; p < 4; p++)
                ldsm4(bf[buf][p][0], bf[buf][p][1], bf[buf][p][2], bf[buf][p][3],
                      sWu + ((wn + p * 16 + b_row) * RSH + kb + b_col) * 2);
        };

        load_frags(0, 0);
        #pragma unroll
        for (int ks = 0; ks < 4; ks++) {
            int cur = ks & 1;
            if (ks < 3) load_frags(cur ^ 1, ks + 1);
            #pragma unroll
            for (int mi = 0; mi < 2; mi++)
                #pragma unroll
                for (int p = 0; p < 4; p++) {
                    mma16816(c[mi][2*p],   af[cur][mi][0], af[cur][mi][1], af[cur][mi][2],
                             af[cur][mi][3], bf[cur][p][0], bf[cur][p][1]);
                    mma16816(c[mi][2*p+1], af[cur][mi][0], af[cur][mi][1], af[cur][mi][2],
                             af[cur][mi][3], bf[cur][p][2], bf[cur][p][3]);
                }
        }
    }

    bool use_relu = (flags & 1) != 0;
    bool use_res  = (flags & 2) != 0;
    bool out_h    = (flags & 4) != 0;
    float* Cf = (float*)Cout;
    __half* Ch = (__half*)Cout;
    #pragma unroll
    for (int mi = 0; mi < 2; mi++) {
        #pragma unroll
        for (int ni = 0; ni < 8; ni++) {
            int colg = col0 + wn + ni * 8 + tig * 2;
            int r0 = row0 + wm + mi * 16 + gid;
            int r1 = r0 + 8;
            float b0 = bias[colg], b1 = bias[colg + 1];
            float2 o0, o1;
            o0.x = c[mi][ni][0] + b0; o0.y = c[mi][ni][1] + b1;
            o1.x = c[mi][ni][2] + b0; o1.y = c[mi][ni][3] + b1;
            size_t i0 = (size_t)r0 * N + colg;
            size_t i1 = (size_t)r1 * N + colg;
            if (use_res) {
                float2 rv0 = *(const float2*)(res + i0);
                float2 rv1 = *(const float2*)(res + i1);
                o0.x += rv0.x; o0.y += rv0.y;
                o1.x += rv1.x; o1.y += rv1.y;
            }
            if (use_relu) {
                o0.x = fmaxf(o0.x, 0.f); o0.y = fmaxf(o0.y, 0.f);
                o1.x = fmaxf(o1.x, 0.f); o1.y = fmaxf(o1.y, 0.f);
            }
            if (out_h) {
                __half2 h0 = __floats2half2_rn(o0.x, o0.y);
                __half2 h1 = __floats2half2_rn(o1.x, o1.y);
                *(unsigned*)(Ch + i0) = *(unsigned*)&h0;
                *(unsigned*)(Ch + i1) = *(unsigned*)&h1;
            } else {
                *(float2*)(Cf + i0) = o0;
                *(float2*)(Cf + i1) = o1;
            }
        }
    }
}

// ---------------- fp16 tensor-core flash attention (AQ=128, 8 warps) ----------
#define AQ 128
#define AK 64
#define AH 72   // halves per smem row

__global__ __launch_bounds__(256) void attn_h(const __half* __restrict__ Q,
                                              const __half* __restrict__ Km,
                                              const __half* __restrict__ Vm,
                                              __half* __restrict__ O,
                                              int Sq, int Sk, int causal,
                                              int qstr, int kstr, int vstr) {
    __shared__ __half Qs[AQ*AH], Ks[AK*AH], Vs[AK*AH];

    int qt = blockIdx.x, h = blockIdx.y, b = blockIdx.z;
    int tid = threadIdx.x;
    int wid = tid >> 5, lane = tid & 31;

    unsigned sQ = (unsigned)__cvta_generic_to_shared(Qs);
    unsigned sK = (unsigned)__cvta_generic_to_shared(Ks);
    unsigned sV = (unsigned)__cvta_generic_to_shared(Vs);

    {
        int r = tid >> 1;
        int cb = (tid & 1) * 32;
        int qgl = qt * AQ + r;
        const __half* src = Q + ((size_t)(b * Sq + qgl)) * qstr + h * HD + cb;
        uint4 z = {0u, 0u, 0u, 0u};
        #pragma unroll
        for (int i = 0; i < 4; i++) {
            uint4 v = (qgl < Sq) ? *(const uint4*)(src + i * 8) : z;
            *(uint4*)&Qs[r * AH + cb + i * 8] = v;
        }
    }
    __syncthreads();

    int a_row = lane & 15;
    int a_col = (lane >> 4) * 8;
    unsigned aq[4][4];
    #pragma unroll
    for (int ks = 0; ks < 4; ks++)
        ldsm4(aq[ks][0], aq[ks][1], aq[ks][2], aq[ks][3],
              sQ + ((wid * 16 + a_row) * AH + ks * 16 + a_col) * 2);

    int b_row = (lane & 7) + ((lane & 16) >> 1);
    int b_col = lane & 8;

    int r0 = lane >> 2, tig = lane & 3;
    int qgl0 = qt * AQ + wid * 16 + r0;
    int qgl1 = qgl0 + 8;
    float m0 = -1e30f, m1 = -1e30f, l0 = 0.f, l1 = 0.f;
    float o[8][4];
    #pragma unroll
    for (int j = 0; j < 8; j++)
        #pragma unroll
        for (int q = 0; q < 4; q++) o[j][q] = 0.f;

    int q_hi = qt * AQ + AQ - 1;
    int keff = causal ? min(q_hi + 1, Sk) : Sk;
    int ntiles = (keff + AK - 1) / AK;

    int kr = tid >> 3;
    int kc = (tid & 7) * 8;
    uint4 pk[2], pv[2];
    {
        uint4 z = {0u, 0u, 0u, 0u};
        #pragma unroll
        for (int j2 = 0; j2 < 2; j2++) {
            int kg = kr + 32 * j2;
            bool ok = kg < Sk;
            pk[j2] = ok ? *(const uint4*)(Km + ((size_t)(b * Sk + kg)) * kstr + h * HD + kc) : z;
            pv[j2] = ok ? *(const uint4*)(Vm + ((size_t)(b * Sk + kg)) * vstr + h * HD + kc) : z;
        }
    }

    for (int kt = 0; kt < ntiles; kt++) {
        #pragma unroll
        for (int j2 = 0; j2 < 2; j2++) {
            *(uint4*)&Ks[(kr + 32 * j2) * AH + kc] = pk[j2];
            *(uint4*)&Vs[(kr + 32 * j2) * AH + kc] = pv[j2];
        }
        __syncthreads();

        if (kt + 1 < ntiles) {
            uint4 z = {0u, 0u, 0u, 0u};
            #pragma unroll
            for (int j2 = 0; j2 < 2; j2++) {
                int kg = (kt + 1) * AK + kr + 32 * j2;
                bool ok = kg < Sk;
                pk[j2] = ok ? *(const uint4*)(Km + ((size_t)(b * Sk + kg)) * kstr + h * HD + kc) : z;
                pv[j2] = ok ? *(const uint4*)(Vm + ((size_t)(b * Sk + kg)) * vstr + h * HD + kc) : z;
            }
        }

        float s[8][4];
        #pragma unroll
        for (int j = 0; j < 8; j++)
            #pragma unroll
            for (int q = 0; q < 4; q++) s[j][q] = 0.f;

        #pragma unroll
        for (int ks = 0; ks < 4; ks++) {
            #pragma unroll
            for (int p = 0; p < 4; p++) {
                unsigned bf0, bf1, bf2, bf3;
                ldsm4(bf0, bf1, bf2, bf3,
                      sK + ((p * 16 + b_row) * AH + ks * 16 + b_col) * 2);
                mma16816(s[2*p],   aq[ks][0], aq[ks][1], aq[ks][2], aq[ks][3], bf0, bf1);
                mma16816(s[2*p+1], aq[ks][0], aq[ks][1], aq[ks][2], aq[ks][3], bf2, bf3);
            }
        }

        int kvalid0 = causal ? min(qgl0 + 1, Sk) : Sk;
        int kvalid1 = causal ? min(qgl1 + 1, Sk) : Sk;
        int kgb = kt * AK + tig * 2;
        float tm0 = -1e30f, tm1 = -1e30f;
        #pragma unroll
        for (int j = 0; j < 8; j++) {
            int kg = kgb + j * 8;
            s[j][0] = (kg     < kvalid0) ? s[j][0] * 0.125f : -1e30f;
            s[j][1] = (kg + 1 < kvalid0) ? s[j][1] * 0.125f : -1e30f;
            s[j][2] = (kg     < kvalid1) ? s[j][2] * 0.125f : -1e30f;
            s[j][3] = (kg + 1 < kvalid1) ? s[j][3] * 0.125f : -1e30f;
            tm0 = fmaxf(tm0, fmaxf(s[j][0], s[j][1]));
            tm1 = fmaxf(tm1, fmaxf(s[j][2], s[j][3]));
        }
        tm0 = fmaxf(tm0, __shfl_xor_sync(0xffffffffu, tm0, 1));
        tm0 = fmaxf(tm0, __shfl_xor_sync(0xffffffffu, tm0, 2));
        tm1 = fmaxf(tm1, __shfl_xor_sync(0xffffffffu, tm1, 1));
        tm1 = fmaxf(tm1, __shfl_xor_sync(0xffffffffu, tm1, 2));

        float mn0 = fmaxf(m0, tm0), mn1 = fmaxf(m1, tm1);
        float sc0 = __expf(m0 - mn0), sc1 = __expf(m1 - mn1);
        float ps0 = 0.f, ps1 = 0.f;
        #pragma unroll
        for (int j = 0; j < 8; j++) {
            s[j][0] = __expf(s[j][0] - mn0);
            s[j][1] = __expf(s[j][1] - mn0);
            s[j][2] = __expf(s[j][2] - mn1);
            s[j][3] = __expf(s[j][3] - mn1);
            ps0 += s[j][0] + s[j][1];
            ps1 += s[j][2] + s[j][3];
        }
        ps0 += __shfl_xor_sync(0xffffffffu, ps0, 1);
        ps0 += __shfl_xor_sync(0xffffffffu, ps0, 2);
        ps1 += __shfl_xor_sync(0xffffffffu, ps1, 1);
        ps1 += __shfl_xor_sync(0xffffffffu, ps1, 2);
        l0 = l0 * sc0 + ps0;  m0 = mn0;
        l1 = l1 * sc1 + ps1;  m1 = mn1;
        #pragma unroll
        for (int j = 0; j < 8; j++) {
            o[j][0] *= sc0; o[j][1] *= sc0;
            o[j][2] *= sc1; o[j][3] *= sc1;
        }

        unsigned pa[4][4];
        #pragma unroll
        for (int t = 0; t < 4; t++) {
            __half2 h0 = __floats2half2_rn(s[2*t][0],   s[2*t][1]);
            __half2 h1 = __floats2half2_rn(s[2*t][2],   s[2*t][3]);
            __half2 h2 = __floats2half2_rn(s[2*t+1][0], s[2*t+1][1]);
            __half2 h3 = __floats2half2_rn(s[2*t+1][2], s[2*t+1][3]);
            pa[t][0] = *(unsigned*)&h0;
            pa[t][1] = *(unsigned*)&h1;
            pa[t][2] = *(unsigned*)&h2;
            pa[t][3] = *(unsigned*)&h3;
        }

        #pragma unroll
        for (int t = 0; t < 4; t++) {
            #pragma unroll
            for (int p = 0; p < 4; p++) {
                unsigned bv0, bv1, bv2, bv3;
                ldsm4t(bv0, bv1, bv2, bv3,
                       sV + ((t * 16 + (lane & 15)) * AH + p * 16 + (lane >> 4) * 8) * 2);
                mma16816(o[2*p],   pa[t][0], pa[t][1], pa[t][2], pa[t][3], bv0, bv1);
                mma16816(o[2*p+1], pa[t][0], pa[t][1], pa[t][2], pa[t][3], bv2, bv3);
            }
        }
        __syncthreads();
    }

    float inv0 = 1.0f / l0, inv1 = 1.0f / l1;
    #pragma unroll
    for (int j = 0; j < 8; j++) {
        int d = j * 8 + tig * 2;
        if (qgl0 < Sq) {
            __half2 h0 = __floats2half2_rn(o[j][0] * inv0, o[j][1] * inv0);
            *(unsigned*)(O + ((size_t)(b * Sq + qgl0)) * DMODEL + h * HD + d) = *(unsigned*)&h0;
        }
        if (qgl1 < Sq) {
            __half2 h1 = __floats2half2_rn(o[j][2] * inv1, o[j][3] * inv1);
            *(unsigned*)(O + ((size_t)(b * Sq + qgl1)) * DMODEL + h * HD + d) = *(unsigned*)&h1;
        }
    }
}

// ---------------- host orchestration ----------------
extern "C" void kernel_launch(void* const* d_in, const int* in_sizes, int n_in,
                              void* d_out, int out_size) {
    const float* tgt      = (const float*)d_in[0];
    const float* memory   = (const float*)d_in[1];
    const float* sa_in_w  = (const float*)d_in[2];
    const float* sa_in_b  = (const float*)d_in[3];
    const float* sa_out_w = (const float*)d_in[4];
    const float* sa_out_b = (const float*)d_in[5];
    const float* ca_in_w  = (const float*)d_in[6];
    const float* ca_in_b  = (const float*)d_in[7];
    const float* ca_out_w = (const float*)d_in[8];
    const float* ca_out_b = (const float*)d_in[9];
    const float* ff1_w    = (const float*)d_in[10];
    const float* ff1_b    = (const float*)d_in[11];
    const float* ff2_w    = (const float*)d_in[12];
    const float* ff2_b    = (const float*)d_in[13];
    const float* ln1_g    = (const float*)d_in[14];
    const float* ln1_b    = (const float*)d_in[15];
    const float* ln2_g    = (const float*)d_in[16];
    const float* ln2_b    = (const float*)d_in[17];
    const float* ln3_g    = (const float*)d_in[18];
    const float* ln3_b    = (const float*)d_in[19];
    float* out = (float*)d_out;

    float *p_x;
    __half *p_qkh, *p_vh, *p_qh, *p_kvh, *p_hh, *p_ropedh, *p_attnh, *p_ffhh, *p_memh, *p_wh;
    cudaGetSymbolAddress((void**)&p_x,      g_x);
    cudaGetSymbolAddress((void**)&p_qkh,    g_qkh);
    cudaGetSymbolAddress((void**)&p_vh,     g_vh);
    cudaGetSymbolAddress((void**)&p_qh,     g_qh);
    cudaGetSymbolAddress((void**)&p_kvh,    g_kvh);
    cudaGetSymbolAddress((void**)&p_hh,     g_hh);
    cudaGetSymbolAddress((void**)&p_ropedh, g_ropedh);
    cudaGetSymbolAddress((void**)&p_attnh,  g_attnh);
    cudaGetSymbolAddress((void**)&p_ffhh,   g_ffhh);
    cudaGetSymbolAddress((void**)&p_memh,   g_memh);
    cudaGetSymbolAddress((void**)&p_wh,     g_wh);

    static int init_done = 0;
    static cudaStream_t s2;
    static cudaEvent_t evFork, evJoin;
    if (!init_done) {
        cudaFuncSetAttribute(hgemm, cudaFuncAttributeMaxDynamicSharedMemorySize, GSMEM);
        cudaStreamCreateWithFlags(&s2, cudaStreamNonBlocking);
        cudaEventCreateWithFlags(&evFork, cudaEventDisableTiming);
        cudaEventCreateWithFlags(&evJoin, cudaEventDisableTiming);
        init_done = 1;
    }

    auto tohalf = [](const float* src, __half* dst, int n, cudaStream_t st) {
        int n4 = n / 4;
        int blocks = (n4 + 1023) / 1024;
        to_half_kernel<<<blocks, 256, 0, st>>>((const float4*)src, (uint2*)dst, n4);
    };

    // ---- weight converts on main stream (needed by both streams) ----
    tohalf(sa_in_w,  p_wh + OW_SA_IN,  3 * DMODEL * DMODEL, 0);
    tohalf(sa_out_w, p_wh + OW_SA_OUT, DMODEL * DMODEL, 0);
    tohalf(ca_in_w,  p_wh + OW_CA_IN,  3 * DMODEL * DMODEL, 0);
    tohalf(ca_out_w, p_wh + OW_CA_OUT, DMODEL * DMODEL, 0);
    tohalf(ff1_w,    p_wh + OW_FF1,    DFF * DMODEL, 0);
    tohalf(ff2_w,    p_wh + OW_FF2,    DMODEL * DFF, 0);

    dim3 gemm_nt_d(DMODEL / 128, NT / 128);
    dim3 gemm_nt_2d(2048 / 128, NT / 128);
    dim3 gemm_mt_2d(2048 / 128, MTOK / 128);
    dim3 gemm_ff1(DFF / 128, NT / 128);
    int qtiles = (SQ + AQ - 1) / AQ;                // 2

    // ---- fork: stream2 does memory convert + big CA k|v GEMM concurrently ----
    cudaEventRecord(evFork, 0);
    cudaStreamWaitEvent(s2, evFork, 0);
    tohalf(memory, p_memh, MTOK * DMODEL, s2);
    hgemm<<<gemm_mt_2d, 256, GSMEM, s2>>>(p_memh, p_wh + OW_CA_IN + (size_t)DMODEL*DMODEL,
                                          ca_in_b + DMODEL, nullptr, p_kvh, MTOK, 2048, DMODEL, 4);
    cudaEventRecord(evJoin, s2);

    // ---- main stream: self-attention block ----
    ln_kernel<<<NT, 256>>>(tgt, ln1_g, ln1_b, p_hh, p_ropedh);   // fused LN+RoPE
    hgemm<<<gemm_nt_2d, 256, GSMEM>>>(p_ropedh, p_wh + OW_SA_IN, sa_in_b, nullptr, p_qkh, NT, 2048, DMODEL, 4);
    hgemm<<<gemm_nt_d, 256, GSMEM>>>(p_hh, p_wh + OW_SA_IN + (size_t)2*DMODEL*DMODEL, sa_in_b + 2*DMODEL, nullptr, p_vh, NT, DMODEL, DMODEL, 4);
    attn_h<<<dim3(qtiles, NH, BB), 256>>>(p_qkh, p_qkh + 1024, p_vh, p_attnh, SQ, SQ, 1, 2048, 2048, 1024);
    hgemm<<<gemm_nt_d, 256, GSMEM>>>(p_attnh, p_wh + OW_SA_OUT, sa_out_b, tgt, p_x, NT, DMODEL, DMODEL, 2);

    // ---- cross-attention block ----
    ln_kernel<<<NT, 256>>>(p_x, ln2_g, ln2_b, p_hh, nullptr);
    hgemm<<<gemm_nt_d, 256, GSMEM>>>(p_hh, p_wh + OW_CA_IN, ca_in_b, nullptr, p_qh, NT, DMODEL, DMODEL, 4);
    cudaStreamWaitEvent(0, evJoin, 0);   // join: kv GEMM must be done
    attn_h<<<dim3(qtiles, NH, BB), 256>>>(p_qh, p_kvh, p_kvh + 1024, p_attnh, SQ, SMEMLEN, 0, 1024, 2048, 2048);
    hgemm<<<gemm_nt_d, 256, GSMEM>>>(p_attnh, p_wh + OW_CA_OUT, ca_out_b, p_x, p_x, NT, DMODEL, DMODEL, 2);

    // ---- feed-forward block ----
    ln_kernel<<<NT, 256>>>(p_x, ln3_g, ln3_b, p_hh, nullptr);
    hgemm<<<gemm_ff1, 256, GSMEM>>>(p_hh,   p_wh + OW_FF1, ff1_b, nullptr, p_ffhh, NT, DFF, DMODEL, 1 | 4);
    hgemm<<<gemm_nt_d, 256, GSMEM>>>(p_ffhh, p_wh + OW_FF2, ff2_b, p_x, out, NT, DMODEL, DFF, 2);
}